// round 2
// baseline (speedup 1.0000x reference)
#include <cuda_runtime.h>
#include <math.h>

#define HWSZ 65536
#define NWD  256

// scratch (device globals — no runtime allocation)
__device__ float g_res1[4ull*128*HWSZ];   // post-attention residual stream ("out")
__device__ float g_h1  [4ull*512*HWSZ];   // ffn hidden after 1x1+gelu

__device__ __forceinline__ float gelu_f(float v) {
    return 0.5f*v*(1.0f + erff(v*0.7071067811865475f));
}

// ================= Kernel 1: LN1 + QKV + gate + window attention + proj + residual ==============
// one CTA per 8x8 window, 256 threads
__global__ void __launch_bounds__(256) k1_attn(
    const float* __restrict__ x, const float* __restrict__ l0,
    const float* __restrict__ n1w, const float* __restrict__ n1b,
    const float* __restrict__ qkvw,
    const float* __restrict__ gw, const float* __restrict__ gbv,
    const float* __restrict__ pw, const float* __restrict__ pbv)
{
    extern __shared__ float sm[];
    float* xn  = sm;                 // 64*129  (LN'd x; reused as attention output)
    float* qs  = xn + 64*129;        // 64*129
    float* ks  = qs + 64*129;        // 64*129
    float* vs  = ks + 64*129;        // 64*129
    float* sc  = vs + 64*129;        // 64*65   (per-head scores)
    float* Wts = sc + 64*65;         // 128*130 (transposed weight tile)
    float* l0s = Wts + 128*130;      // 64

    const int tid  = threadIdx.x;
    const int wid  = tid >> 5, lane = tid & 31;
    const int blk  = blockIdx.x;
    const int b    = blk >> 10;
    const int wr   = blk & 1023;
    const int y0   = (wr >> 5) << 3;
    const int x0   = (wr & 31) << 3;
    const float* xb = x + (size_t)b*128*HWSZ;

    // load x window (coalesced 32B rows)
    for (int idx = tid; idx < 64*128; idx += 256) {
        int c = idx >> 6, t = idx & 63;
        xn[t*129 + c] = xb[(size_t)c*HWSZ + (y0 + (t>>3))*NWD + (x0 + (t&7))];
    }
    if (tid < 64) l0s[tid] = l0[(size_t)b*HWSZ + (y0 + (tid>>3))*NWD + (x0 + (tid&7))];
    __syncthreads();

    // LayerNorm over channels, warp per 8 tokens
    for (int t = wid*8; t < wid*8 + 8; t++) {
        float s = 0.f, ss = 0.f;
#pragma unroll
        for (int k = 0; k < 4; k++) { float v = xn[t*129 + lane + k*32]; s += v; ss += v*v; }
#pragma unroll
        for (int o = 16; o > 0; o >>= 1) {
            s  += __shfl_xor_sync(0xffffffffu, s, o);
            ss += __shfl_xor_sync(0xffffffffu, ss, o);
        }
        float mu   = s*(1.f/128.f);
        float rstd = rsqrtf(ss*(1.f/128.f) - mu*mu + 1e-6f);
#pragma unroll
        for (int k = 0; k < 4; k++) {
            int c = lane + k*32;
            xn[t*129 + c] = (xn[t*129 + c] - mu)*rstd*n1w[c] + n1b[c];
        }
    }
    __syncthreads();

    const int tg = tid & 15, og = tid >> 4;

    // QKV GEMM: 3 output tiles of 128 (== q, k, v exactly)
    for (int ot = 0; ot < 3; ot++) {
        for (int idx = tid; idx < 128*128; idx += 256) {
            int ol = idx >> 7, c = idx & 127;
            Wts[c*130 + ol] = qkvw[(size_t)(ot*128 + ol)*128 + c];
        }
        __syncthreads();
        float acc[4][8];
#pragma unroll
        for (int r = 0; r < 4; r++)
#pragma unroll
            for (int j = 0; j < 8; j++) acc[r][j] = 0.f;
#pragma unroll 4
        for (int c = 0; c < 128; c++) {
            float xv[4], wv[8];
#pragma unroll
            for (int r = 0; r < 4; r++) xv[r] = xn[(tg*4+r)*129 + c];
#pragma unroll
            for (int j = 0; j < 8; j++) wv[j] = Wts[c*130 + og*8 + j];
#pragma unroll
            for (int r = 0; r < 4; r++)
#pragma unroll
                for (int j = 0; j < 8; j++) acc[r][j] = fmaf(xv[r], wv[j], acc[r][j]);
        }
        if (ot == 0) {
            // q with illumination gate
            float gwr[8], gbr[8];
#pragma unroll
            for (int j = 0; j < 8; j++) { gwr[j] = gw[og*8+j]; gbr[j] = gbv[og*8+j]; }
#pragma unroll
            for (int r = 0; r < 4; r++) {
                int t = tg*4 + r; float lv = l0s[t];
#pragma unroll
                for (int j = 0; j < 8; j++) {
                    float z = lv*gwr[j] + gbr[j];
                    float g = 1.f/(1.f + __expf(-z));
                    qs[t*129 + og*8 + j] = acc[r][j]*g;
                }
            }
        } else {
            float* dst = (ot == 1) ? ks : vs;
#pragma unroll
            for (int r = 0; r < 4; r++)
#pragma unroll
                for (int j = 0; j < 8; j++) dst[(tg*4+r)*129 + og*8 + j] = acc[r][j];
        }
        __syncthreads();
    }

    // attention, head by head (scores buffer reused)
    for (int hd = 0; hd < 8; hd++) {
        const int qo = hd*16;
        {   // scores: thread = (i, 16-wide j block)
            int i = tid >> 2, jb = tid & 3;
            float qv[16];
#pragma unroll
            for (int d = 0; d < 16; d++) qv[d] = qs[i*129 + qo + d];
#pragma unroll 4
            for (int jj = 0; jj < 16; jj++) {
                int j = jb*16 + jj;
                float dot = 0.f;
#pragma unroll
                for (int d = 0; d < 16; d++) dot = fmaf(qv[d], ks[j*129 + qo + d], dot);
                sc[i*65 + j] = dot*0.25f;   // scale = 16^-0.5
            }
        }
        __syncthreads();
        // softmax: warp per 8 rows
        for (int i = wid*8; i < wid*8 + 8; i++) {
            float a = sc[i*65 + lane], c2 = sc[i*65 + lane + 32];
            float m = fmaxf(a, c2);
#pragma unroll
            for (int o = 16; o > 0; o >>= 1) m = fmaxf(m, __shfl_xor_sync(0xffffffffu, m, o));
            float ea = __expf(a - m), eb = __expf(c2 - m);
            float s2 = ea + eb;
#pragma unroll
            for (int o = 16; o > 0; o >>= 1) s2 += __shfl_xor_sync(0xffffffffu, s2, o);
            float inv = 1.f/s2;
            sc[i*65 + lane]      = ea*inv;
            sc[i*65 + lane + 32] = eb*inv;
        }
        __syncthreads();
        {   // AV: thread = (i, 4-wide d group); write into xn (ao)
            int i = tid >> 2, dg = tid & 3;
            float a0=0.f, a1=0.f, a2=0.f, a3=0.f;
#pragma unroll 4
            for (int j = 0; j < 64; j++) {
                float p = sc[i*65 + j];
                const float* vp = vs + j*129 + qo + dg*4;
                a0 = fmaf(p, vp[0], a0);
                a1 = fmaf(p, vp[1], a1);
                a2 = fmaf(p, vp[2], a2);
                a3 = fmaf(p, vp[3], a3);
            }
            float* op = xn + i*129 + qo + dg*4;
            op[0]=a0; op[1]=a1; op[2]=a2; op[3]=a3;
        }
        __syncthreads();
    }

    // proj + bias + shortcut -> g_res1
    for (int idx = tid; idx < 128*128; idx += 256) {
        int co = idx >> 7, ci = idx & 127;
        Wts[ci*130 + co] = pw[(size_t)co*128 + ci];
    }
    __syncthreads();
    float acc2[4][8];
#pragma unroll
    for (int r = 0; r < 4; r++)
#pragma unroll
        for (int j = 0; j < 8; j++) acc2[r][j] = 0.f;
#pragma unroll 4
    for (int c = 0; c < 128; c++) {
        float xv[4], wv[8];
#pragma unroll
        for (int r = 0; r < 4; r++) xv[r] = xn[(tg*4+r)*129 + c];
#pragma unroll
        for (int j = 0; j < 8; j++) wv[j] = Wts[c*130 + og*8 + j];
#pragma unroll
        for (int r = 0; r < 4; r++)
#pragma unroll
            for (int j = 0; j < 8; j++) acc2[r][j] = fmaf(xv[r], wv[j], acc2[r][j]);
    }
    float pbr[8];
#pragma unroll
    for (int j = 0; j < 8; j++) pbr[j] = pbv[og*8+j];
    float* r1 = g_res1 + (size_t)b*128*HWSZ;
#pragma unroll
    for (int r = 0; r < 4; r++) {
        int t = tg*4 + r;
        int py = y0 + (t>>3), px = x0 + (t&7);
#pragma unroll
        for (int j = 0; j < 8; j++) {
            int o = og*8 + j;
            size_t gi = (size_t)o*HWSZ + py*NWD + px;
            r1[gi] = acc2[r][j] + pbr[j] + xb[gi];
        }
    }
}

// ================= Kernel 2: LN2 + FFN1 (C->512) + bias + GELU ==================================
// one CTA per 64 consecutive pixels in a row
__global__ void __launch_bounds__(256) k2_ffn1(
    const float* __restrict__ n2w, const float* __restrict__ n2b,
    const float* __restrict__ w1, const float* __restrict__ b1)
{
    extern __shared__ float sm[];
    float* xn  = sm;            // 64*129
    float* Wts = xn + 64*129;   // 128*130
    const int tid  = threadIdx.x;
    const int wid  = tid >> 5, lane = tid & 31;
    const int blk  = blockIdx.x;
    const int b    = blk >> 10;
    const int rr   = blk & 1023;
    const int y    = rr >> 2;
    const int x0   = (rr & 3)*64;
    const float* rb = g_res1 + (size_t)b*128*HWSZ + y*NWD + x0;

    for (int idx = tid; idx < 64*128; idx += 256) {
        int c = idx >> 6, t = idx & 63;
        xn[t*129 + c] = rb[(size_t)c*HWSZ + t];
    }
    __syncthreads();

    for (int t = wid*8; t < wid*8 + 8; t++) {
        float s = 0.f, ss = 0.f;
#pragma unroll
        for (int k = 0; k < 4; k++) { float v = xn[t*129 + lane + k*32]; s += v; ss += v*v; }
#pragma unroll
        for (int o = 16; o > 0; o >>= 1) {
            s  += __shfl_xor_sync(0xffffffffu, s, o);
            ss += __shfl_xor_sync(0xffffffffu, ss, o);
        }
        float mu   = s*(1.f/128.f);
        float rstd = rsqrtf(ss*(1.f/128.f) - mu*mu + 1e-6f);
#pragma unroll
        for (int k = 0; k < 4; k++) {
            int c = lane + k*32;
            xn[t*129 + c] = (xn[t*129 + c] - mu)*rstd*n2w[c] + n2b[c];
        }
    }
    __syncthreads();

    const int tg = tid & 15, og = tid >> 4;
    float* hb = g_h1 + (size_t)b*512*HWSZ + y*NWD + x0;
    for (int ot = 0; ot < 4; ot++) {
        for (int idx = tid; idx < 128*128; idx += 256) {
            int ol = idx >> 7, c = idx & 127;
            Wts[c*130 + ol] = w1[(size_t)(ot*128 + ol)*128 + c];
        }
        __syncthreads();
        float acc[4][8];
#pragma unroll
        for (int r = 0; r < 4; r++)
#pragma unroll
            for (int j = 0; j < 8; j++) acc[r][j] = 0.f;
#pragma unroll 4
        for (int c = 0; c < 128; c++) {
            float xv[4], wv[8];
#pragma unroll
            for (int r = 0; r < 4; r++) xv[r] = xn[(tg*4+r)*129 + c];
#pragma unroll
            for (int j = 0; j < 8; j++) wv[j] = Wts[c*130 + og*8 + j];
#pragma unroll
            for (int r = 0; r < 4; r++)
#pragma unroll
                for (int j = 0; j < 8; j++) acc[r][j] = fmaf(xv[r], wv[j], acc[r][j]);
        }
        float bbr[8];
#pragma unroll
        for (int j = 0; j < 8; j++) bbr[j] = b1[ot*128 + og*8 + j];
#pragma unroll
        for (int r = 0; r < 4; r++) {
            int t = tg*4 + r;
#pragma unroll
            for (int j = 0; j < 8; j++) {
                float v = acc[r][j] + bbr[j];
                hb[(size_t)(ot*128 + og*8 + j)*HWSZ + t] = gelu_f(v);
            }
        }
        __syncthreads();
    }
}

// ================= Kernel 3: depthwise 3x3 + GELU + FFN2 (512->C) + bias + residual =============
// one CTA per 8x8 spatial tile, channel chunks of 64
__global__ void __launch_bounds__(256) k3_ffn2(
    const float* __restrict__ dw, const float* __restrict__ dwb,
    const float* __restrict__ w2, const float* __restrict__ b2,
    float* __restrict__ out)
{
    extern __shared__ float sm[];
    float* hs  = sm;            // 64*101 halo (10x10 per channel)
    float* gs  = hs + 64*101;   // 64*65  post-dw+gelu
    float* w2s = gs + 64*65;    // 128*65 weight chunk
    const int tid = threadIdx.x;
    const int blk = blockIdx.x;
    const int b   = blk >> 10;
    const int rr  = blk & 1023;
    const int y0  = (rr >> 5) << 3;
    const int x0  = (rr & 31) << 3;
    const float* hbase = g_h1 + (size_t)b*512*HWSZ;
    const int tg = tid & 15, cg = tid >> 4;

    float acc[4][8];
#pragma unroll
    for (int r = 0; r < 4; r++)
#pragma unroll
        for (int j = 0; j < 8; j++) acc[r][j] = 0.f;

    for (int ck = 0; ck < 8; ck++) {
        const int c0 = ck*64;
        for (int idx = tid; idx < 64*100; idx += 256) {
            int ch = idx / 100;
            int p  = idx - ch*100;
            int pr = p / 10;
            int py = y0 - 1 + pr;
            int px = x0 - 1 + (p - pr*10);
            float v = 0.f;
            if ((unsigned)py < 256u && (unsigned)px < 256u)
                v = hbase[(size_t)(c0+ch)*HWSZ + py*NWD + px];
            hs[ch*101 + p] = v;
        }
        for (int idx = tid; idx < 128*64; idx += 256) {
            int c = idx >> 6, chl = idx & 63;
            w2s[c*65 + chl] = w2[(size_t)c*512 + c0 + chl];
        }
        __syncthreads();
        for (int idx = tid; idx < 64*64; idx += 256) {
            int t = idx >> 6, chl = idx & 63;
            int ty = t >> 3, tx = t & 7;
            const float* dwp = dw + (size_t)(c0+chl)*9;
            const float* hp  = hs + chl*101;
            float s = 0.f;
#pragma unroll
            for (int ky = 0; ky < 3; ky++)
#pragma unroll
                for (int kx = 0; kx < 3; kx++)
                    s = fmaf(dwp[ky*3+kx], hp[(ty+ky)*10 + tx+kx], s);
            s += dwb[c0+chl];
            gs[t*65 + chl] = gelu_f(s);
        }
        __syncthreads();
#pragma unroll 2
        for (int ch = 0; ch < 64; ch++) {
            float xv[4], wv[8];
#pragma unroll
            for (int r = 0; r < 4; r++) xv[r] = gs[(tg*4+r)*65 + ch];
#pragma unroll
            for (int j = 0; j < 8; j++) wv[j] = w2s[(cg*8+j)*65 + ch];
#pragma unroll
            for (int r = 0; r < 4; r++)
#pragma unroll
                for (int j = 0; j < 8; j++) acc[r][j] = fmaf(xv[r], wv[j], acc[r][j]);
        }
        __syncthreads();
    }

    float b2r[8];
#pragma unroll
    for (int j = 0; j < 8; j++) b2r[j] = b2[cg*8+j];
    const float* r1 = g_res1 + (size_t)b*128*HWSZ;
    float* ob = out + (size_t)b*128*HWSZ;
#pragma unroll
    for (int r = 0; r < 4; r++) {
        int t = tg*4 + r;
        int py = y0 + (t>>3), px = x0 + (t&7);
#pragma unroll
        for (int j = 0; j < 8; j++) {
            int o = cg*8 + j;
            size_t gi = (size_t)o*HWSZ + py*NWD + px;
            ob[gi] = acc[r][j] + b2r[j] + r1[gi];
        }
    }
}

// =================================================================================================
extern "C" void kernel_launch(void* const* d_in, const int* in_sizes, int n_in,
                              void* d_out, int out_size)
{
    const float* x    = (const float*)d_in[0];
    const float* l0   = (const float*)d_in[1];
    const float* n1w  = (const float*)d_in[2];
    const float* n1b  = (const float*)d_in[3];
    const float* n2w  = (const float*)d_in[4];
    const float* n2b  = (const float*)d_in[5];
    const float* qkvw = (const float*)d_in[6];
    const float* gw   = (const float*)d_in[7];
    const float* gb   = (const float*)d_in[8];
    const float* pw   = (const float*)d_in[9];
    const float* pb   = (const float*)d_in[10];
    const float* w1   = (const float*)d_in[11];
    const float* b1   = (const float*)d_in[12];
    const float* dwv  = (const float*)d_in[13];
    const float* dwb  = (const float*)d_in[14];
    const float* w2   = (const float*)d_in[15];
    const float* b2   = (const float*)d_in[16];
    float* out = (float*)d_out;

    const int smem1 = (4*64*129 + 64*65 + 128*130 + 64) * (int)sizeof(float);   // 215552
    const int smem2 = (64*129 + 128*130) * (int)sizeof(float);                  //  99584
    const int smem3 = (64*101 + 64*65 + 128*65) * (int)sizeof(float);           //  75776

    cudaFuncSetAttribute(k1_attn, cudaFuncAttributeMaxDynamicSharedMemorySize, smem1);
    cudaFuncSetAttribute(k2_ffn1, cudaFuncAttributeMaxDynamicSharedMemorySize, smem2);
    cudaFuncSetAttribute(k3_ffn2, cudaFuncAttributeMaxDynamicSharedMemorySize, smem3);

    k1_attn<<<4096, 256, smem1>>>(x, l0, n1w, n1b, qkvw, gw, gb, pw, pb);
    k2_ffn1<<<4096, 256, smem2>>>(n2w, n2b, w1, b1);
    k3_ffn2<<<4096, 256, smem3>>>(dwv, dwb, w2, b2, out);
}

// round 4
// speedup vs baseline: 1.7346x; 1.7346x over previous
#include <cuda_runtime.h>
#include <math.h>

#define HWSZ 65536
#define NWD  256
typedef unsigned long long u64;

// scratch (device globals — no runtime allocation)
__device__ float g_res1[4ull*128*HWSZ];   // post-attention residual stream
__device__ float g_h1  [4ull*512*HWSZ];   // ffn hidden after 1x1+gelu

__device__ __forceinline__ u64 pk2(float lo, float hi){ u64 r; asm("mov.b64 %0,{%1,%2};":"=l"(r):"f"(lo),"f"(hi)); return r; }
__device__ __forceinline__ u64 dup2(float v){ return pk2(v, v); }
__device__ __forceinline__ void fma2(u64& d, u64 a, u64 b){ asm("fma.rn.f32x2 %0,%1,%2,%0;":"+l"(d):"l"(a),"l"(b)); }
__device__ __forceinline__ float lo2(u64 v){ return __uint_as_float((unsigned)v); }
__device__ __forceinline__ float hi2(u64 v){ return __uint_as_float((unsigned)(v>>32)); }
__device__ __forceinline__ float gelu_f(float v){ return 0.5f*v*(1.0f + erff(v*0.7071067811865475f)); }
__device__ __forceinline__ float sigm(float z){ return 1.f/(1.f + __expf(-z)); }

// Packed-register GEMM core.
// xs: [KC c][64 t] stride 64 (activation, float4 over t)
// Ws: [KC c][132]  stride 132 (weights, pairs over ol)
// acc[r][jp]: outputs for t = tg*4+r, ol = og*8 + jp*2 (+1 in hi half)
template<int KC>
__device__ __forceinline__ void gemm_core(const float* __restrict__ xs,
                                          const float* __restrict__ Ws,
                                          int tg, int og, u64 acc[4][4])
{
    const float* xp = xs + tg*4;
    const float* wp = Ws + og*8;
#pragma unroll 8
    for (int c = 0; c < KC; c++) {
        float4 xv = *(const float4*)(xp + c*64);
        ulonglong2 wA = *(const ulonglong2*)(wp + c*132);
        ulonglong2 wB = *(const ulonglong2*)(wp + c*132 + 4);
        u64 x0 = dup2(xv.x), x1 = dup2(xv.y), x2 = dup2(xv.z), x3 = dup2(xv.w);
        fma2(acc[0][0], x0, wA.x); fma2(acc[0][1], x0, wA.y); fma2(acc[0][2], x0, wB.x); fma2(acc[0][3], x0, wB.y);
        fma2(acc[1][0], x1, wA.x); fma2(acc[1][1], x1, wA.y); fma2(acc[1][2], x1, wB.x); fma2(acc[1][3], x1, wB.y);
        fma2(acc[2][0], x2, wA.x); fma2(acc[2][1], x2, wA.y); fma2(acc[2][2], x2, wB.x); fma2(acc[2][3], x2, wB.y);
        fma2(acc[3][0], x3, wA.x); fma2(acc[3][1], x3, wA.y); fma2(acc[3][2], x3, wB.x); fma2(acc[3][3], x3, wB.y);
    }
}

// ================= Kernel 1: LN1 + QKV + gate + window attention + proj + residual ==============
__global__ void __launch_bounds__(256,1) k1_attn(
    const float* __restrict__ x, const float* __restrict__ l0,
    const float* __restrict__ n1w, const float* __restrict__ n1b,
    const float* __restrict__ qkvw,
    const float* __restrict__ gw, const float* __restrict__ gbv,
    const float* __restrict__ pw, const float* __restrict__ pbv)
{
    extern __shared__ float sm[];
    float* xs  = sm;             // 8192  [c][64] LN'd x; reused as attention output
    float* qs  = xs + 8192;      // 8192  [c][64]
    float* ks  = qs + 8192;      // 8192  [c][64]
    float* vt  = ks + 8192;      // 8448  [t][132] token-major V
    float* sc  = vt + 8448;      // 4160  [i][65] scores (reused as LN reduction buf)
    float* Ws  = sc + 4160;      // 16896 [c][132] weight tile
    float* l0s = Ws + 16896;     // 64

    const int tid = threadIdx.x;
    const int blk = blockIdx.x;
    const int b   = blk >> 10, wr = blk & 1023;
    const int y0  = (wr >> 5) << 3, xw = (wr & 31) << 3;
    const float* xb = x + (size_t)b*128*HWSZ;
    const int tg = tid & 15, og = tid >> 4;

    // load x window into [c][t]
    for (int idx = tid; idx < 8192; idx += 256) {
        int c = idx >> 6, t = idx & 63;
        xs[c*64 + t] = xb[(size_t)c*HWSZ + (y0 + (t>>3))*NWD + xw + (t&7)];
    }
    if (tid < 64) l0s[tid] = l0[(size_t)b*HWSZ + (y0 + (tid>>3))*NWD + xw + (tid&7)];
    __syncthreads();

    // LayerNorm over channels: thread = (t, quarter of c)
    {
        int t = tid & 63, q = tid >> 6;
        float s = 0.f, ss = 0.f;
#pragma unroll
        for (int cc = 0; cc < 32; cc++) {
            float v = xs[(q*32+cc)*64 + t];
            s += v; ss += v*v;
        }
        float* rs = sc;          // [4][64]
        float* rq = sc + 256;    // [4][64]
        rs[q*64+t] = s; rq[q*64+t] = ss;
        __syncthreads();
        s  = rs[t] + rs[64+t] + rs[128+t] + rs[192+t];
        ss = rq[t] + rq[64+t] + rq[128+t] + rq[192+t];
        float mu   = s*(1.f/128.f);
        float rstd = rsqrtf(ss*(1.f/128.f) - mu*mu + 1e-6f);
#pragma unroll
        for (int cc = 0; cc < 32; cc++) {
            int c = q*32+cc;
            xs[c*64+t] = (xs[c*64+t]-mu)*rstd*n1w[c] + n1b[c];
        }
    }
    __syncthreads();

    // QKV: 3 output tiles of 128
    for (int ot = 0; ot < 3; ot++) {
        for (int idx = tid; idx < 16384; idx += 256) {
            int c = idx & 127, ol = idx >> 7;
            Ws[c*132 + ol] = qkvw[(size_t)(ot*128+ol)*128 + c];
        }
        __syncthreads();
        u64 acc[4][4];
#pragma unroll
        for (int r = 0; r < 4; r++)
#pragma unroll
            for (int jp = 0; jp < 4; jp++) acc[r][jp] = 0ull;
        gemm_core<128>(xs, Ws, tg, og, acc);

        if (ot < 2) {
            float* dst = ot ? ks : qs;
            float lv0 = l0s[tg*4], lv1 = l0s[tg*4+1], lv2 = l0s[tg*4+2], lv3 = l0s[tg*4+3];
#pragma unroll
            for (int jp = 0; jp < 4; jp++) {
#pragma unroll
                for (int h = 0; h < 2; h++) {
                    int o = og*8 + jp*2 + h;
                    float4 col;
                    col.x = h ? hi2(acc[0][jp]) : lo2(acc[0][jp]);
                    col.y = h ? hi2(acc[1][jp]) : lo2(acc[1][jp]);
                    col.z = h ? hi2(acc[2][jp]) : lo2(acc[2][jp]);
                    col.w = h ? hi2(acc[3][jp]) : lo2(acc[3][jp]);
                    if (ot == 0) {
                        float gww = gw[o], gbb = gbv[o];
                        col.x *= sigm(lv0*gww+gbb);
                        col.y *= sigm(lv1*gww+gbb);
                        col.z *= sigm(lv2*gww+gbb);
                        col.w *= sigm(lv3*gww+gbb);
                    }
                    *(float4*)(dst + o*64 + tg*4) = col;
                }
            }
        } else {
            // V -> token-major vt[t][132]
#pragma unroll
            for (int r = 0; r < 4; r++) {
                float4 a = make_float4(lo2(acc[r][0]), hi2(acc[r][0]), lo2(acc[r][1]), hi2(acc[r][1]));
                float4 c4 = make_float4(lo2(acc[r][2]), hi2(acc[r][2]), lo2(acc[r][3]), hi2(acc[r][3]));
                *(float4*)(vt + (tg*4+r)*132 + og*8)     = a;
                *(float4*)(vt + (tg*4+r)*132 + og*8 + 4) = c4;
            }
        }
        __syncthreads();
    }

    // attention, head by head
    for (int hd = 0; hd < 8; hd++) {
        const int qo = hd*16;
        {   // scores: thread = (i, 16-wide j block), packed over j pairs
            int i = tid >> 2, jb = tid & 3;
            u64 qd[16];
#pragma unroll
            for (int d = 0; d < 16; d++) qd[d] = dup2(qs[(qo+d)*64 + i]);
            u64 accS[8];
#pragma unroll
            for (int j2 = 0; j2 < 8; j2++) accS[j2] = 0ull;
#pragma unroll 4
            for (int d = 0; d < 16; d++) {
                const u64* kp = (const u64*)(ks + (qo+d)*64 + jb*16);
#pragma unroll
                for (int j2 = 0; j2 < 8; j2++) fma2(accS[j2], qd[d], kp[j2]);
            }
#pragma unroll
            for (int j2 = 0; j2 < 8; j2++) {
                sc[i*65 + jb*16 + j2*2]     = lo2(accS[j2])*0.25f;
                sc[i*65 + jb*16 + j2*2 + 1] = hi2(accS[j2])*0.25f;
            }
        }
        __syncthreads();
        {   // softmax: warp per 8 rows
            int wid = tid >> 5, lane = tid & 31;
            for (int i = wid*8; i < wid*8 + 8; i++) {
                float a = sc[i*65 + lane], c2 = sc[i*65 + lane + 32];
                float m = fmaxf(a, c2);
#pragma unroll
                for (int o = 16; o > 0; o >>= 1) m = fmaxf(m, __shfl_xor_sync(0xffffffffu, m, o));
                float ea = __expf(a - m), eb = __expf(c2 - m);
                float s2 = ea + eb;
#pragma unroll
                for (int o = 16; o > 0; o >>= 1) s2 += __shfl_xor_sync(0xffffffffu, s2, o);
                float inv = 1.f/s2;
                sc[i*65 + lane]      = ea*inv;
                sc[i*65 + lane + 32] = eb*inv;
            }
        }
        __syncthreads();
        {   // AV: thread = (i, 4-wide d group), packed over d pairs; out -> xs[c][t]
            int i = tid >> 2, dg = tid & 3;
            u64 a0 = 0ull, a1 = 0ull;
#pragma unroll 4
            for (int j = 0; j < 64; j++) {
                u64 pd = dup2(sc[i*65 + j]);
                ulonglong2 vv = *(const ulonglong2*)(vt + j*132 + qo + dg*4);
                fma2(a0, pd, vv.x);
                fma2(a1, pd, vv.y);
            }
            xs[(qo+dg*4+0)*64 + i] = lo2(a0);
            xs[(qo+dg*4+1)*64 + i] = hi2(a0);
            xs[(qo+dg*4+2)*64 + i] = lo2(a1);
            xs[(qo+dg*4+3)*64 + i] = hi2(a1);
        }
        __syncthreads();
    }

    // proj + bias + shortcut -> g_res1
    for (int idx = tid; idx < 16384; idx += 256) {
        int c = idx & 127, ol = idx >> 7;
        Ws[c*132 + ol] = pw[(size_t)ol*128 + c];
    }
    __syncthreads();
    u64 acc[4][4];
#pragma unroll
    for (int r = 0; r < 4; r++)
#pragma unroll
        for (int jp = 0; jp < 4; jp++) acc[r][jp] = 0ull;
    gemm_core<128>(xs, Ws, tg, og, acc);

    float* r1 = g_res1 + (size_t)b*128*HWSZ;
    const int t0 = tg*4;
    const size_t pix = (size_t)(y0 + (t0>>3))*NWD + xw + (t0&7);
#pragma unroll
    for (int jp = 0; jp < 4; jp++)
#pragma unroll
        for (int h = 0; h < 2; h++) {
            int o = og*8 + jp*2 + h;
            float pb = pbv[o];
            float4 s4 = *(const float4*)(xb + (size_t)o*HWSZ + pix);
            float4 col;
            col.x = (h ? hi2(acc[0][jp]) : lo2(acc[0][jp])) + pb + s4.x;
            col.y = (h ? hi2(acc[1][jp]) : lo2(acc[1][jp])) + pb + s4.y;
            col.z = (h ? hi2(acc[2][jp]) : lo2(acc[2][jp])) + pb + s4.z;
            col.w = (h ? hi2(acc[3][jp]) : lo2(acc[3][jp])) + pb + s4.w;
            *(float4*)(r1 + (size_t)o*HWSZ + pix) = col;
        }
}

// ================= Kernel 2: LN2 + FFN1 (128->512) + bias + GELU ================================
__global__ void __launch_bounds__(256,2) k2_ffn1(
    const float* __restrict__ n2w, const float* __restrict__ n2b,
    const float* __restrict__ w1, const float* __restrict__ b1)
{
    extern __shared__ float sm[];
    float* xs  = sm;             // 8192  [c][64]
    float* Ws  = xs + 8192;      // 16896 [c][132]
    float* red = Ws + 16896;     // 512

    const int tid = threadIdx.x;
    const int blk = blockIdx.x;
    const int b   = blk >> 10, rr = blk & 1023;
    const int y   = rr >> 2, xp0 = (rr & 3)*64;
    const float* rb = g_res1 + (size_t)b*128*HWSZ + (size_t)y*NWD + xp0;
    const int tg = tid & 15, og = tid >> 4;

    for (int idx = tid; idx < 2048; idx += 256) {
        int c = idx >> 4, t4 = idx & 15;
        *(float4*)(xs + c*64 + t4*4) = *(const float4*)(rb + (size_t)c*HWSZ + t4*4);
    }
    __syncthreads();

    {   // LN2
        int t = tid & 63, q = tid >> 6;
        float s = 0.f, ss = 0.f;
#pragma unroll
        for (int cc = 0; cc < 32; cc++) {
            float v = xs[(q*32+cc)*64 + t];
            s += v; ss += v*v;
        }
        float* rs = red;
        float* rq = red + 256;
        rs[q*64+t] = s; rq[q*64+t] = ss;
        __syncthreads();
        s  = rs[t] + rs[64+t] + rs[128+t] + rs[192+t];
        ss = rq[t] + rq[64+t] + rq[128+t] + rq[192+t];
        float mu   = s*(1.f/128.f);
        float rstd = rsqrtf(ss*(1.f/128.f) - mu*mu + 1e-6f);
#pragma unroll
        for (int cc = 0; cc < 32; cc++) {
            int c = q*32+cc;
            xs[c*64+t] = (xs[c*64+t]-mu)*rstd*n2w[c] + n2b[c];
        }
    }
    __syncthreads();

    float* hb = g_h1 + (size_t)b*512*HWSZ + (size_t)y*NWD + xp0;
    for (int ot = 0; ot < 4; ot++) {
        for (int idx = tid; idx < 16384; idx += 256) {
            int c = idx & 127, ol = idx >> 7;
            Ws[c*132 + ol] = w1[(size_t)(ot*128+ol)*128 + c];
        }
        __syncthreads();
        u64 acc[4][4];
#pragma unroll
        for (int r = 0; r < 4; r++)
#pragma unroll
            for (int jp = 0; jp < 4; jp++) acc[r][jp] = 0ull;
        gemm_core<128>(xs, Ws, tg, og, acc);
#pragma unroll
        for (int jp = 0; jp < 4; jp++)
#pragma unroll
            for (int h = 0; h < 2; h++) {
                int o = ot*128 + og*8 + jp*2 + h;
                float bb = b1[o];
                float4 col;
                col.x = gelu_f((h ? hi2(acc[0][jp]) : lo2(acc[0][jp])) + bb);
                col.y = gelu_f((h ? hi2(acc[1][jp]) : lo2(acc[1][jp])) + bb);
                col.z = gelu_f((h ? hi2(acc[2][jp]) : lo2(acc[2][jp])) + bb);
                col.w = gelu_f((h ? hi2(acc[3][jp]) : lo2(acc[3][jp])) + bb);
                *(float4*)(hb + (size_t)o*HWSZ + tg*4) = col;
            }
        __syncthreads();
    }
}

// ================= Kernel 3: depthwise 3x3 + GELU + FFN2 (512->128) + bias + residual ===========
__global__ void __launch_bounds__(256,2) k3_ffn2(
    const float* __restrict__ dw, const float* __restrict__ dwb,
    const float* __restrict__ w2, const float* __restrict__ b2,
    float* __restrict__ out)
{
    extern __shared__ float sm[];
    float* hs = sm;              // 6464 [ch][101] halo
    float* gs = hs + 6464;       // 4096 [ch][64] post-dw+gelu
    float* Ws = gs + 4096;       // 8448 [ch][132]

    const int tid = threadIdx.x;
    const int blk = blockIdx.x;
    const int b   = blk >> 10, rr = blk & 1023;
    const int y0  = (rr >> 5) << 3, xw = (rr & 31) << 3;
    const float* hbase = g_h1 + (size_t)b*512*HWSZ;
    const int tg = tid & 15, cg = tid >> 4;

    u64 acc[4][4];
#pragma unroll
    for (int r = 0; r < 4; r++)
#pragma unroll
        for (int jp = 0; jp < 4; jp++) acc[r][jp] = 0ull;

    for (int ck = 0; ck < 8; ck++) {
        const int c0 = ck*64;
        for (int idx = tid; idx < 6400; idx += 256) {
            int ch = idx / 100;
            int p  = idx - ch*100;
            int pr = p / 10;
            int py = y0 - 1 + pr;
            int px = xw - 1 + (p - pr*10);
            float v = 0.f;
            if ((unsigned)py < 256u && (unsigned)px < 256u)
                v = hbase[(size_t)(c0+ch)*HWSZ + py*NWD + px];
            hs[ch*101 + p] = v;
        }
        for (int idx = tid; idx < 8192; idx += 256) {
            int chl = idx & 63, ol = idx >> 6;
            Ws[chl*132 + ol] = w2[(size_t)ol*512 + c0 + chl];
        }
        __syncthreads();
        for (int idx = tid; idx < 4096; idx += 256) {
            int t = idx & 63, chl = idx >> 6;
            int ty = t >> 3, tx = t & 7;
            const float* dwp = dw + (size_t)(c0+chl)*9;
            const float* hp  = hs + chl*101;
            float s = 0.f;
#pragma unroll
            for (int ky = 0; ky < 3; ky++)
#pragma unroll
                for (int kx = 0; kx < 3; kx++)
                    s = fmaf(dwp[ky*3+kx], hp[(ty+ky)*10 + tx+kx], s);
            gs[chl*64 + t] = gelu_f(s + dwb[c0+chl]);
        }
        __syncthreads();
        gemm_core<64>(gs, Ws, tg, cg, acc);
        __syncthreads();
    }

    const float* r1 = g_res1 + (size_t)b*128*HWSZ;
    float* ob = out + (size_t)b*128*HWSZ;
    const int t0 = tg*4;
    const size_t pix = (size_t)(y0 + (t0>>3))*NWD + xw + (t0&7);
#pragma unroll
    for (int jp = 0; jp < 4; jp++)
#pragma unroll
        for (int h = 0; h < 2; h++) {
            int o = cg*8 + jp*2 + h;
            float bb = b2[o];
            float4 s4 = *(const float4*)(r1 + (size_t)o*HWSZ + pix);
            float4 col;
            col.x = (h ? hi2(acc[0][jp]) : lo2(acc[0][jp])) + bb + s4.x;
            col.y = (h ? hi2(acc[1][jp]) : lo2(acc[1][jp])) + bb + s4.y;
            col.z = (h ? hi2(acc[2][jp]) : lo2(acc[2][jp])) + bb + s4.z;
            col.w = (h ? hi2(acc[3][jp]) : lo2(acc[3][jp])) + bb + s4.w;
            *(float4*)(ob + (size_t)o*HWSZ + pix) = col;
        }
}

// =================================================================================================
extern "C" void kernel_launch(void* const* d_in, const int* in_sizes, int n_in,
                              void* d_out, int out_size)
{
    const float* x    = (const float*)d_in[0];
    const float* l0   = (const float*)d_in[1];
    const float* n1w  = (const float*)d_in[2];
    const float* n1b  = (const float*)d_in[3];
    const float* n2w  = (const float*)d_in[4];
    const float* n2b  = (const float*)d_in[5];
    const float* qkvw = (const float*)d_in[6];
    const float* gw   = (const float*)d_in[7];
    const float* gb   = (const float*)d_in[8];
    const float* pw   = (const float*)d_in[9];
    const float* pb   = (const float*)d_in[10];
    const float* w1   = (const float*)d_in[11];
    const float* b1   = (const float*)d_in[12];
    const float* dwv  = (const float*)d_in[13];
    const float* dwb  = (const float*)d_in[14];
    const float* w2   = (const float*)d_in[15];
    const float* b2   = (const float*)d_in[16];
    float* out = (float*)d_out;

    const int smem1 = (8192*3 + 8448 + 4160 + 16896 + 64) * (int)sizeof(float);  // 216576
    const int smem2 = (8192 + 16896 + 512) * (int)sizeof(float);                 // 102400
    const int smem3 = (6464 + 4096 + 8448) * (int)sizeof(float);                 //  76032

    cudaFuncSetAttribute(k1_attn, cudaFuncAttributeMaxDynamicSharedMemorySize, smem1);
    cudaFuncSetAttribute(k2_ffn1, cudaFuncAttributeMaxDynamicSharedMemorySize, smem2);
    cudaFuncSetAttribute(k3_ffn2, cudaFuncAttributeMaxDynamicSharedMemorySize, smem3);

    k1_attn<<<4096, 256, smem1>>>(x, l0, n1w, n1b, qkvw, gw, gb, pw, pb);
    k2_ffn1<<<4096, 256, smem2>>>(n2w, n2b, w1, b1);
    k3_ffn2<<<4096, 256, smem3>>>(dwv, dwb, w2, b2, out);
}

// round 5
// speedup vs baseline: 2.1084x; 1.2155x over previous
#include <cuda_runtime.h>
#include <math.h>

#define HWSZ 65536
#define NWD  256
typedef unsigned long long u64;

// scratch (device globals — no runtime allocation)
__device__ float g_res1[4ull*128*HWSZ];   // post-attention residual stream
__device__ float g_h1  [4ull*512*HWSZ];   // ffn hidden after 1x1+gelu

__device__ __forceinline__ u64 pk2(float lo, float hi){ u64 r; asm("mov.b64 %0,{%1,%2};":"=l"(r):"f"(lo),"f"(hi)); return r; }
__device__ __forceinline__ u64 dup2(float v){ return pk2(v, v); }
__device__ __forceinline__ void fma2(u64& d, u64 a, u64 b){ asm("fma.rn.f32x2 %0,%1,%2,%0;":"+l"(d):"l"(a),"l"(b)); }
__device__ __forceinline__ float lo2(u64 v){ return __uint_as_float((unsigned)v); }
__device__ __forceinline__ float hi2(u64 v){ return __uint_as_float((unsigned)(v>>32)); }
__device__ __forceinline__ float gelu_f(float v){ return 0.5f*v*(1.0f + erff(v*0.7071067811865475f)); }
__device__ __forceinline__ float sigm(float z){ return 1.f/(1.f + __expf(-z)); }

// 4t x 4ol packed GEMM core (for 512-thread k1 and 64-ol-tile k2)
// xs: [KC c][64 t], Ws: [KC c][WSTR] (ol minor), acc[r][jp] covers ol = og*4 + jp*2 (+1 hi)
template<int KC, int WSTR>
__device__ __forceinline__ void gemm44(const float* __restrict__ xs,
                                       const float* __restrict__ Ws,
                                       int tg, int og, u64 acc[4][2])
{
    const float* xp = xs + tg*4;
    const float* wp = Ws + og*4;
#pragma unroll 8
    for (int c = 0; c < KC; c++) {
        float4 xv = *(const float4*)(xp + c*64);
        ulonglong2 w = *(const ulonglong2*)(wp + c*WSTR);
        u64 x0 = dup2(xv.x), x1 = dup2(xv.y), x2 = dup2(xv.z), x3 = dup2(xv.w);
        fma2(acc[0][0], x0, w.x); fma2(acc[0][1], x0, w.y);
        fma2(acc[1][0], x1, w.x); fma2(acc[1][1], x1, w.y);
        fma2(acc[2][0], x2, w.x); fma2(acc[2][1], x2, w.y);
        fma2(acc[3][0], x3, w.x); fma2(acc[3][1], x3, w.y);
    }
}

// 4t x 8ol packed GEMM core (k3)
template<int KC>
__device__ __forceinline__ void gemm48(const float* __restrict__ xs,
                                       const float* __restrict__ Ws,
                                       int tg, int og, u64 acc[4][4])
{
    const float* xp = xs + tg*4;
    const float* wp = Ws + og*8;
#pragma unroll 8
    for (int c = 0; c < KC; c++) {
        float4 xv = *(const float4*)(xp + c*64);
        ulonglong2 wA = *(const ulonglong2*)(wp + c*132);
        ulonglong2 wB = *(const ulonglong2*)(wp + c*132 + 4);
        u64 x0 = dup2(xv.x), x1 = dup2(xv.y), x2 = dup2(xv.z), x3 = dup2(xv.w);
        fma2(acc[0][0], x0, wA.x); fma2(acc[0][1], x0, wA.y); fma2(acc[0][2], x0, wB.x); fma2(acc[0][3], x0, wB.y);
        fma2(acc[1][0], x1, wA.x); fma2(acc[1][1], x1, wA.y); fma2(acc[1][2], x1, wB.x); fma2(acc[1][3], x1, wB.y);
        fma2(acc[2][0], x2, wA.x); fma2(acc[2][1], x2, wA.y); fma2(acc[2][2], x2, wB.x); fma2(acc[2][3], x2, wB.y);
        fma2(acc[3][0], x3, wA.x); fma2(acc[3][1], x3, wA.y); fma2(acc[3][2], x3, wB.x); fma2(acc[3][3], x3, wB.y);
    }
}

// ================= Kernel 1: LN1 + QKV + gate + window attention + proj + residual ==============
// 512 threads per 8x8 window; sync-free register-resident attention (head = tid>>6)
__global__ void __launch_bounds__(512,1) k1_attn(
    const float* __restrict__ x, const float* __restrict__ l0,
    const float* __restrict__ n1w, const float* __restrict__ n1b,
    const float* __restrict__ qkvw,
    const float* __restrict__ gw, const float* __restrict__ gbv,
    const float* __restrict__ pw, const float* __restrict__ pbv)
{
    extern __shared__ float sm[];
    float* xs  = sm;             // 8192  [c][64] LN'd x; reused as attention output
    float* qt  = xs + 8192;      // 8448  [t][132] token-major Q
    float* kt  = qt + 8448;      // 8448  [t][132] token-major K
    float* vt  = kt + 8448;      // 8448  [t][132] token-major V
    float* Ws  = vt + 8448;      // 16896 [c][132] weight tile
    float* l0s = Ws + 16896;     // 64
    float* red = l0s + 64;       // 1024

    const int tid = threadIdx.x;
    const int blk = blockIdx.x;
    const int b   = blk >> 10, wr = blk & 1023;
    const int y0  = (wr >> 5) << 3, xw = (wr & 31) << 3;
    const float* xb = x + (size_t)b*128*HWSZ;
    const int tg = tid & 15, og = tid >> 4;   // og in 0..31

    // load x window into [c][t]
    for (int idx = tid; idx < 8192; idx += 512) {
        int c = idx >> 6, t = idx & 63;
        xs[c*64 + t] = xb[(size_t)c*HWSZ + (y0 + (t>>3))*NWD + xw + (t&7)];
    }
    if (tid < 64) l0s[tid] = l0[(size_t)b*HWSZ + (y0 + (tid>>3))*NWD + xw + (tid&7)];
    __syncthreads();

    // LayerNorm over channels: thread = (t, eighth of c)
    {
        int t = tid & 63, q8 = tid >> 6;
        float s = 0.f, ss = 0.f;
#pragma unroll
        for (int cc = 0; cc < 16; cc++) {
            float v = xs[(q8*16+cc)*64 + t];
            s += v; ss += v*v;
        }
        red[q8*64+t] = s; red[512 + q8*64+t] = ss;
        __syncthreads();
        s = 0.f; ss = 0.f;
#pragma unroll
        for (int k = 0; k < 8; k++) { s += red[k*64+t]; ss += red[512 + k*64+t]; }
        float mu   = s*(1.f/128.f);
        float rstd = rsqrtf(ss*(1.f/128.f) - mu*mu + 1e-6f);
#pragma unroll
        for (int cc = 0; cc < 16; cc++) {
            int c = q8*16+cc;
            xs[c*64+t] = (xs[c*64+t]-mu)*rstd*n1w[c] + n1b[c];
        }
    }
    __syncthreads();

    // QKV: 3 output tiles of 128, results stored token-major
    for (int ot = 0; ot < 3; ot++) {
        for (int idx = tid; idx < 16384; idx += 512) {
            int c = idx & 127, ol = idx >> 7;
            Ws[c*132 + ol] = qkvw[(size_t)(ot*128+ol)*128 + c];
        }
        __syncthreads();
        u64 acc[4][2];
#pragma unroll
        for (int r = 0; r < 4; r++) { acc[r][0] = 0ull; acc[r][1] = 0ull; }
        gemm44<128,132>(xs, Ws, tg, og, acc);

        float* dst = (ot == 0) ? qt : (ot == 1) ? kt : vt;
        if (ot == 0) {
            float gw0 = gw[og*4], gw1 = gw[og*4+1], gw2 = gw[og*4+2], gw3 = gw[og*4+3];
            float gb0 = gbv[og*4], gb1 = gbv[og*4+1], gb2 = gbv[og*4+2], gb3 = gbv[og*4+3];
#pragma unroll
            for (int r = 0; r < 4; r++) {
                float lv = l0s[tg*4+r];
                float4 v4;
                v4.x = lo2(acc[r][0]) * sigm(lv*gw0+gb0);
                v4.y = hi2(acc[r][0]) * sigm(lv*gw1+gb1);
                v4.z = lo2(acc[r][1]) * sigm(lv*gw2+gb2);
                v4.w = hi2(acc[r][1]) * sigm(lv*gw3+gb3);
                *(float4*)(dst + (tg*4+r)*132 + og*4) = v4;
            }
        } else {
#pragma unroll
            for (int r = 0; r < 4; r++) {
                float4 v4 = make_float4(lo2(acc[r][0]), hi2(acc[r][0]),
                                        lo2(acc[r][1]), hi2(acc[r][1]));
                *(float4*)(dst + (tg*4+r)*132 + og*4) = v4;
            }
        }
        __syncthreads();
    }

    // ---- attention: 8 heads x 64 threads, fully register-resident, no internal syncs ----
    {
        int i = tid & 63, hd = tid >> 6;
        const int qo = hd*16;
        const ulonglong2* qp = (const ulonglong2*)(qt + i*132 + qo);
        ulonglong2 qa = qp[0], qb = qp[1], qc = qp[2], qd = qp[3];

        float p[64];
#pragma unroll
        for (int j = 0; j < 64; j++) {
            const ulonglong2* kp = (const ulonglong2*)(kt + j*132 + qo);
            ulonglong2 k0 = kp[0], k1 = kp[1], k2 = kp[2], k3 = kp[3];
            u64 a = 0ull;
            fma2(a, qa.x, k0.x); fma2(a, qa.y, k0.y);
            fma2(a, qb.x, k1.x); fma2(a, qb.y, k1.y);
            fma2(a, qc.x, k2.x); fma2(a, qc.y, k2.y);
            fma2(a, qd.x, k3.x); fma2(a, qd.y, k3.y);
            p[j] = (lo2(a) + hi2(a)) * 0.25f;   // scale = 16^-0.5
        }
        float m = p[0];
#pragma unroll
        for (int j = 1; j < 64; j++) m = fmaxf(m, p[j]);
        float s = 0.f;
#pragma unroll
        for (int j = 0; j < 64; j++) { p[j] = __expf(p[j] - m); s += p[j]; }
        float inv = 1.f/s;

        u64 o2[8];
#pragma unroll
        for (int d2 = 0; d2 < 8; d2++) o2[d2] = 0ull;
#pragma unroll
        for (int j = 0; j < 64; j++) {
            u64 pj = dup2(p[j]*inv);
            const ulonglong2* vp = (const ulonglong2*)(vt + j*132 + qo);
            ulonglong2 v0 = vp[0], v1 = vp[1], v2 = vp[2], v3 = vp[3];
            fma2(o2[0], pj, v0.x); fma2(o2[1], pj, v0.y);
            fma2(o2[2], pj, v1.x); fma2(o2[3], pj, v1.y);
            fma2(o2[4], pj, v2.x); fma2(o2[5], pj, v2.y);
            fma2(o2[6], pj, v3.x); fma2(o2[7], pj, v3.y);
        }
#pragma unroll
        for (int d2 = 0; d2 < 8; d2++) {
            xs[(qo + d2*2  )*64 + i] = lo2(o2[d2]);
            xs[(qo + d2*2+1)*64 + i] = hi2(o2[d2]);
        }
    }

    // proj + bias + shortcut -> g_res1
    for (int idx = tid; idx < 16384; idx += 512) {
        int c = idx & 127, ol = idx >> 7;
        Ws[c*132 + ol] = pw[(size_t)ol*128 + c];
    }
    __syncthreads();
    u64 acc[4][2];
#pragma unroll
    for (int r = 0; r < 4; r++) { acc[r][0] = 0ull; acc[r][1] = 0ull; }
    gemm44<128,132>(xs, Ws, tg, og, acc);

    float* r1 = g_res1 + (size_t)b*128*HWSZ;
    const int t0 = tg*4;
    const size_t pix = (size_t)(y0 + (t0>>3))*NWD + xw + (t0&7);
#pragma unroll
    for (int jp = 0; jp < 2; jp++)
#pragma unroll
        for (int h = 0; h < 2; h++) {
            int o = og*4 + jp*2 + h;
            float pb = pbv[o];
            float4 s4 = *(const float4*)(xb + (size_t)o*HWSZ + pix);
            float4 col;
            col.x = (h ? hi2(acc[0][jp]) : lo2(acc[0][jp])) + pb + s4.x;
            col.y = (h ? hi2(acc[1][jp]) : lo2(acc[1][jp])) + pb + s4.y;
            col.z = (h ? hi2(acc[2][jp]) : lo2(acc[2][jp])) + pb + s4.z;
            col.w = (h ? hi2(acc[3][jp]) : lo2(acc[3][jp])) + pb + s4.w;
            *(float4*)(r1 + (size_t)o*HWSZ + pix) = col;
        }
}

// ================= Kernel 2: LN2 + FFN1 (128->512) + bias + GELU ================================
// 64-ol weight tiles -> 70KB smem -> 3 CTAs/SM (24 warps)
__global__ void __launch_bounds__(256,3) k2_ffn1(
    const float* __restrict__ n2w, const float* __restrict__ n2b,
    const float* __restrict__ w1, const float* __restrict__ b1)
{
    extern __shared__ float sm[];
    float* xs  = sm;             // 8192 [c][64]
    float* Ws  = xs + 8192;      // 8704 [c][68]
    float* red = Ws + 8704;      // 512

    const int tid = threadIdx.x;
    const int blk = blockIdx.x;
    const int b   = blk >> 10, rr = blk & 1023;
    const int y   = rr >> 2, xp0 = (rr & 3)*64;
    const float* rb = g_res1 + (size_t)b*128*HWSZ + (size_t)y*NWD + xp0;
    const int tg = tid & 15, og = tid >> 4;   // og in 0..15

    for (int idx = tid; idx < 2048; idx += 256) {
        int c = idx >> 4, t4 = idx & 15;
        *(float4*)(xs + c*64 + t4*4) = *(const float4*)(rb + (size_t)c*HWSZ + t4*4);
    }
    __syncthreads();

    {   // LN2
        int t = tid & 63, q = tid >> 6;
        float s = 0.f, ss = 0.f;
#pragma unroll
        for (int cc = 0; cc < 32; cc++) {
            float v = xs[(q*32+cc)*64 + t];
            s += v; ss += v*v;
        }
        red[q*64+t] = s; red[256 + q*64+t] = ss;
        __syncthreads();
        s  = red[t] + red[64+t] + red[128+t] + red[192+t];
        ss = red[256+t] + red[320+t] + red[384+t] + red[448+t];
        float mu   = s*(1.f/128.f);
        float rstd = rsqrtf(ss*(1.f/128.f) - mu*mu + 1e-6f);
#pragma unroll
        for (int cc = 0; cc < 32; cc++) {
            int c = q*32+cc;
            xs[c*64+t] = (xs[c*64+t]-mu)*rstd*n2w[c] + n2b[c];
        }
    }
    __syncthreads();

    float* hb = g_h1 + (size_t)b*512*HWSZ + (size_t)y*NWD + xp0;
    for (int ot = 0; ot < 8; ot++) {
        for (int idx = tid; idx < 8192; idx += 256) {
            int c = idx & 127, ol = idx >> 7;   // ol in 0..63
            Ws[c*68 + ol] = w1[(size_t)(ot*64+ol)*128 + c];
        }
        __syncthreads();
        u64 acc[4][2];
#pragma unroll
        for (int r = 0; r < 4; r++) { acc[r][0] = 0ull; acc[r][1] = 0ull; }
        gemm44<128,68>(xs, Ws, tg, og, acc);
#pragma unroll
        for (int jp = 0; jp < 2; jp++)
#pragma unroll
            for (int h = 0; h < 2; h++) {
                int o = ot*64 + og*4 + jp*2 + h;
                float bb = b1[o];
                float4 col;
                col.x = gelu_f((h ? hi2(acc[0][jp]) : lo2(acc[0][jp])) + bb);
                col.y = gelu_f((h ? hi2(acc[1][jp]) : lo2(acc[1][jp])) + bb);
                col.z = gelu_f((h ? hi2(acc[2][jp]) : lo2(acc[2][jp])) + bb);
                col.w = gelu_f((h ? hi2(acc[3][jp]) : lo2(acc[3][jp])) + bb);
                *(float4*)(hb + (size_t)o*HWSZ + tg*4) = col;
            }
        __syncthreads();
    }
}

// ================= Kernel 3: depthwise 3x3 + GELU + FFN2 (512->128) + bias + residual ===========
__global__ void __launch_bounds__(256,2) k3_ffn2(
    const float* __restrict__ dw, const float* __restrict__ dwb,
    const float* __restrict__ w2, const float* __restrict__ b2,
    float* __restrict__ out)
{
    extern __shared__ float sm[];
    float* hs = sm;              // 6464 [ch][101] halo
    float* gs = hs + 6464;       // 4096 [ch][64] post-dw+gelu
    float* Ws = gs + 4096;       // 8448 [ch][132]

    const int tid = threadIdx.x;
    const int blk = blockIdx.x;
    const int b   = blk >> 10, rr = blk & 1023;
    const int y0  = (rr >> 5) << 3, xw = (rr & 31) << 3;
    const float* hbase = g_h1 + (size_t)b*512*HWSZ;
    const int tg = tid & 15, cg = tid >> 4;

    u64 acc[4][4];
#pragma unroll
    for (int r = 0; r < 4; r++)
#pragma unroll
        for (int jp = 0; jp < 4; jp++) acc[r][jp] = 0ull;

    for (int ck = 0; ck < 8; ck++) {
        const int c0 = ck*64;
        for (int idx = tid; idx < 6400; idx += 256) {
            int ch = idx / 100;
            int p  = idx - ch*100;
            int pr = p / 10;
            int py = y0 - 1 + pr;
            int px = xw - 1 + (p - pr*10);
            float v = 0.f;
            if ((unsigned)py < 256u && (unsigned)px < 256u)
                v = hbase[(size_t)(c0+ch)*HWSZ + py*NWD + px];
            hs[ch*101 + p] = v;
        }
        for (int idx = tid; idx < 8192; idx += 256) {
            int chl = idx & 63, ol = idx >> 6;
            Ws[chl*132 + ol] = w2[(size_t)ol*512 + c0 + chl];
        }
        __syncthreads();
        for (int idx = tid; idx < 4096; idx += 256) {
            int t = idx & 63, chl = idx >> 6;
            int ty = t >> 3, tx = t & 7;
            const float* dwp = dw + (size_t)(c0+chl)*9;
            const float* hp  = hs + chl*101;
            float s = 0.f;
#pragma unroll
            for (int ky = 0; ky < 3; ky++)
#pragma unroll
                for (int kx = 0; kx < 3; kx++)
                    s = fmaf(dwp[ky*3+kx], hp[(ty+ky)*10 + tx+kx], s);
            gs[chl*64 + t] = gelu_f(s + dwb[c0+chl]);
        }
        __syncthreads();
        gemm48<64>(gs, Ws, tg, cg, acc);
        __syncthreads();
    }

    const float* r1 = g_res1 + (size_t)b*128*HWSZ;
    float* ob = out + (size_t)b*128*HWSZ;
    const int t0 = tg*4;
    const size_t pix = (size_t)(y0 + (t0>>3))*NWD + xw + (t0&7);
#pragma unroll
    for (int jp = 0; jp < 4; jp++)
#pragma unroll
        for (int h = 0; h < 2; h++) {
            int o = cg*8 + jp*2 + h;
            float bb = b2[o];
            float4 s4 = *(const float4*)(r1 + (size_t)o*HWSZ + pix);
            float4 col;
            col.x = (h ? hi2(acc[0][jp]) : lo2(acc[0][jp])) + bb + s4.x;
            col.y = (h ? hi2(acc[1][jp]) : lo2(acc[1][jp])) + bb + s4.y;
            col.z = (h ? hi2(acc[2][jp]) : lo2(acc[2][jp])) + bb + s4.z;
            col.w = (h ? hi2(acc[3][jp]) : lo2(acc[3][jp])) + bb + s4.w;
            *(float4*)(ob + (size_t)o*HWSZ + pix) = col;
        }
}

// =================================================================================================
extern "C" void kernel_launch(void* const* d_in, const int* in_sizes, int n_in,
                              void* d_out, int out_size)
{
    const float* x    = (const float*)d_in[0];
    const float* l0   = (const float*)d_in[1];
    const float* n1w  = (const float*)d_in[2];
    const float* n1b  = (const float*)d_in[3];
    const float* n2w  = (const float*)d_in[4];
    const float* n2b  = (const float*)d_in[5];
    const float* qkvw = (const float*)d_in[6];
    const float* gw   = (const float*)d_in[7];
    const float* gb   = (const float*)d_in[8];
    const float* pw   = (const float*)d_in[9];
    const float* pb   = (const float*)d_in[10];
    const float* w1   = (const float*)d_in[11];
    const float* b1   = (const float*)d_in[12];
    const float* dwv  = (const float*)d_in[13];
    const float* dwb  = (const float*)d_in[14];
    const float* w2   = (const float*)d_in[15];
    const float* b2   = (const float*)d_in[16];
    float* out = (float*)d_out;

    const int smem1 = (8192 + 3*8448 + 16896 + 64 + 1024) * (int)sizeof(float);  // 206080
    const int smem2 = (8192 + 8704 + 512) * (int)sizeof(float);                  //  69632
    const int smem3 = (6464 + 4096 + 8448) * (int)sizeof(float);                 //  76032

    cudaFuncSetAttribute(k1_attn, cudaFuncAttributeMaxDynamicSharedMemorySize, smem1);
    cudaFuncSetAttribute(k2_ffn1, cudaFuncAttributeMaxDynamicSharedMemorySize, smem2);
    cudaFuncSetAttribute(k3_ffn2, cudaFuncAttributeMaxDynamicSharedMemorySize, smem3);

    k1_attn<<<4096, 512, smem1>>>(x, l0, n1w, n1b, qkvw, gw, gb, pw, pb);
    k2_ffn1<<<4096, 256, smem2>>>(n2w, n2b, w1, b1);
    k3_ffn2<<<4096, 256, smem3>>>(dwv, dwb, w2, b2, out);
}

// round 6
// speedup vs baseline: 2.2947x; 1.0883x over previous
#include <cuda_runtime.h>
#include <math.h>

#define HWSZ 65536
#define NWD  256
typedef unsigned long long u64;

__device__ float g_res1[4ull*128*HWSZ];
__device__ float g_h1  [4ull*512*HWSZ];

__device__ __forceinline__ u64 pk2(float lo, float hi){ u64 r; asm("mov.b64 %0,{%1,%2};":"=l"(r):"f"(lo),"f"(hi)); return r; }
__device__ __forceinline__ u64 dup2(float v){ return pk2(v, v); }
__device__ __forceinline__ void fma2(u64& d, u64 a, u64 b){ asm("fma.rn.f32x2 %0,%1,%2,%0;":"+l"(d):"l"(a),"l"(b)); }
__device__ __forceinline__ float lo2(u64 v){ return __uint_as_float((unsigned)v); }
__device__ __forceinline__ float hi2(u64 v){ return __uint_as_float((unsigned)(v>>32)); }
__device__ __forceinline__ float gelu_f(float v){ return 0.5f*v*(1.0f + erff(v*0.7071067811865475f)); }
__device__ __forceinline__ float sigm(float z){ return 1.f/(1.f + __expf(-z)); }

// 4t x 8ol packed GEMM core (k3, Ws stride 132)
template<int KC>
__device__ __forceinline__ void gemm48(const float* __restrict__ xs,
                                       const float* __restrict__ Ws,
                                       int tg, int og, u64 acc[4][4])
{
    const float* xp = xs + tg*4;
    const float* wp = Ws + og*8;
#pragma unroll 8
    for (int c = 0; c < KC; c++) {
        float4 xv = *(const float4*)(xp + c*64);
        ulonglong2 wA = *(const ulonglong2*)(wp + c*132);
        ulonglong2 wB = *(const ulonglong2*)(wp + c*132 + 4);
        u64 x0 = dup2(xv.x), x1 = dup2(xv.y), x2 = dup2(xv.z), x3 = dup2(xv.w);
        fma2(acc[0][0], x0, wA.x); fma2(acc[0][1], x0, wA.y); fma2(acc[0][2], x0, wB.x); fma2(acc[0][3], x0, wB.y);
        fma2(acc[1][0], x1, wA.x); fma2(acc[1][1], x1, wA.y); fma2(acc[1][2], x1, wB.x); fma2(acc[1][3], x1, wB.y);
        fma2(acc[2][0], x2, wA.x); fma2(acc[2][1], x2, wA.y); fma2(acc[2][2], x2, wB.x); fma2(acc[2][3], x2, wB.y);
        fma2(acc[3][0], x3, wA.x); fma2(acc[3][1], x3, wA.y); fma2(acc[3][2], x3, wB.x); fma2(acc[3][3], x3, wB.y);
    }
}

// 4t x 4ol packed GEMM core (k1 proj)
template<int KC, int WSTR>
__device__ __forceinline__ void gemm44(const float* __restrict__ xs,
                                       const float* __restrict__ Ws,
                                       int tg, int og, u64 acc[4][2])
{
    const float* xp = xs + tg*4;
    const float* wp = Ws + og*4;
#pragma unroll 8
    for (int c = 0; c < KC; c++) {
        float4 xv = *(const float4*)(xp + c*64);
        ulonglong2 w = *(const ulonglong2*)(wp + c*WSTR);
        u64 x0 = dup2(xv.x), x1 = dup2(xv.y), x2 = dup2(xv.z), x3 = dup2(xv.w);
        fma2(acc[0][0], x0, w.x); fma2(acc[0][1], x0, w.y);
        fma2(acc[1][0], x1, w.x); fma2(acc[1][1], x1, w.y);
        fma2(acc[2][0], x2, w.x); fma2(acc[2][1], x2, w.y);
        fma2(acc[3][0], x3, w.x); fma2(acc[3][1], x3, w.y);
    }
}

// ================= Kernel 1: LN1 + fused QKV sweep + gate + attention + proj + residual =========
#define K1_WB 6336      // 16 c x 396 (384 ol + pad)
__global__ void __launch_bounds__(512,1) k1_attn(
    const float* __restrict__ x, const float* __restrict__ l0,
    const float* __restrict__ n1w, const float* __restrict__ n1b,
    const float* __restrict__ qkvw,
    const float* __restrict__ gw, const float* __restrict__ gbv,
    const float* __restrict__ pw, const float* __restrict__ pbv)
{
    extern __shared__ float sm[];
    float* xs  = sm;             // 8192  [c][64]
    float* qt  = xs + 8192;      // 8448  [t][132]
    float* kt  = qt + 8448;      // 8448  (reused as proj weight store, with vt)
    float* vt  = kt + 8448;      // 8448
    float* Wb  = vt + 8448;      // 2 * 6336 chunk buffers
    float* l0s = Wb + 2*K1_WB;   // 64
    float* red = l0s + 64;       // 1024

    const int tid = threadIdx.x;
    const int blk = blockIdx.x;
    const int b   = blk >> 10, wr = blk & 1023;
    const int y0  = (wr >> 5) << 3, xw = (wr & 31) << 3;
    const float* xb = x + (size_t)b*128*HWSZ;
    const int tg4  = tid & 15;      // 16 t-groups of 4
    const int og12 = tid >> 4;      // 32 ol-groups of 12 (covers 384)

    for (int idx = tid; idx < 8192; idx += 512) {
        int c = idx >> 6, t = idx & 63;
        xs[c*64 + t] = xb[(size_t)c*HWSZ + (y0 + (t>>3))*NWD + xw + (t&7)];
    }
    if (tid < 64) l0s[tid] = l0[(size_t)b*HWSZ + (y0 + (tid>>3))*NWD + xw + (tid&7)];
    __syncthreads();

    // LayerNorm
    {
        int t = tid & 63, q8 = tid >> 6;
        float s = 0.f, ss = 0.f;
#pragma unroll
        for (int cc = 0; cc < 16; cc++) {
            float v = xs[(q8*16+cc)*64 + t];
            s += v; ss += v*v;
        }
        red[q8*64+t] = s; red[512 + q8*64+t] = ss;
        __syncthreads();
        s = 0.f; ss = 0.f;
#pragma unroll
        for (int k = 0; k < 8; k++) { s += red[k*64+t]; ss += red[512 + k*64+t]; }
        float mu   = s*(1.f/128.f);
        float rstd = rsqrtf(ss*(1.f/128.f) - mu*mu + 1e-6f);
#pragma unroll
        for (int cc = 0; cc < 16; cc++) {
            int c = q8*16+cc;
            xs[c*64+t] = (xs[c*64+t]-mu)*rstd*n1w[c] + n1b[c];
        }
    }

    // ---- fused QKV sweep: 64t x 384ol, weights streamed in 16-c chunks ----
    u64 acc[4][6];
#pragma unroll
    for (int r = 0; r < 4; r++)
#pragma unroll
        for (int p = 0; p < 6; p++) acc[r][p] = 0ull;

    // stage chunk 0
    {
#pragma unroll
        for (int i = 0; i < 12; i++) {
            int idx = tid + i*512;
            int cc = idx & 15, o = idx >> 4;
            Wb[cc*396 + o] = qkvw[(size_t)o*128 + cc];
        }
    }
    __syncthreads();

    for (int ck = 0; ck < 8; ck++) {
        const float* Wcur = Wb + (ck & 1)*K1_WB;
        float pf[12];
        if (ck < 7) {
            int c0n = (ck+1)*16;
#pragma unroll
            for (int i = 0; i < 12; i++) {
                int idx = tid + i*512;
                int cc = idx & 15, o = idx >> 4;
                pf[i] = qkvw[(size_t)o*128 + c0n + cc];
            }
        }
        const int c0 = ck*16;
        const float* wrow0 = Wcur + og12*12;
#pragma unroll 4
        for (int cc = 0; cc < 16; cc++) {
            float4 xv = *(const float4*)(xs + (c0+cc)*64 + tg4*4);
            const float* wrow = wrow0 + cc*396;
            ulonglong2 wA = *(const ulonglong2*)(wrow);
            ulonglong2 wB = *(const ulonglong2*)(wrow + 4);
            ulonglong2 wC = *(const ulonglong2*)(wrow + 8);
            u64 x0 = dup2(xv.x), x1 = dup2(xv.y), x2 = dup2(xv.z), x3 = dup2(xv.w);
            fma2(acc[0][0], x0, wA.x); fma2(acc[0][1], x0, wA.y); fma2(acc[0][2], x0, wB.x);
            fma2(acc[0][3], x0, wB.y); fma2(acc[0][4], x0, wC.x); fma2(acc[0][5], x0, wC.y);
            fma2(acc[1][0], x1, wA.x); fma2(acc[1][1], x1, wA.y); fma2(acc[1][2], x1, wB.x);
            fma2(acc[1][3], x1, wB.y); fma2(acc[1][4], x1, wC.x); fma2(acc[1][5], x1, wC.y);
            fma2(acc[2][0], x2, wA.x); fma2(acc[2][1], x2, wA.y); fma2(acc[2][2], x2, wB.x);
            fma2(acc[2][3], x2, wB.y); fma2(acc[2][4], x2, wC.x); fma2(acc[2][5], x2, wC.y);
            fma2(acc[3][0], x3, wA.x); fma2(acc[3][1], x3, wA.y); fma2(acc[3][2], x3, wB.x);
            fma2(acc[3][3], x3, wB.y); fma2(acc[3][4], x3, wC.x); fma2(acc[3][5], x3, wC.y);
        }
        if (ck < 7) {
            float* Wnext = Wb + ((ck+1) & 1)*K1_WB;
#pragma unroll
            for (int i = 0; i < 12; i++) {
                int idx = tid + i*512;
                int cc = idx & 15, o = idx >> 4;
                Wnext[cc*396 + o] = pf[i];
            }
        }
        __syncthreads();
    }

    // QKV epilogue -> qt/kt/vt token-major, gate on q
#pragma unroll
    for (int r = 0; r < 4; r++) {
        int t = tg4*4 + r;
        float lv = l0s[t];
#pragma unroll
        for (int p = 0; p < 6; p++) {
            int ol = og12*12 + p*2;
            float lo = lo2(acc[r][p]), hi = hi2(acc[r][p]);
            int seg = ol >> 7, loc = ol & 127;
            float* dst = (seg == 0) ? qt : (seg == 1) ? kt : vt;
            if (seg == 0) {
                lo *= sigm(lv*gw[ol]   + gbv[ol]);
                hi *= sigm(lv*gw[ol+1] + gbv[ol+1]);
            }
            *(u64*)(dst + t*132 + loc) = pk2(lo, hi);
        }
    }
    __syncthreads();

    // ---- attention: 8 heads x 64 threads, register-resident ----
    {
        int i = tid & 63, hd = tid >> 6;
        const int qo = hd*16;
        const ulonglong2* qp = (const ulonglong2*)(qt + i*132 + qo);
        ulonglong2 qa = qp[0], qb = qp[1], qc = qp[2], qd = qp[3];

        float p[64];
#pragma unroll
        for (int j = 0; j < 64; j++) {
            const ulonglong2* kp = (const ulonglong2*)(kt + j*132 + qo);
            ulonglong2 k0 = kp[0], k1 = kp[1], k2 = kp[2], k3 = kp[3];
            u64 a = 0ull;
            fma2(a, qa.x, k0.x); fma2(a, qa.y, k0.y);
            fma2(a, qb.x, k1.x); fma2(a, qb.y, k1.y);
            fma2(a, qc.x, k2.x); fma2(a, qc.y, k2.y);
            fma2(a, qd.x, k3.x); fma2(a, qd.y, k3.y);
            p[j] = (lo2(a) + hi2(a)) * 0.25f;
        }
        float m = p[0];
#pragma unroll
        for (int j = 1; j < 64; j++) m = fmaxf(m, p[j]);
        float s = 0.f;
#pragma unroll
        for (int j = 0; j < 64; j++) { p[j] = __expf(p[j] - m); s += p[j]; }
        float inv = 1.f/s;

        u64 o2[8];
#pragma unroll
        for (int d2 = 0; d2 < 8; d2++) o2[d2] = 0ull;
#pragma unroll
        for (int j = 0; j < 64; j++) {
            u64 pj = dup2(p[j]*inv);
            const ulonglong2* vp = (const ulonglong2*)(vt + j*132 + qo);
            ulonglong2 v0 = vp[0], v1 = vp[1], v2 = vp[2], v3 = vp[3];
            fma2(o2[0], pj, v0.x); fma2(o2[1], pj, v0.y);
            fma2(o2[2], pj, v1.x); fma2(o2[3], pj, v1.y);
            fma2(o2[4], pj, v2.x); fma2(o2[5], pj, v2.y);
            fma2(o2[6], pj, v3.x); fma2(o2[7], pj, v3.y);
        }
#pragma unroll
        for (int d2 = 0; d2 < 8; d2++) {
            xs[(qo + d2*2  )*64 + i] = lo2(o2[d2]);
            xs[(qo + d2*2+1)*64 + i] = hi2(o2[d2]);
        }
    }
    __syncthreads();   // attention done reading kt/vt before overwrite

    // proj weights -> kt region (16896 floats spans kt+vt exactly)
    float* Wsp = kt;
    for (int idx = tid; idx < 16384; idx += 512) {
        int c = idx & 127, ol = idx >> 7;
        Wsp[c*132 + ol] = pw[(size_t)ol*128 + c];
    }
    __syncthreads();
    {
        const int og = tid >> 4;   // 0..31
        u64 pacc[4][2];
#pragma unroll
        for (int r = 0; r < 4; r++) { pacc[r][0] = 0ull; pacc[r][1] = 0ull; }
        gemm44<128,132>(xs, Wsp, tg4, og, pacc);

        float* r1 = g_res1 + (size_t)b*128*HWSZ;
        const int t0 = tg4*4;
        const size_t pix = (size_t)(y0 + (t0>>3))*NWD + xw + (t0&7);
#pragma unroll
        for (int jp = 0; jp < 2; jp++)
#pragma unroll
            for (int h = 0; h < 2; h++) {
                int o = og*4 + jp*2 + h;
                float pb = pbv[o];
                float4 s4 = *(const float4*)(xb + (size_t)o*HWSZ + pix);
                float4 col;
                col.x = (h ? hi2(pacc[0][jp]) : lo2(pacc[0][jp])) + pb + s4.x;
                col.y = (h ? hi2(pacc[1][jp]) : lo2(pacc[1][jp])) + pb + s4.y;
                col.z = (h ? hi2(pacc[2][jp]) : lo2(pacc[2][jp])) + pb + s4.z;
                col.w = (h ? hi2(pacc[3][jp]) : lo2(pacc[3][jp])) + pb + s4.w;
                *(float4*)(r1 + (size_t)o*HWSZ + pix) = col;
            }
    }
}

// ================= Kernel 2: LN2 + FFN1 single 64x512 sweep + bias + GELU =======================
#define K2_WB 8384      // 16 c x 524 (512 ol + pad)
__global__ void __launch_bounds__(512,1) k2_ffn1(
    const float* __restrict__ n2w, const float* __restrict__ n2b,
    const float* __restrict__ w1, const float* __restrict__ b1)
{
    extern __shared__ float sm[];
    float* xs  = sm;             // 8192 [c][64]
    float* Wb  = xs + 8192;      // 2 * 8384
    float* red = Wb + 2*K2_WB;   // 1024

    const int tid = threadIdx.x;
    const int blk = blockIdx.x;
    const int b   = blk >> 10, rr = blk & 1023;
    const int y   = rr >> 2, xp0 = (rr & 3)*64;
    const float* rb = g_res1 + (size_t)b*128*HWSZ + (size_t)y*NWD + xp0;
    const int tg = tid & 7;      // 8 t-groups of 8
    const int og = tid >> 3;     // 64 ol-groups of 8

    for (int idx = tid; idx < 2048; idx += 512) {
        int c = idx >> 4, t4 = idx & 15;
        *(float4*)(xs + c*64 + t4*4) = *(const float4*)(rb + (size_t)c*HWSZ + t4*4);
    }
    __syncthreads();

    {   // LN2
        int t = tid & 63, q8 = tid >> 6;
        float s = 0.f, ss = 0.f;
#pragma unroll
        for (int cc = 0; cc < 16; cc++) {
            float v = xs[(q8*16+cc)*64 + t];
            s += v; ss += v*v;
        }
        red[q8*64+t] = s; red[512 + q8*64+t] = ss;
        __syncthreads();
        s = 0.f; ss = 0.f;
#pragma unroll
        for (int k = 0; k < 8; k++) { s += red[k*64+t]; ss += red[512 + k*64+t]; }
        float mu   = s*(1.f/128.f);
        float rstd = rsqrtf(ss*(1.f/128.f) - mu*mu + 1e-6f);
#pragma unroll
        for (int cc = 0; cc < 16; cc++) {
            int c = q8*16+cc;
            xs[c*64+t] = (xs[c*64+t]-mu)*rstd*n2w[c] + n2b[c];
        }
    }

    u64 acc[8][4];
#pragma unroll
    for (int r = 0; r < 8; r++)
#pragma unroll
        for (int jp = 0; jp < 4; jp++) acc[r][jp] = 0ull;

    // stage chunk 0
#pragma unroll
    for (int i = 0; i < 16; i++) {
        int idx = tid + i*512;
        int cc = idx & 15, o = idx >> 4;
        Wb[cc*524 + o] = w1[(size_t)o*128 + cc];
    }
    __syncthreads();

    for (int ck = 0; ck < 8; ck++) {
        const float* Wcur = Wb + (ck & 1)*K2_WB;
        float pf[16];
        if (ck < 7) {
            int c0n = (ck+1)*16;
#pragma unroll
            for (int i = 0; i < 16; i++) {
                int idx = tid + i*512;
                int cc = idx & 15, o = idx >> 4;
                pf[i] = w1[(size_t)o*128 + c0n + cc];
            }
        }
        const int c0 = ck*16;
        const float* xpA = xs + tg*8;
        const float* wrow0 = Wcur + og*8;
#pragma unroll 4
        for (int cc = 0; cc < 16; cc++) {
            float4 xa = *(const float4*)(xpA + (c0+cc)*64);
            float4 xb2 = *(const float4*)(xpA + (c0+cc)*64 + 4);
            const float* wrow = wrow0 + cc*524;
            ulonglong2 wA = *(const ulonglong2*)(wrow);
            ulonglong2 wB = *(const ulonglong2*)(wrow + 4);
            u64 x0 = dup2(xa.x), x1 = dup2(xa.y), x2 = dup2(xa.z), x3 = dup2(xa.w);
            u64 x4 = dup2(xb2.x), x5 = dup2(xb2.y), x6 = dup2(xb2.z), x7 = dup2(xb2.w);
            fma2(acc[0][0], x0, wA.x); fma2(acc[0][1], x0, wA.y); fma2(acc[0][2], x0, wB.x); fma2(acc[0][3], x0, wB.y);
            fma2(acc[1][0], x1, wA.x); fma2(acc[1][1], x1, wA.y); fma2(acc[1][2], x1, wB.x); fma2(acc[1][3], x1, wB.y);
            fma2(acc[2][0], x2, wA.x); fma2(acc[2][1], x2, wA.y); fma2(acc[2][2], x2, wB.x); fma2(acc[2][3], x2, wB.y);
            fma2(acc[3][0], x3, wA.x); fma2(acc[3][1], x3, wA.y); fma2(acc[3][2], x3, wB.x); fma2(acc[3][3], x3, wB.y);
            fma2(acc[4][0], x4, wA.x); fma2(acc[4][1], x4, wA.y); fma2(acc[4][2], x4, wB.x); fma2(acc[4][3], x4, wB.y);
            fma2(acc[5][0], x5, wA.x); fma2(acc[5][1], x5, wA.y); fma2(acc[5][2], x5, wB.x); fma2(acc[5][3], x5, wB.y);
            fma2(acc[6][0], x6, wA.x); fma2(acc[6][1], x6, wA.y); fma2(acc[6][2], x6, wB.x); fma2(acc[6][3], x6, wB.y);
            fma2(acc[7][0], x7, wA.x); fma2(acc[7][1], x7, wA.y); fma2(acc[7][2], x7, wB.x); fma2(acc[7][3], x7, wB.y);
        }
        if (ck < 7) {
            float* Wnext = Wb + ((ck+1) & 1)*K2_WB;
#pragma unroll
            for (int i = 0; i < 16; i++) {
                int idx = tid + i*512;
                int cc = idx & 15, o = idx >> 4;
                Wnext[cc*524 + o] = pf[i];
            }
        }
        __syncthreads();
    }

    float* hb = g_h1 + (size_t)b*512*HWSZ + (size_t)y*NWD + xp0;
#pragma unroll
    for (int jp = 0; jp < 4; jp++)
#pragma unroll
        for (int h = 0; h < 2; h++) {
            int o = og*8 + jp*2 + h;
            float bb = b1[o];
            float4 cA, cB;
            cA.x = gelu_f((h ? hi2(acc[0][jp]) : lo2(acc[0][jp])) + bb);
            cA.y = gelu_f((h ? hi2(acc[1][jp]) : lo2(acc[1][jp])) + bb);
            cA.z = gelu_f((h ? hi2(acc[2][jp]) : lo2(acc[2][jp])) + bb);
            cA.w = gelu_f((h ? hi2(acc[3][jp]) : lo2(acc[3][jp])) + bb);
            cB.x = gelu_f((h ? hi2(acc[4][jp]) : lo2(acc[4][jp])) + bb);
            cB.y = gelu_f((h ? hi2(acc[5][jp]) : lo2(acc[5][jp])) + bb);
            cB.z = gelu_f((h ? hi2(acc[6][jp]) : lo2(acc[6][jp])) + bb);
            cB.w = gelu_f((h ? hi2(acc[7][jp]) : lo2(acc[7][jp])) + bb);
            *(float4*)(hb + (size_t)o*HWSZ + tg*8)     = cA;
            *(float4*)(hb + (size_t)o*HWSZ + tg*8 + 4) = cB;
        }
}

// ================= Kernel 3: depthwise 3x3 + GELU + FFN2 (512->128) + bias + residual ===========
__global__ void __launch_bounds__(256,2) k3_ffn2(
    const float* __restrict__ dw, const float* __restrict__ dwb,
    const float* __restrict__ w2, const float* __restrict__ b2,
    float* __restrict__ out)
{
    extern __shared__ float sm[];
    float* hs = sm;              // 8192 [ch][10 rows x 12 stride] halo
    float* gs = hs + 8192;       // 4096 [ch][64]
    float* Ws = gs + 4096;       // 8448 [ch][132]

    const int tid = threadIdx.x;
    const int blk = blockIdx.x;
    const int b   = blk >> 10, rr = blk & 1023;
    const int y0  = (rr >> 5) << 3, xw = (rr & 31) << 3;
    const float* hbase = g_h1 + (size_t)b*512*HWSZ;
    const int tg = tid & 15, cg = tid >> 4;

    u64 acc[4][4];
#pragma unroll
    for (int r = 0; r < 4; r++)
#pragma unroll
        for (int jp = 0; jp < 4; jp++) acc[r][jp] = 0ull;

    for (int ck = 0; ck < 8; ck++) {
        const int c0 = ck*64;
        for (int idx = tid; idx < 6400; idx += 256) {
            int ch = idx / 100;
            int p  = idx - ch*100;
            int pr = p / 10;
            int pc = p - pr*10;
            int py = y0 - 1 + pr;
            int px = xw - 1 + pc;
            float v = 0.f;
            if ((unsigned)py < 256u && (unsigned)px < 256u)
                v = hbase[(size_t)(c0+ch)*HWSZ + py*NWD + px];
            hs[ch*128 + pr*12 + pc] = v;
        }
        for (int idx = tid; idx < 8192; idx += 256) {
            int chl = idx & 63, ol = idx >> 6;
            Ws[chl*132 + ol] = w2[(size_t)ol*512 + c0 + chl];
        }
        __syncthreads();
        // depthwise conv: thread = (chl, row), 8-wide vectorized row
#pragma unroll
        for (int k = 0; k < 2; k++) {
            int u   = tid + k*256;
            int chl = u >> 3, row = u & 7;
            const float* dwp = dw + (size_t)(c0+chl)*9;
            const float* hp  = hs + chl*128 + row*12;
            float o8[8];
            float bbv = dwb[c0+chl];
#pragma unroll
            for (int xp = 0; xp < 8; xp++) o8[xp] = bbv;
#pragma unroll
            for (int ky = 0; ky < 3; ky++) {
                const float* rp = hp + ky*12;
                float4 ra = *(const float4*)(rp);
                float4 rb4 = *(const float4*)(rp + 4);
                float2 rc = *(const float2*)(rp + 8);
                float rw[10] = {ra.x, ra.y, ra.z, ra.w, rb4.x, rb4.y, rb4.z, rb4.w, rc.x, rc.y};
                float d0 = dwp[ky*3], d1 = dwp[ky*3+1], d2 = dwp[ky*3+2];
#pragma unroll
                for (int xp = 0; xp < 8; xp++)
                    o8[xp] = fmaf(d0, rw[xp], fmaf(d1, rw[xp+1], fmaf(d2, rw[xp+2], o8[xp])));
            }
            float4 gA, gB;
            gA.x = gelu_f(o8[0]); gA.y = gelu_f(o8[1]); gA.z = gelu_f(o8[2]); gA.w = gelu_f(o8[3]);
            gB.x = gelu_f(o8[4]); gB.y = gelu_f(o8[5]); gB.z = gelu_f(o8[6]); gB.w = gelu_f(o8[7]);
            *(float4*)(gs + chl*64 + row*8)     = gA;
            *(float4*)(gs + chl*64 + row*8 + 4) = gB;
        }
        __syncthreads();
        gemm48<64>(gs, Ws, tg, cg, acc);
        __syncthreads();
    }

    const float* r1 = g_res1 + (size_t)b*128*HWSZ;
    float* ob = out + (size_t)b*128*HWSZ;
    const int t0 = tg*4;
    const size_t pix = (size_t)(y0 + (t0>>3))*NWD + xw + (t0&7);
#pragma unroll
    for (int jp = 0; jp < 4; jp++)
#pragma unroll
        for (int h = 0; h < 2; h++) {
            int o = cg*8 + jp*2 + h;
            float bb = b2[o];
            float4 s4 = *(const float4*)(r1 + (size_t)o*HWSZ + pix);
            float4 col;
            col.x = (h ? hi2(acc[0][jp]) : lo2(acc[0][jp])) + bb + s4.x;
            col.y = (h ? hi2(acc[1][jp]) : lo2(acc[1][jp])) + bb + s4.y;
            col.z = (h ? hi2(acc[2][jp]) : lo2(acc[2][jp])) + bb + s4.z;
            col.w = (h ? hi2(acc[3][jp]) : lo2(acc[3][jp])) + bb + s4.w;
            *(float4*)(ob + (size_t)o*HWSZ + pix) = col;
        }
}

// =================================================================================================
extern "C" void kernel_launch(void* const* d_in, const int* in_sizes, int n_in,
                              void* d_out, int out_size)
{
    const float* x    = (const float*)d_in[0];
    const float* l0   = (const float*)d_in[1];
    const float* n1w  = (const float*)d_in[2];
    const float* n1b  = (const float*)d_in[3];
    const float* n2w  = (const float*)d_in[4];
    const float* n2b  = (const float*)d_in[5];
    const float* qkvw = (const float*)d_in[6];
    const float* gw   = (const float*)d_in[7];
    const float* gb   = (const float*)d_in[8];
    const float* pw   = (const float*)d_in[9];
    const float* pb   = (const float*)d_in[10];
    const float* w1   = (const float*)d_in[11];
    const float* b1   = (const float*)d_in[12];
    const float* dwv  = (const float*)d_in[13];
    const float* dwb  = (const float*)d_in[14];
    const float* w2   = (const float*)d_in[15];
    const float* b2   = (const float*)d_in[16];
    float* out = (float*)d_out;

    const int smem1 = (8192 + 3*8448 + 2*K1_WB + 64 + 1024) * (int)sizeof(float);  // 189184
    const int smem2 = (8192 + 2*K2_WB + 1024) * (int)sizeof(float);                // 103936
    const int smem3 = (8192 + 4096 + 8448) * (int)sizeof(float);                   //  82944

    cudaFuncSetAttribute(k1_attn, cudaFuncAttributeMaxDynamicSharedMemorySize, smem1);
    cudaFuncSetAttribute(k2_ffn1, cudaFuncAttributeMaxDynamicSharedMemorySize, smem2);
    cudaFuncSetAttribute(k3_ffn2, cudaFuncAttributeMaxDynamicSharedMemorySize, smem3);

    k1_attn<<<4096, 512, smem1>>>(x, l0, n1w, n1b, qkvw, gw, gb, pw, pb);
    k2_ffn1<<<4096, 512, smem2>>>(n2w, n2b, w1, b1);
    k3_ffn2<<<4096, 256, smem3>>>(dwv, dwb, w2, b2, out);
}

// round 7
// speedup vs baseline: 2.4206x; 1.0548x over previous
#include <cuda_runtime.h>
#include <math.h>

#define HWSZ 65536
#define NWD  256
typedef unsigned long long u64;

__device__ float g_res1[4ull*128*HWSZ];
__device__ float g_h1  [4ull*512*HWSZ];

__device__ __forceinline__ u64 pk2(float lo, float hi){ u64 r; asm("mov.b64 %0,{%1,%2};":"=l"(r):"f"(lo),"f"(hi)); return r; }
__device__ __forceinline__ u64 dup2(float v){ return pk2(v, v); }
__device__ __forceinline__ void fma2(u64& d, u64 a, u64 b){ asm("fma.rn.f32x2 %0,%1,%2,%0;":"+l"(d):"l"(a),"l"(b)); }
__device__ __forceinline__ u64 mul2(u64 a, u64 b){ u64 d; asm("mul.rn.f32x2 %0,%1,%2;":"=l"(d):"l"(a),"l"(b)); return d; }
__device__ __forceinline__ float lo2(u64 v){ return __uint_as_float((unsigned)v); }
__device__ __forceinline__ float hi2(u64 v){ return __uint_as_float((unsigned)(v>>32)); }
__device__ __forceinline__ float gelu_f(float v){ return 0.5f*v*(1.0f + erff(v*0.7071067811865475f)); }
__device__ __forceinline__ float sigm(float z){ return 1.f/(1.f + __expf(-z)); }

// 4t x 4ol packed GEMM core
template<int KC, int WSTR>
__device__ __forceinline__ void gemm44(const float* __restrict__ xs,
                                       const float* __restrict__ Ws,
                                       int tg, int og, u64 acc[4][2])
{
    const float* xp = xs + tg*4;
    const float* wp = Ws + og*4;
#pragma unroll 8
    for (int c = 0; c < KC; c++) {
        float4 xv = *(const float4*)(xp + c*64);
        ulonglong2 w = *(const ulonglong2*)(wp + c*WSTR);
        u64 x0 = dup2(xv.x), x1 = dup2(xv.y), x2 = dup2(xv.z), x3 = dup2(xv.w);
        fma2(acc[0][0], x0, w.x); fma2(acc[0][1], x0, w.y);
        fma2(acc[1][0], x1, w.x); fma2(acc[1][1], x1, w.y);
        fma2(acc[2][0], x2, w.x); fma2(acc[2][1], x2, w.y);
        fma2(acc[3][0], x3, w.x); fma2(acc[3][1], x3, w.y);
    }
}

// ================= Kernel 1: LN1 + fused QKV sweep + gate + attention + proj + residual =========
#define K1_WB 6336      // 16 c x 396
__global__ void __launch_bounds__(512,1) k1_attn(
    const float* __restrict__ x, const float* __restrict__ l0,
    const float* __restrict__ n1w, const float* __restrict__ n1b,
    const float* __restrict__ qkvw,
    const float* __restrict__ gw, const float* __restrict__ gbv,
    const float* __restrict__ pw, const float* __restrict__ pbv)
{
    extern __shared__ float sm[];
    float* xs  = sm;             // 8192  [c][64]
    float* qt  = xs + 8192;      // 8448  [t][132]
    float* kt  = qt + 8448;      // 8448
    float* vt  = kt + 8448;      // 8448
    float* Wb  = vt + 8448;      // 2 * 6336
    float* l0s = Wb + 2*K1_WB;   // 64
    float* red = l0s + 64;       // 1024

    const int tid = threadIdx.x;
    const int blk = blockIdx.x;
    const int b   = blk >> 10, wr = blk & 1023;
    const int y0  = (wr >> 5) << 3, xw = (wr & 31) << 3;
    const float* xb = x + (size_t)b*128*HWSZ;
    const int tg4  = tid & 15;
    const int og12 = tid >> 4;

    for (int idx = tid; idx < 8192; idx += 512) {
        int c = idx >> 6, t = idx & 63;
        xs[c*64 + t] = xb[(size_t)c*HWSZ + (y0 + (t>>3))*NWD + xw + (t&7)];
    }
    if (tid < 64) l0s[tid] = l0[(size_t)b*HWSZ + (y0 + (tid>>3))*NWD + xw + (tid&7)];
    __syncthreads();

    // LayerNorm
    {
        int t = tid & 63, q8 = tid >> 6;
        float s = 0.f, ss = 0.f;
#pragma unroll
        for (int cc = 0; cc < 16; cc++) {
            float v = xs[(q8*16+cc)*64 + t];
            s += v; ss += v*v;
        }
        red[q8*64+t] = s; red[512 + q8*64+t] = ss;
        __syncthreads();
        s = 0.f; ss = 0.f;
#pragma unroll
        for (int k = 0; k < 8; k++) { s += red[k*64+t]; ss += red[512 + k*64+t]; }
        float mu   = s*(1.f/128.f);
        float rstd = rsqrtf(ss*(1.f/128.f) - mu*mu + 1e-6f);
#pragma unroll
        for (int cc = 0; cc < 16; cc++) {
            int c = q8*16+cc;
            xs[c*64+t] = (xs[c*64+t]-mu)*rstd*n1w[c] + n1b[c];
        }
    }

    // ---- fused QKV sweep: 64t x 384ol, weights streamed in 16-c chunks ----
    u64 acc[4][6];
#pragma unroll
    for (int r = 0; r < 4; r++)
#pragma unroll
        for (int p = 0; p < 6; p++) acc[r][p] = 0ull;

#pragma unroll
    for (int i = 0; i < 12; i++) {
        int idx = tid + i*512;
        int cc = idx & 15, o = idx >> 4;
        Wb[cc*396 + o] = qkvw[(size_t)o*128 + cc];
    }
    __syncthreads();

    for (int ck = 0; ck < 8; ck++) {
        const float* Wcur = Wb + (ck & 1)*K1_WB;
        float pf[12];
        if (ck < 7) {
            int c0n = (ck+1)*16;
#pragma unroll
            for (int i = 0; i < 12; i++) {
                int idx = tid + i*512;
                int cc = idx & 15, o = idx >> 4;
                pf[i] = qkvw[(size_t)o*128 + c0n + cc];
            }
        }
        const int c0 = ck*16;
        const float* wrow0 = Wcur + og12*12;
#pragma unroll 4
        for (int cc = 0; cc < 16; cc++) {
            float4 xv = *(const float4*)(xs + (c0+cc)*64 + tg4*4);
            const float* wrow = wrow0 + cc*396;
            ulonglong2 wA = *(const ulonglong2*)(wrow);
            ulonglong2 wB = *(const ulonglong2*)(wrow + 4);
            ulonglong2 wC = *(const ulonglong2*)(wrow + 8);
            u64 x0 = dup2(xv.x), x1 = dup2(xv.y), x2 = dup2(xv.z), x3 = dup2(xv.w);
            fma2(acc[0][0], x0, wA.x); fma2(acc[0][1], x0, wA.y); fma2(acc[0][2], x0, wB.x);
            fma2(acc[0][3], x0, wB.y); fma2(acc[0][4], x0, wC.x); fma2(acc[0][5], x0, wC.y);
            fma2(acc[1][0], x1, wA.x); fma2(acc[1][1], x1, wA.y); fma2(acc[1][2], x1, wB.x);
            fma2(acc[1][3], x1, wB.y); fma2(acc[1][4], x1, wC.x); fma2(acc[1][5], x1, wC.y);
            fma2(acc[2][0], x2, wA.x); fma2(acc[2][1], x2, wA.y); fma2(acc[2][2], x2, wB.x);
            fma2(acc[2][3], x2, wB.y); fma2(acc[2][4], x2, wC.x); fma2(acc[2][5], x2, wC.y);
            fma2(acc[3][0], x3, wA.x); fma2(acc[3][1], x3, wA.y); fma2(acc[3][2], x3, wB.x);
            fma2(acc[3][3], x3, wB.y); fma2(acc[3][4], x3, wC.x); fma2(acc[3][5], x3, wC.y);
        }
        if (ck < 7) {
            float* Wnext = Wb + ((ck+1) & 1)*K1_WB;
#pragma unroll
            for (int i = 0; i < 12; i++) {
                int idx = tid + i*512;
                int cc = idx & 15, o = idx >> 4;
                Wnext[cc*396 + o] = pf[i];
            }
        }
        __syncthreads();
    }

    // QKV epilogue -> qt/kt/vt token-major, gate on q
#pragma unroll
    for (int r = 0; r < 4; r++) {
        int t = tg4*4 + r;
        float lv = l0s[t];
#pragma unroll
        for (int p = 0; p < 6; p++) {
            int ol = og12*12 + p*2;
            float lo = lo2(acc[r][p]), hi = hi2(acc[r][p]);
            int seg = ol >> 7, loc = ol & 127;
            float* dst = (seg == 0) ? qt : (seg == 1) ? kt : vt;
            if (seg == 0) {
                lo *= sigm(lv*gw[ol]   + gbv[ol]);
                hi *= sigm(lv*gw[ol+1] + gbv[ol+1]);
            }
            *(u64*)(dst + t*132 + loc) = pk2(lo, hi);
        }
    }
    __syncthreads();

    // ---- attention: 8 heads x 32 i-pairs (rows i, i+32), online softmax, no spills ----
    if (tid < 256) {
        const int ip = tid & 31, hd = tid >> 5;
        const int qo = hd*16;
        const ulonglong2* qpA = (const ulonglong2*)(qt + ip*132 + qo);
        const ulonglong2* qpB = (const ulonglong2*)(qt + (ip+32)*132 + qo);
        ulonglong2 qa0 = qpA[0], qa1 = qpA[1], qa2 = qpA[2], qa3 = qpA[3];
        ulonglong2 qb0 = qpB[0], qb1 = qpB[1], qb2 = qpB[2], qb3 = qpB[3];

        float mA = -1e30f, lA = 0.f, mB = -1e30f, lB = 0.f;
        u64 oA[8], oB[8];
#pragma unroll
        for (int d2 = 0; d2 < 8; d2++) { oA[d2] = 0ull; oB[d2] = 0ull; }

        for (int jc = 0; jc < 8; jc++) {
            float eA[8], eB[8];
            float cmA = -1e30f, cmB = -1e30f;
#pragma unroll
            for (int jj = 0; jj < 8; jj++) {
                int j = jc*8 + jj;
                const ulonglong2* kp = (const ulonglong2*)(kt + j*132 + qo);
                ulonglong2 k0 = kp[0], k1 = kp[1], k2 = kp[2], k3 = kp[3];
                u64 a = 0ull;
                fma2(a, qa0.x, k0.x); fma2(a, qa0.y, k0.y);
                fma2(a, qa1.x, k1.x); fma2(a, qa1.y, k1.y);
                fma2(a, qa2.x, k2.x); fma2(a, qa2.y, k2.y);
                fma2(a, qa3.x, k3.x); fma2(a, qa3.y, k3.y);
                float sA = (lo2(a) + hi2(a))*0.25f;
                u64 bq = 0ull;
                fma2(bq, qb0.x, k0.x); fma2(bq, qb0.y, k0.y);
                fma2(bq, qb1.x, k1.x); fma2(bq, qb1.y, k1.y);
                fma2(bq, qb2.x, k2.x); fma2(bq, qb2.y, k2.y);
                fma2(bq, qb3.x, k3.x); fma2(bq, qb3.y, k3.y);
                float sB = (lo2(bq) + hi2(bq))*0.25f;
                eA[jj] = sA; cmA = fmaxf(cmA, sA);
                eB[jj] = sB; cmB = fmaxf(cmB, sB);
            }
            float mnA = fmaxf(mA, cmA), mnB = fmaxf(mB, cmB);
            float scA = __expf(mA - mnA), scB = __expf(mB - mnB);
            mA = mnA; mB = mnB;
            float sumA = 0.f, sumB = 0.f;
#pragma unroll
            for (int jj = 0; jj < 8; jj++) {
                eA[jj] = __expf(eA[jj] - mA); sumA += eA[jj];
                eB[jj] = __expf(eB[jj] - mB); sumB += eB[jj];
            }
            lA = lA*scA + sumA; lB = lB*scB + sumB;
            u64 s2A = dup2(scA), s2B = dup2(scB);
#pragma unroll
            for (int d2 = 0; d2 < 8; d2++) {
                oA[d2] = mul2(oA[d2], s2A);
                oB[d2] = mul2(oB[d2], s2B);
            }
#pragma unroll
            for (int jj = 0; jj < 8; jj++) {
                int j = jc*8 + jj;
                const ulonglong2* vp = (const ulonglong2*)(vt + j*132 + qo);
                ulonglong2 v0 = vp[0], v1 = vp[1], v2 = vp[2], v3 = vp[3];
                u64 pA = dup2(eA[jj]), pB = dup2(eB[jj]);
                fma2(oA[0], pA, v0.x); fma2(oA[1], pA, v0.y);
                fma2(oA[2], pA, v1.x); fma2(oA[3], pA, v1.y);
                fma2(oA[4], pA, v2.x); fma2(oA[5], pA, v2.y);
                fma2(oA[6], pA, v3.x); fma2(oA[7], pA, v3.y);
                fma2(oB[0], pB, v0.x); fma2(oB[1], pB, v0.y);
                fma2(oB[2], pB, v1.x); fma2(oB[3], pB, v1.y);
                fma2(oB[4], pB, v2.x); fma2(oB[5], pB, v2.y);
                fma2(oB[6], pB, v3.x); fma2(oB[7], pB, v3.y);
            }
        }
        float invA = 1.f/lA, invB = 1.f/lB;
#pragma unroll
        for (int d2 = 0; d2 < 8; d2++) {
            xs[(qo + d2*2  )*64 + ip]      = lo2(oA[d2])*invA;
            xs[(qo + d2*2+1)*64 + ip]      = hi2(oA[d2])*invA;
            xs[(qo + d2*2  )*64 + ip + 32] = lo2(oB[d2])*invB;
            xs[(qo + d2*2+1)*64 + ip + 32] = hi2(oB[d2])*invB;
        }
    }
    __syncthreads();

    // proj weights -> kt region
    float* Wsp = kt;
    for (int idx = tid; idx < 16384; idx += 512) {
        int c = idx & 127, ol = idx >> 7;
        Wsp[c*132 + ol] = pw[(size_t)ol*128 + c];
    }
    __syncthreads();
    {
        const int og = tid >> 4;
        u64 pacc[4][2];
#pragma unroll
        for (int r = 0; r < 4; r++) { pacc[r][0] = 0ull; pacc[r][1] = 0ull; }
        gemm44<128,132>(xs, Wsp, tg4, og, pacc);

        float* r1 = g_res1 + (size_t)b*128*HWSZ;
        const int t0 = tg4*4;
        const size_t pix = (size_t)(y0 + (t0>>3))*NWD + xw + (t0&7);
#pragma unroll
        for (int jp = 0; jp < 2; jp++)
#pragma unroll
            for (int h = 0; h < 2; h++) {
                int o = og*4 + jp*2 + h;
                float pb = pbv[o];
                float4 s4 = *(const float4*)(xb + (size_t)o*HWSZ + pix);
                float4 col;
                col.x = (h ? hi2(pacc[0][jp]) : lo2(pacc[0][jp])) + pb + s4.x;
                col.y = (h ? hi2(pacc[1][jp]) : lo2(pacc[1][jp])) + pb + s4.y;
                col.z = (h ? hi2(pacc[2][jp]) : lo2(pacc[2][jp])) + pb + s4.z;
                col.w = (h ? hi2(pacc[3][jp]) : lo2(pacc[3][jp])) + pb + s4.w;
                *(float4*)(r1 + (size_t)o*HWSZ + pix) = col;
            }
    }
}

// ================= Kernel 2: LN2 + FFN1 single 64x512 sweep + bias + GELU =======================
#define K2_WB 8384      // 16 c x 524
__global__ void __launch_bounds__(512,1) k2_ffn1(
    const float* __restrict__ n2w, const float* __restrict__ n2b,
    const float* __restrict__ w1, const float* __restrict__ b1)
{
    extern __shared__ float sm[];
    float* xs  = sm;             // 8192 [c][64]
    float* Wb  = xs + 8192;      // 2 * 8384
    float* red = Wb + 2*K2_WB;   // 1024

    const int tid = threadIdx.x;
    const int blk = blockIdx.x;
    const int b   = blk >> 10, rr = blk & 1023;
    const int y   = rr >> 2, xp0 = (rr & 3)*64;
    const float* rb = g_res1 + (size_t)b*128*HWSZ + (size_t)y*NWD + xp0;
    const int tg = tid & 7;
    const int og = tid >> 3;

    for (int idx = tid; idx < 2048; idx += 512) {
        int c = idx >> 4, t4 = idx & 15;
        *(float4*)(xs + c*64 + t4*4) = *(const float4*)(rb + (size_t)c*HWSZ + t4*4);
    }
    __syncthreads();

    {   // LN2
        int t = tid & 63, q8 = tid >> 6;
        float s = 0.f, ss = 0.f;
#pragma unroll
        for (int cc = 0; cc < 16; cc++) {
            float v = xs[(q8*16+cc)*64 + t];
            s += v; ss += v*v;
        }
        red[q8*64+t] = s; red[512 + q8*64+t] = ss;
        __syncthreads();
        s = 0.f; ss = 0.f;
#pragma unroll
        for (int k = 0; k < 8; k++) { s += red[k*64+t]; ss += red[512 + k*64+t]; }
        float mu   = s*(1.f/128.f);
        float rstd = rsqrtf(ss*(1.f/128.f) - mu*mu + 1e-6f);
#pragma unroll
        for (int cc = 0; cc < 16; cc++) {
            int c = q8*16+cc;
            xs[c*64+t] = (xs[c*64+t]-mu)*rstd*n2w[c] + n2b[c];
        }
    }

    u64 acc[8][4];
#pragma unroll
    for (int r = 0; r < 8; r++)
#pragma unroll
        for (int jp = 0; jp < 4; jp++) acc[r][jp] = 0ull;

#pragma unroll
    for (int i = 0; i < 16; i++) {
        int idx = tid + i*512;
        int cc = idx & 15, o = idx >> 4;
        Wb[cc*524 + o] = w1[(size_t)o*128 + cc];
    }
    __syncthreads();

    for (int ck = 0; ck < 8; ck++) {
        const float* Wcur = Wb + (ck & 1)*K2_WB;
        float pf[16];
        if (ck < 7) {
            int c0n = (ck+1)*16;
#pragma unroll
            for (int i = 0; i < 16; i++) {
                int idx = tid + i*512;
                int cc = idx & 15, o = idx >> 4;
                pf[i] = w1[(size_t)o*128 + c0n + cc];
            }
        }
        const int c0 = ck*16;
        const float* xpA = xs + tg*4;          // rows tg*4..+3
        const float* xpB = xs + 32 + tg*4;     // rows 32+tg*4..+3
        const float* wrow0 = Wcur + og*8;
#pragma unroll 4
        for (int cc = 0; cc < 16; cc++) {
            float4 xa = *(const float4*)(xpA + (c0+cc)*64);
            float4 xb2 = *(const float4*)(xpB + (c0+cc)*64);
            const float* wrow = wrow0 + cc*524;
            ulonglong2 wA = *(const ulonglong2*)(wrow);
            ulonglong2 wB = *(const ulonglong2*)(wrow + 4);
            u64 x0 = dup2(xa.x), x1 = dup2(xa.y), x2 = dup2(xa.z), x3 = dup2(xa.w);
            u64 x4 = dup2(xb2.x), x5 = dup2(xb2.y), x6 = dup2(xb2.z), x7 = dup2(xb2.w);
            fma2(acc[0][0], x0, wA.x); fma2(acc[0][1], x0, wA.y); fma2(acc[0][2], x0, wB.x); fma2(acc[0][3], x0, wB.y);
            fma2(acc[1][0], x1, wA.x); fma2(acc[1][1], x1, wA.y); fma2(acc[1][2], x1, wB.x); fma2(acc[1][3], x1, wB.y);
            fma2(acc[2][0], x2, wA.x); fma2(acc[2][1], x2, wA.y); fma2(acc[2][2], x2, wB.x); fma2(acc[2][3], x2, wB.y);
            fma2(acc[3][0], x3, wA.x); fma2(acc[3][1], x3, wA.y); fma2(acc[3][2], x3, wB.x); fma2(acc[3][3], x3, wB.y);
            fma2(acc[4][0], x4, wA.x); fma2(acc[4][1], x4, wA.y); fma2(acc[4][2], x4, wB.x); fma2(acc[4][3], x4, wB.y);
            fma2(acc[5][0], x5, wA.x); fma2(acc[5][1], x5, wA.y); fma2(acc[5][2], x5, wB.x); fma2(acc[5][3], x5, wB.y);
            fma2(acc[6][0], x6, wA.x); fma2(acc[6][1], x6, wA.y); fma2(acc[6][2], x6, wB.x); fma2(acc[6][3], x6, wB.y);
            fma2(acc[7][0], x7, wA.x); fma2(acc[7][1], x7, wA.y); fma2(acc[7][2], x7, wB.x); fma2(acc[7][3], x7, wB.y);
        }
        if (ck < 7) {
            float* Wnext = Wb + ((ck+1) & 1)*K2_WB;
#pragma unroll
            for (int i = 0; i < 16; i++) {
                int idx = tid + i*512;
                int cc = idx & 15, o = idx >> 4;
                Wnext[cc*524 + o] = pf[i];
            }
        }
        __syncthreads();
    }

    float* hb = g_h1 + (size_t)b*512*HWSZ + (size_t)y*NWD + xp0;
#pragma unroll
    for (int jp = 0; jp < 4; jp++)
#pragma unroll
        for (int h = 0; h < 2; h++) {
            int o = og*8 + jp*2 + h;
            float bb = b1[o];
            float4 cA, cB;
            cA.x = gelu_f((h ? hi2(acc[0][jp]) : lo2(acc[0][jp])) + bb);
            cA.y = gelu_f((h ? hi2(acc[1][jp]) : lo2(acc[1][jp])) + bb);
            cA.z = gelu_f((h ? hi2(acc[2][jp]) : lo2(acc[2][jp])) + bb);
            cA.w = gelu_f((h ? hi2(acc[3][jp]) : lo2(acc[3][jp])) + bb);
            cB.x = gelu_f((h ? hi2(acc[4][jp]) : lo2(acc[4][jp])) + bb);
            cB.y = gelu_f((h ? hi2(acc[5][jp]) : lo2(acc[5][jp])) + bb);
            cB.z = gelu_f((h ? hi2(acc[6][jp]) : lo2(acc[6][jp])) + bb);
            cB.w = gelu_f((h ? hi2(acc[7][jp]) : lo2(acc[7][jp])) + bb);
            *(float4*)(hb + (size_t)o*HWSZ + tg*4)      = cA;
            *(float4*)(hb + (size_t)o*HWSZ + 32 + tg*4) = cB;
        }
}

// ================= Kernel 3: depthwise 3x3 + GELU + FFN2 (512->128) + bias + residual ===========
// Ws split into two 64-ol passes -> 65KB smem -> 3 CTAs/SM
__global__ void __launch_bounds__(256,3) k3_ffn2(
    const float* __restrict__ dw, const float* __restrict__ dwb,
    const float* __restrict__ w2, const float* __restrict__ b2,
    float* __restrict__ out)
{
    extern __shared__ float sm[];
    float* hs = sm;              // 8192 [ch][10 rows x 12 stride]
    float* gs = hs + 8192;       // 4096 [ch][64]
    float* Ws = gs + 4096;       // 4352 [ch][68] (one 64-ol half)

    const int tid = threadIdx.x;
    const int blk = blockIdx.x;
    const int b   = blk >> 10, rr = blk & 1023;
    const int y0  = (rr >> 5) << 3, xw = (rr & 31) << 3;
    const float* hbase = g_h1 + (size_t)b*512*HWSZ;
    const int tg = tid & 15, og = tid >> 4;

    u64 acc0[4][2], acc1[4][2];
#pragma unroll
    for (int r = 0; r < 4; r++) {
        acc0[r][0] = 0ull; acc0[r][1] = 0ull;
        acc1[r][0] = 0ull; acc1[r][1] = 0ull;
    }

    for (int ck = 0; ck < 8; ck++) {
        const int c0 = ck*64;
        for (int idx = tid; idx < 6400; idx += 256) {
            int ch = idx / 100;
            int p  = idx - ch*100;
            int pr = p / 10;
            int pc = p - pr*10;
            int py = y0 - 1 + pr;
            int px = xw - 1 + pc;
            float v = 0.f;
            if ((unsigned)py < 256u && (unsigned)px < 256u)
                v = hbase[(size_t)(c0+ch)*HWSZ + py*NWD + px];
            hs[ch*128 + pr*12 + pc] = v;
        }
        // weight half 0 (ol 0..63)
        for (int idx = tid; idx < 4096; idx += 256) {
            int chl = idx & 63, ol = idx >> 6;
            Ws[chl*68 + ol] = w2[(size_t)ol*512 + c0 + chl];
        }
        __syncthreads();
        // depthwise conv
#pragma unroll
        for (int k = 0; k < 2; k++) {
            int u   = tid + k*256;
            int chl = u >> 3, row = u & 7;
            const float* dwp = dw + (size_t)(c0+chl)*9;
            const float* hp  = hs + chl*128 + row*12;
            float o8[8];
            float bbv = dwb[c0+chl];
#pragma unroll
            for (int xp = 0; xp < 8; xp++) o8[xp] = bbv;
#pragma unroll
            for (int ky = 0; ky < 3; ky++) {
                const float* rp = hp + ky*12;
                float4 ra = *(const float4*)(rp);
                float4 rb4 = *(const float4*)(rp + 4);
                float2 rc = *(const float2*)(rp + 8);
                float rw[10] = {ra.x, ra.y, ra.z, ra.w, rb4.x, rb4.y, rb4.z, rb4.w, rc.x, rc.y};
                float d0 = dwp[ky*3], d1 = dwp[ky*3+1], d2 = dwp[ky*3+2];
#pragma unroll
                for (int xp = 0; xp < 8; xp++)
                    o8[xp] = fmaf(d0, rw[xp], fmaf(d1, rw[xp+1], fmaf(d2, rw[xp+2], o8[xp])));
            }
            float4 gA, gB;
            gA.x = gelu_f(o8[0]); gA.y = gelu_f(o8[1]); gA.z = gelu_f(o8[2]); gA.w = gelu_f(o8[3]);
            gB.x = gelu_f(o8[4]); gB.y = gelu_f(o8[5]); gB.z = gelu_f(o8[6]); gB.w = gelu_f(o8[7]);
            *(float4*)(gs + chl*64 + row*8)     = gA;
            *(float4*)(gs + chl*64 + row*8 + 4) = gB;
        }
        __syncthreads();
        gemm44<64,68>(gs, Ws, tg, og, acc0);
        __syncthreads();
        // weight half 1 (ol 64..127)
        for (int idx = tid; idx < 4096; idx += 256) {
            int chl = idx & 63, ol = idx >> 6;
            Ws[chl*68 + ol] = w2[(size_t)(64+ol)*512 + c0 + chl];
        }
        __syncthreads();
        gemm44<64,68>(gs, Ws, tg, og, acc1);
        __syncthreads();
    }

    const float* r1 = g_res1 + (size_t)b*128*HWSZ;
    float* ob = out + (size_t)b*128*HWSZ;
    const int t0 = tg*4;
    const size_t pix = (size_t)(y0 + (t0>>3))*NWD + xw + (t0&7);
#pragma unroll
    for (int half = 0; half < 2; half++) {
        u64 (*ac)[2] = half ? acc1 : acc0;
#pragma unroll
        for (int jp = 0; jp < 2; jp++)
#pragma unroll
            for (int h = 0; h < 2; h++) {
                int o = half*64 + og*4 + jp*2 + h;
                float bb = b2[o];
                float4 s4 = *(const float4*)(r1 + (size_t)o*HWSZ + pix);
                float4 col;
                col.x = (h ? hi2(ac[0][jp]) : lo2(ac[0][jp])) + bb + s4.x;
                col.y = (h ? hi2(ac[1][jp]) : lo2(ac[1][jp])) + bb + s4.y;
                col.z = (h ? hi2(ac[2][jp]) : lo2(ac[2][jp])) + bb + s4.z;
                col.w = (h ? hi2(ac[3][jp]) : lo2(ac[3][jp])) + bb + s4.w;
                *(float4*)(ob + (size_t)o*HWSZ + pix) = col;
            }
    }
}

// =================================================================================================
extern "C" void kernel_launch(void* const* d_in, const int* in_sizes, int n_in,
                              void* d_out, int out_size)
{
    const float* x    = (const float*)d_in[0];
    const float* l0   = (const float*)d_in[1];
    const float* n1w  = (const float*)d_in[2];
    const float* n1b  = (const float*)d_in[3];
    const float* n2w  = (const float*)d_in[4];
    const float* n2b  = (const float*)d_in[5];
    const float* qkvw = (const float*)d_in[6];
    const float* gw   = (const float*)d_in[7];
    const float* gb   = (const float*)d_in[8];
    const float* pw   = (const float*)d_in[9];
    const float* pb   = (const float*)d_in[10];
    const float* w1   = (const float*)d_in[11];
    const float* b1   = (const float*)d_in[12];
    const float* dwv  = (const float*)d_in[13];
    const float* dwb  = (const float*)d_in[14];
    const float* w2   = (const float*)d_in[15];
    const float* b2   = (const float*)d_in[16];
    float* out = (float*)d_out;

    const int smem1 = (8192 + 3*8448 + 2*K1_WB + 64 + 1024) * (int)sizeof(float);  // 189184
    const int smem2 = (8192 + 2*K2_WB + 1024) * (int)sizeof(float);                // 103936
    const int smem3 = (8192 + 4096 + 4352) * (int)sizeof(float);                   //  66560

    cudaFuncSetAttribute(k1_attn, cudaFuncAttributeMaxDynamicSharedMemorySize, smem1);
    cudaFuncSetAttribute(k2_ffn1, cudaFuncAttributeMaxDynamicSharedMemorySize, smem2);
    cudaFuncSetAttribute(k3_ffn2, cudaFuncAttributeMaxDynamicSharedMemorySize, smem3);

    k1_attn<<<4096, 512, smem1>>>(x, l0, n1w, n1b, qkvw, gw, gb, pw, pb);
    k2_ffn1<<<4096, 512, smem2>>>(n2w, n2b, w1, b1);
    k3_ffn2<<<4096, 256, smem3>>>(dwv, dwb, w2, b2, out);
}

// round 11
// speedup vs baseline: 2.6488x; 1.0943x over previous
#include <cuda_runtime.h>
#include <cuda_bf16.h>
#include <stdint.h>
#include <math.h>

#define HWSZ 65536
#define NWD  256
typedef unsigned long long u64;

__device__ float g_res1[4ull*128*HWSZ];
__device__ float g_h1  [4ull*512*HWSZ];

__device__ __forceinline__ u64 pk2(float lo, float hi){ u64 r; asm("mov.b64 %0,{%1,%2};":"=l"(r):"f"(lo),"f"(hi)); return r; }
__device__ __forceinline__ u64 dup2(float v){ return pk2(v, v); }
__device__ __forceinline__ void fma2(u64& d, u64 a, u64 b){ asm("fma.rn.f32x2 %0,%1,%2,%0;":"+l"(d):"l"(a),"l"(b)); }
__device__ __forceinline__ u64 mul2(u64 a, u64 b){ u64 d; asm("mul.rn.f32x2 %0,%1,%2;":"=l"(d):"l"(a),"l"(b)); return d; }
__device__ __forceinline__ float lo2(u64 v){ return __uint_as_float((unsigned)v); }
__device__ __forceinline__ float hi2(u64 v){ return __uint_as_float((unsigned)(v>>32)); }
__device__ __forceinline__ float gelu_f(float v){ return 0.5f*v*(1.0f + erff(v*0.7071067811865475f)); }
__device__ __forceinline__ float sigm(float z){ return 1.f/(1.f + __expf(-z)); }

__device__ __forceinline__ uint32_t smem_u32(const void* p){
    uint32_t a;
    asm("{ .reg .u64 t; cvta.to.shared.u64 t, %1; cvt.u32.u64 %0, t; }" : "=r"(a) : "l"(p));
    return a;
}
__device__ __forceinline__ void ldsm4(uint32_t& r0, uint32_t& r1, uint32_t& r2, uint32_t& r3, uint32_t addr){
    asm volatile("ldmatrix.sync.aligned.m8n8.x4.shared.b16 {%0,%1,%2,%3}, [%4];"
                 : "=r"(r0), "=r"(r1), "=r"(r2), "=r"(r3) : "r"(addr));
}
__device__ __forceinline__ void mma_bf16(float* d, uint32_t a0, uint32_t a1, uint32_t a2, uint32_t a3,
                                         uint32_t b0, uint32_t b1){
    asm volatile("mma.sync.aligned.m16n8k16.row.col.f32.bf16.bf16.f32 "
                 "{%0,%1,%2,%3}, {%4,%5,%6,%7}, {%8,%9}, {%0,%1,%2,%3};"
                 : "+f"(d[0]), "+f"(d[1]), "+f"(d[2]), "+f"(d[3])
                 : "r"(a0), "r"(a1), "r"(a2), "r"(a3), "r"(b0), "r"(b1));
}
__device__ __forceinline__ unsigned short bfh(float v){ return __bfloat16_as_ushort(__float2bfloat16_rn(v)); }
__device__ __forceinline__ float bf2f(unsigned short u){ return __bfloat162float(__ushort_as_bfloat16(u)); }

// 4t x 4ol packed GEMM core (scalar kernels)
template<int KC, int WSTR>
__device__ __forceinline__ void gemm44(const float* __restrict__ xs,
                                       const float* __restrict__ Ws,
                                       int tg, int og, u64 acc[4][2])
{
    const float* xp = xs + tg*4;
    const float* wp = Ws + og*4;
#pragma unroll 8
    for (int c = 0; c < KC; c++) {
        float4 xv = *(const float4*)(xp + c*64);
        ulonglong2 w = *(const ulonglong2*)(wp + c*WSTR);
        u64 x0 = dup2(xv.x), x1 = dup2(xv.y), x2 = dup2(xv.z), x3 = dup2(xv.w);
        fma2(acc[0][0], x0, w.x); fma2(acc[0][1], x0, w.y);
        fma2(acc[1][0], x1, w.x); fma2(acc[1][1], x1, w.y);
        fma2(acc[2][0], x2, w.x); fma2(acc[2][1], x2, w.y);
        fma2(acc[3][0], x3, w.x); fma2(acc[3][1], x3, w.y);
    }
}

// ================= Kernel 1 (unchanged, passing) ================================================
#define K1_WB 6336
__global__ void __launch_bounds__(512,1) k1_attn(
    const float* __restrict__ x, const float* __restrict__ l0,
    const float* __restrict__ n1w, const float* __restrict__ n1b,
    const float* __restrict__ qkvw,
    const float* __restrict__ gw, const float* __restrict__ gbv,
    const float* __restrict__ pw, const float* __restrict__ pbv)
{
    extern __shared__ float sm[];
    float* xs  = sm;
    float* qt  = xs + 8192;
    float* kt  = qt + 8448;
    float* vt  = kt + 8448;
    float* Wb  = vt + 8448;
    float* l0s = Wb + 2*K1_WB;
    float* red = l0s + 64;

    const int tid = threadIdx.x;
    const int blk = blockIdx.x;
    const int b   = blk >> 10, wr = blk & 1023;
    const int y0  = (wr >> 5) << 3, xw = (wr & 31) << 3;
    const float* xb = x + (size_t)b*128*HWSZ;
    const int tg4  = tid & 15;
    const int og12 = tid >> 4;

    for (int idx = tid; idx < 8192; idx += 512) {
        int c = idx >> 6, t = idx & 63;
        xs[c*64 + t] = xb[(size_t)c*HWSZ + (y0 + (t>>3))*NWD + xw + (t&7)];
    }
    if (tid < 64) l0s[tid] = l0[(size_t)b*HWSZ + (y0 + (tid>>3))*NWD + xw + (tid&7)];
    __syncthreads();

    {
        int t = tid & 63, q8 = tid >> 6;
        float s = 0.f, ss = 0.f;
#pragma unroll
        for (int cc = 0; cc < 16; cc++) {
            float v = xs[(q8*16+cc)*64 + t];
            s += v; ss += v*v;
        }
        red[q8*64+t] = s; red[512 + q8*64+t] = ss;
        __syncthreads();
        s = 0.f; ss = 0.f;
#pragma unroll
        for (int k = 0; k < 8; k++) { s += red[k*64+t]; ss += red[512 + k*64+t]; }
        float mu   = s*(1.f/128.f);
        float rstd = rsqrtf(ss*(1.f/128.f) - mu*mu + 1e-6f);
#pragma unroll
        for (int cc = 0; cc < 16; cc++) {
            int c = q8*16+cc;
            xs[c*64+t] = (xs[c*64+t]-mu)*rstd*n1w[c] + n1b[c];
        }
    }

    u64 acc[4][6];
#pragma unroll
    for (int r = 0; r < 4; r++)
#pragma unroll
        for (int p = 0; p < 6; p++) acc[r][p] = 0ull;

#pragma unroll
    for (int i = 0; i < 12; i++) {
        int idx = tid + i*512;
        int cc = idx & 15, o = idx >> 4;
        Wb[cc*396 + o] = qkvw[(size_t)o*128 + cc];
    }
    __syncthreads();

    for (int ck = 0; ck < 8; ck++) {
        const float* Wcur = Wb + (ck & 1)*K1_WB;
        float pf[12];
        if (ck < 7) {
            int c0n = (ck+1)*16;
#pragma unroll
            for (int i = 0; i < 12; i++) {
                int idx = tid + i*512;
                int cc = idx & 15, o = idx >> 4;
                pf[i] = qkvw[(size_t)o*128 + c0n + cc];
            }
        }
        const int c0 = ck*16;
        const float* wrow0 = Wcur + og12*12;
#pragma unroll 4
        for (int cc = 0; cc < 16; cc++) {
            float4 xv = *(const float4*)(xs + (c0+cc)*64 + tg4*4);
            const float* wrow = wrow0 + cc*396;
            ulonglong2 wA = *(const ulonglong2*)(wrow);
            ulonglong2 wB = *(const ulonglong2*)(wrow + 4);
            ulonglong2 wC = *(const ulonglong2*)(wrow + 8);
            u64 x0 = dup2(xv.x), x1 = dup2(xv.y), x2 = dup2(xv.z), x3 = dup2(xv.w);
            fma2(acc[0][0], x0, wA.x); fma2(acc[0][1], x0, wA.y); fma2(acc[0][2], x0, wB.x);
            fma2(acc[0][3], x0, wB.y); fma2(acc[0][4], x0, wC.x); fma2(acc[0][5], x0, wC.y);
            fma2(acc[1][0], x1, wA.x); fma2(acc[1][1], x1, wA.y); fma2(acc[1][2], x1, wB.x);
            fma2(acc[1][3], x1, wB.y); fma2(acc[1][4], x1, wC.x); fma2(acc[1][5], x1, wC.y);
            fma2(acc[2][0], x2, wA.x); fma2(acc[2][1], x2, wA.y); fma2(acc[2][2], x2, wB.x);
            fma2(acc[2][3], x2, wB.y); fma2(acc[2][4], x2, wC.x); fma2(acc[2][5], x2, wC.y);
            fma2(acc[3][0], x3, wA.x); fma2(acc[3][1], x3, wA.y); fma2(acc[3][2], x3, wB.x);
            fma2(acc[3][3], x3, wB.y); fma2(acc[3][4], x3, wC.x); fma2(acc[3][5], x3, wC.y);
        }
        if (ck < 7) {
            float* Wnext = Wb + ((ck+1) & 1)*K1_WB;
#pragma unroll
            for (int i = 0; i < 12; i++) {
                int idx = tid + i*512;
                int cc = idx & 15, o = idx >> 4;
                Wnext[cc*396 + o] = pf[i];
            }
        }
        __syncthreads();
    }

#pragma unroll
    for (int r = 0; r < 4; r++) {
        int t = tg4*4 + r;
        float lv = l0s[t];
#pragma unroll
        for (int p = 0; p < 6; p++) {
            int ol = og12*12 + p*2;
            float lo = lo2(acc[r][p]), hi = hi2(acc[r][p]);
            int seg = ol >> 7, loc = ol & 127;
            float* dst = (seg == 0) ? qt : (seg == 1) ? kt : vt;
            if (seg == 0) {
                lo *= sigm(lv*gw[ol]   + gbv[ol]);
                hi *= sigm(lv*gw[ol+1] + gbv[ol+1]);
            }
            *(u64*)(dst + t*132 + loc) = pk2(lo, hi);
        }
    }
    __syncthreads();

    if (tid < 256) {
        const int ip = tid & 31, hd = tid >> 5;
        const int qo = hd*16;
        const ulonglong2* qpA = (const ulonglong2*)(qt + ip*132 + qo);
        const ulonglong2* qpB = (const ulonglong2*)(qt + (ip+32)*132 + qo);
        ulonglong2 qa0 = qpA[0], qa1 = qpA[1], qa2 = qpA[2], qa3 = qpA[3];
        ulonglong2 qb0 = qpB[0], qb1 = qpB[1], qb2 = qpB[2], qb3 = qpB[3];

        float mA = -1e30f, lA = 0.f, mB = -1e30f, lB = 0.f;
        u64 oA[8], oB[8];
#pragma unroll
        for (int d2 = 0; d2 < 8; d2++) { oA[d2] = 0ull; oB[d2] = 0ull; }

        for (int jc = 0; jc < 8; jc++) {
            float eA[8], eB[8];
            float cmA = -1e30f, cmB = -1e30f;
#pragma unroll
            for (int jj = 0; jj < 8; jj++) {
                int j = jc*8 + jj;
                const ulonglong2* kp = (const ulonglong2*)(kt + j*132 + qo);
                ulonglong2 k0 = kp[0], k1 = kp[1], k2 = kp[2], k3 = kp[3];
                u64 a = 0ull;
                fma2(a, qa0.x, k0.x); fma2(a, qa0.y, k0.y);
                fma2(a, qa1.x, k1.x); fma2(a, qa1.y, k1.y);
                fma2(a, qa2.x, k2.x); fma2(a, qa2.y, k2.y);
                fma2(a, qa3.x, k3.x); fma2(a, qa3.y, k3.y);
                float sA = (lo2(a) + hi2(a))*0.25f;
                u64 bq = 0ull;
                fma2(bq, qb0.x, k0.x); fma2(bq, qb0.y, k0.y);
                fma2(bq, qb1.x, k1.x); fma2(bq, qb1.y, k1.y);
                fma2(bq, qb2.x, k2.x); fma2(bq, qb2.y, k2.y);
                fma2(bq, qb3.x, k3.x); fma2(bq, qb3.y, k3.y);
                float sB = (lo2(bq) + hi2(bq))*0.25f;
                eA[jj] = sA; cmA = fmaxf(cmA, sA);
                eB[jj] = sB; cmB = fmaxf(cmB, sB);
            }
            float mnA = fmaxf(mA, cmA), mnB = fmaxf(mB, cmB);
            float scA = __expf(mA - mnA), scB = __expf(mB - mnB);
            mA = mnA; mB = mnB;
            float sumA = 0.f, sumB = 0.f;
#pragma unroll
            for (int jj = 0; jj < 8; jj++) {
                eA[jj] = __expf(eA[jj] - mA); sumA += eA[jj];
                eB[jj] = __expf(eB[jj] - mB); sumB += eB[jj];
            }
            lA = lA*scA + sumA; lB = lB*scB + sumB;
            u64 s2A = dup2(scA), s2B = dup2(scB);
#pragma unroll
            for (int d2 = 0; d2 < 8; d2++) {
                oA[d2] = mul2(oA[d2], s2A);
                oB[d2] = mul2(oB[d2], s2B);
            }
#pragma unroll
            for (int jj = 0; jj < 8; jj++) {
                int j = jc*8 + jj;
                const ulonglong2* vp = (const ulonglong2*)(vt + j*132 + qo);
                ulonglong2 v0 = vp[0], v1 = vp[1], v2 = vp[2], v3 = vp[3];
                u64 pA = dup2(eA[jj]), pB = dup2(eB[jj]);
                fma2(oA[0], pA, v0.x); fma2(oA[1], pA, v0.y);
                fma2(oA[2], pA, v1.x); fma2(oA[3], pA, v1.y);
                fma2(oA[4], pA, v2.x); fma2(oA[5], pA, v2.y);
                fma2(oA[6], pA, v3.x); fma2(oA[7], pA, v3.y);
                fma2(oB[0], pB, v0.x); fma2(oB[1], pB, v0.y);
                fma2(oB[2], pB, v1.x); fma2(oB[3], pB, v1.y);
                fma2(oB[4], pB, v2.x); fma2(oB[5], pB, v2.y);
                fma2(oB[6], pB, v3.x); fma2(oB[7], pB, v3.y);
            }
        }
        float invA = 1.f/lA, invB = 1.f/lB;
#pragma unroll
        for (int d2 = 0; d2 < 8; d2++) {
            xs[(qo + d2*2  )*64 + ip]      = lo2(oA[d2])*invA;
            xs[(qo + d2*2+1)*64 + ip]      = hi2(oA[d2])*invA;
            xs[(qo + d2*2  )*64 + ip + 32] = lo2(oB[d2])*invB;
            xs[(qo + d2*2+1)*64 + ip + 32] = hi2(oB[d2])*invB;
        }
    }
    __syncthreads();

    float* Wsp = kt;
    for (int idx = tid; idx < 16384; idx += 512) {
        int c = idx & 127, ol = idx >> 7;
        Wsp[c*132 + ol] = pw[(size_t)ol*128 + c];
    }
    __syncthreads();
    {
        const int og = tid >> 4;
        u64 pacc[4][2];
#pragma unroll
        for (int r = 0; r < 4; r++) { pacc[r][0] = 0ull; pacc[r][1] = 0ull; }
        gemm44<128,132>(xs, Wsp, tg4, og, pacc);

        float* r1 = g_res1 + (size_t)b*128*HWSZ;
        const int t0 = tg4*4;
        const size_t pix = (size_t)(y0 + (t0>>3))*NWD + xw + (t0&7);
#pragma unroll
        for (int jp = 0; jp < 2; jp++)
#pragma unroll
            for (int h = 0; h < 2; h++) {
                int o = og*4 + jp*2 + h;
                float pb = pbv[o];
                float4 s4 = *(const float4*)(xb + (size_t)o*HWSZ + pix);
                float4 col;
                col.x = (h ? hi2(pacc[0][jp]) : lo2(pacc[0][jp])) + pb + s4.x;
                col.y = (h ? hi2(pacc[1][jp]) : lo2(pacc[1][jp])) + pb + s4.y;
                col.z = (h ? hi2(pacc[2][jp]) : lo2(pacc[2][jp])) + pb + s4.z;
                col.w = (h ? hi2(pacc[3][jp]) : lo2(pacc[3][jp])) + pb + s4.w;
                *(float4*)(r1 + (size_t)o*HWSZ + pix) = col;
            }
    }
}

// ================= Kernel 2: mma.sync bf16 3-pass (LN2 + FFN1 + bias + GELU) ====================
// CTA = 128 pixels. M=128 tok, K=128, N=512 in 4 chunks of 128.
// A/B bf16 hi/lo tiles, row pitch 272 B (136 bf16). Bh/Bl overlay the dead fp32 x buffer.
#define K2B_BH   0
#define K2B_BL   34816
#define K2B_AH   69632
#define K2B_AL   104448
#define K2B_B1   139264
#define K2B_N2W  141312
#define K2B_N2B  141824
#define K2B_RED  142336
#define K2B_SMEM 144384

__global__ void __launch_bounds__(256,1) k2_ffn1(
    const float* __restrict__ n2w, const float* __restrict__ n2b,
    const float* __restrict__ w1, const float* __restrict__ b1)
{
    extern __shared__ char smc[];
    float* xs   = (float*)(smc);             // fp32 x [128c][128t], overlaid later by Bh/Bl
    float* b1s  = (float*)(smc + K2B_B1);
    float* n2ws = (float*)(smc + K2B_N2W);
    float* n2bs = (float*)(smc + K2B_N2B);
    float* red  = (float*)(smc + K2B_RED);

    const int tid  = threadIdx.x;
    const int wid  = tid >> 5, lane = tid & 31;
    const int blk  = blockIdx.x;
    const int b    = blk >> 9, rr = blk & 511;
    const int y    = rr >> 1, x0 = (rr & 1)*128;
    const float* rb = g_res1 + (size_t)b*128*HWSZ + (size_t)y*NWD + x0;

    if (tid < 128) { n2ws[tid] = n2w[tid]; n2bs[tid] = n2b[tid]; }
    b1s[tid] = b1[tid]; b1s[tid+256] = b1[tid+256];

#pragma unroll
    for (int i = 0; i < 16; i++) {
        int idx = tid + i*256;
        int c = idx >> 5, f4 = idx & 31;
        *(float4*)(xs + c*128 + f4*4) = *(const float4*)(rb + (size_t)c*HWSZ + f4*4);
    }
    __syncthreads();

    // LN2 + A hi/lo bf16 conversion into [m][k] pitch-272B tiles
    {
        const int t = tid & 127, h = tid >> 7;
        float s = 0.f, ss = 0.f;
#pragma unroll
        for (int cc = 0; cc < 64; cc++) {
            float v = xs[(h*64+cc)*128 + t];
            s += v; ss += v*v;
        }
        red[h*128+t] = s; red[256 + h*128+t] = ss;
        __syncthreads();
        s  = red[t] + red[128+t];
        ss = red[256+t] + red[384+t];
        float mu   = s*(1.f/128.f);
        float rstd = rsqrtf(ss*(1.f/128.f) - mu*mu + 1e-6f);

        char* Ah = smc + K2B_AH + t*272;
        char* Al = smc + K2B_AL + t*272;
#pragma unroll 8
        for (int cc = 0; cc < 64; cc += 2) {
            int c = h*64 + cc;
            float v0 = (xs[c*128+t]     - mu)*rstd*n2ws[c]   + n2bs[c];
            float v1 = (xs[(c+1)*128+t] - mu)*rstd*n2ws[c+1] + n2bs[c+1];
            unsigned short h0 = bfh(v0), h1 = bfh(v1);
            unsigned short l0v = bfh(v0 - bf2f(h0)), l1v = bfh(v1 - bf2f(h1));
            *(uint32_t*)(Ah + c*2) = (uint32_t)h0  | ((uint32_t)h1  << 16);
            *(uint32_t*)(Al + c*2) = (uint32_t)l0v | ((uint32_t)l1v << 16);
        }
    }
    __syncthreads();

    const uint32_t AhB = smem_u32(smc + K2B_AH), AlB = smem_u32(smc + K2B_AL);
    const uint32_t BhB = smem_u32(smc + K2B_BH), BlB = smem_u32(smc + K2B_BL);
    const int tileM = wid*16;
    // ldmatrix lane address offsets
    const uint32_t aoff = (uint32_t)((tileM + (lane & 15))*272 + (((lane >> 4) << 3))*2);
    const uint32_t boff = (uint32_t)((((lane >> 4) << 3) + (lane & 7))*272 + (((lane >> 3) & 1) << 3)*2);

    float* hb = g_h1 + (size_t)b*512*HWSZ + (size_t)y*NWD + x0;
    const int g = lane >> 2, n0l = (lane & 3)*2;

    for (int ck = 0; ck < 4; ck++) {
        // stage B chunk (n = ck*128 .. +127) hi/lo
        {
            int n_l = tid >> 1, kh = (tid & 1)*64;
            const float* wr = w1 + (size_t)(ck*128 + n_l)*128 + kh;
            char* BhP = smc + K2B_BH + n_l*272 + kh*2;
            char* BlP = smc + K2B_BL + n_l*272 + kh*2;
#pragma unroll 4
            for (int cc = 0; cc < 64; cc += 4) {
                float4 wv = *(const float4*)(wr + cc);
                unsigned short h0 = bfh(wv.x), h1 = bfh(wv.y), h2 = bfh(wv.z), h3 = bfh(wv.w);
                unsigned short l0v = bfh(wv.x - bf2f(h0)), l1v = bfh(wv.y - bf2f(h1));
                unsigned short l2v = bfh(wv.z - bf2f(h2)), l3v = bfh(wv.w - bf2f(h3));
                *(uint32_t*)(BhP + cc*2)     = (uint32_t)h0  | ((uint32_t)h1  << 16);
                *(uint32_t*)(BhP + cc*2 + 4) = (uint32_t)h2  | ((uint32_t)h3  << 16);
                *(uint32_t*)(BlP + cc*2)     = (uint32_t)l0v | ((uint32_t)l1v << 16);
                *(uint32_t*)(BlP + cc*2 + 4) = (uint32_t)l2v | ((uint32_t)l3v << 16);
            }
        }
        __syncthreads();

        float acc[16][4];
#pragma unroll
        for (int nb = 0; nb < 16; nb++)
#pragma unroll
            for (int q = 0; q < 4; q++) acc[nb][q] = 0.f;

#pragma unroll
        for (int pass = 0; pass < 3; pass++) {
            const uint32_t Ab = (pass == 1) ? AlB : AhB;
            const uint32_t Bb = (pass == 2) ? BlB : BhB;
#pragma unroll
            for (int k16 = 0; k16 < 8; k16++) {
                uint32_t a0, a1, a2, a3;
                ldsm4(a0, a1, a2, a3, Ab + aoff + k16*32);
#pragma unroll
                for (int nbp = 0; nbp < 8; nbp++) {
                    uint32_t b0, b1r, b2, b3;
                    ldsm4(b0, b1r, b2, b3, Bb + boff + (uint32_t)(nbp*16*272) + k16*32);
                    mma_bf16(acc[nbp*2],     a0, a1, a2, a3, b0, b1r);
                    mma_bf16(acc[nbp*2 + 1], a0, a1, a2, a3, b2, b3);
                }
            }
        }

        // epilogue: bias + GELU + store
#pragma unroll
        for (int nb = 0; nb < 16; nb++) {
            int n = ck*128 + nb*8 + n0l;
            float bb0 = b1s[n], bb1 = b1s[n+1];
            int m0 = tileM + g;
            hb[(size_t)n*HWSZ + m0]         = gelu_f(acc[nb][0] + bb0);
            hb[(size_t)(n+1)*HWSZ + m0]     = gelu_f(acc[nb][1] + bb1);
            hb[(size_t)n*HWSZ + m0 + 8]     = gelu_f(acc[nb][2] + bb0);
            hb[(size_t)(n+1)*HWSZ + m0 + 8] = gelu_f(acc[nb][3] + bb1);
        }
        __syncthreads();
    }
}

// ================= Kernel 3 (unchanged, passing) ================================================
__global__ void __launch_bounds__(256,3) k3_ffn2(
    const float* __restrict__ dw, const float* __restrict__ dwb,
    const float* __restrict__ w2, const float* __restrict__ b2,
    float* __restrict__ out)
{
    extern __shared__ float sm[];
    float* hs = sm;
    float* gs = hs + 8192;
    float* Ws = gs + 4096;

    const int tid = threadIdx.x;
    const int blk = blockIdx.x;
    const int b   = blk >> 10, rr = blk & 1023;
    const int y0  = (rr >> 5) << 3, xw = (rr & 31) << 3;
    const float* hbase = g_h1 + (size_t)b*512*HWSZ;
    const int tg = tid & 15, og = tid >> 4;

    u64 acc0[4][2], acc1[4][2];
#pragma unroll
    for (int r = 0; r < 4; r++) {
        acc0[r][0] = 0ull; acc0[r][1] = 0ull;
        acc1[r][0] = 0ull; acc1[r][1] = 0ull;
    }

    for (int ck = 0; ck < 8; ck++) {
        const int c0 = ck*64;
        for (int idx = tid; idx < 6400; idx += 256) {
            int ch = idx / 100;
            int p  = idx - ch*100;
            int pr = p / 10;
            int pc = p - pr*10;
            int py = y0 - 1 + pr;
            int px = xw - 1 + pc;
            float v = 0.f;
            if ((unsigned)py < 256u && (unsigned)px < 256u)
                v = hbase[(size_t)(c0+ch)*HWSZ + py*NWD + px];
            hs[ch*128 + pr*12 + pc] = v;
        }
        for (int idx = tid; idx < 4096; idx += 256) {
            int chl = idx & 63, ol = idx >> 6;
            Ws[chl*68 + ol] = w2[(size_t)ol*512 + c0 + chl];
        }
        __syncthreads();
#pragma unroll
        for (int k = 0; k < 2; k++) {
            int u   = tid + k*256;
            int chl = u >> 3, row = u & 7;
            const float* dwp = dw + (size_t)(c0+chl)*9;
            const float* hp  = hs + chl*128 + row*12;
            float o8[8];
            float bbv = dwb[c0+chl];
#pragma unroll
            for (int xp = 0; xp < 8; xp++) o8[xp] = bbv;
#pragma unroll
            for (int ky = 0; ky < 3; ky++) {
                const float* rp = hp + ky*12;
                float4 ra = *(const float4*)(rp);
                float4 rb4 = *(const float4*)(rp + 4);
                float2 rc = *(const float2*)(rp + 8);
                float rw[10] = {ra.x, ra.y, ra.z, ra.w, rb4.x, rb4.y, rb4.z, rb4.w, rc.x, rc.y};
                float d0 = dwp[ky*3], d1 = dwp[ky*3+1], d2 = dwp[ky*3+2];
#pragma unroll
                for (int xp = 0; xp < 8; xp++)
                    o8[xp] = fmaf(d0, rw[xp], fmaf(d1, rw[xp+1], fmaf(d2, rw[xp+2], o8[xp])));
            }
            float4 gA, gB;
            gA.x = gelu_f(o8[0]); gA.y = gelu_f(o8[1]); gA.z = gelu_f(o8[2]); gA.w = gelu_f(o8[3]);
            gB.x = gelu_f(o8[4]); gB.y = gelu_f(o8[5]); gB.z = gelu_f(o8[6]); gB.w = gelu_f(o8[7]);
            *(float4*)(gs + chl*64 + row*8)     = gA;
            *(float4*)(gs + chl*64 + row*8 + 4) = gB;
        }
        __syncthreads();
        gemm44<64,68>(gs, Ws, tg, og, acc0);
        __syncthreads();
        for (int idx = tid; idx < 4096; idx += 256) {
            int chl = idx & 63, ol = idx >> 6;
            Ws[chl*68 + ol] = w2[(size_t)(64+ol)*512 + c0 + chl];
        }
        __syncthreads();
        gemm44<64,68>(gs, Ws, tg, og, acc1);
        __syncthreads();
    }

    const float* r1 = g_res1 + (size_t)b*128*HWSZ;
    float* ob = out + (size_t)b*128*HWSZ;
    const int t0 = tg*4;
    const size_t pix = (size_t)(y0 + (t0>>3))*NWD + xw + (t0&7);
#pragma unroll
    for (int half = 0; half < 2; half++) {
        u64 (*ac)[2] = half ? acc1 : acc0;
#pragma unroll
        for (int jp = 0; jp < 2; jp++)
#pragma unroll
            for (int h = 0; h < 2; h++) {
                int o = half*64 + og*4 + jp*2 + h;
                float bb = b2[o];
                float4 s4 = *(const float4*)(r1 + (size_t)o*HWSZ + pix);
                float4 col;
                col.x = (h ? hi2(ac[0][jp]) : lo2(ac[0][jp])) + bb + s4.x;
                col.y = (h ? hi2(ac[1][jp]) : lo2(ac[1][jp])) + bb + s4.y;
                col.z = (h ? hi2(ac[2][jp]) : lo2(ac[2][jp])) + bb + s4.z;
                col.w = (h ? hi2(ac[3][jp]) : lo2(ac[3][jp])) + bb + s4.w;
                *(float4*)(ob + (size_t)o*HWSZ + pix) = col;
            }
    }
}

// =================================================================================================
extern "C" void kernel_launch(void* const* d_in, const int* in_sizes, int n_in,
                              void* d_out, int out_size)
{
    const float* x    = (const float*)d_in[0];
    const float* l0   = (const float*)d_in[1];
    const float* n1w  = (const float*)d_in[2];
    const float* n1b  = (const float*)d_in[3];
    const float* n2w  = (const float*)d_in[4];
    const float* n2b  = (const float*)d_in[5];
    const float* qkvw = (const float*)d_in[6];
    const float* gw   = (const float*)d_in[7];
    const float* gb   = (const float*)d_in[8];
    const float* pw   = (const float*)d_in[9];
    const float* pb   = (const float*)d_in[10];
    const float* w1   = (const float*)d_in[11];
    const float* b1   = (const float*)d_in[12];
    const float* dwv  = (const float*)d_in[13];
    const float* dwb  = (const float*)d_in[14];
    const float* w2   = (const float*)d_in[15];
    const float* b2   = (const float*)d_in[16];
    float* out = (float*)d_out;

    const int smem1 = (8192 + 3*8448 + 2*K1_WB + 64 + 1024) * (int)sizeof(float);  // 189184
    const int smem3 = (8192 + 4096 + 4352) * (int)sizeof(float);                   //  66560

    cudaFuncSetAttribute(k1_attn, cudaFuncAttributeMaxDynamicSharedMemorySize, smem1);
    cudaFuncSetAttribute(k2_ffn1, cudaFuncAttributeMaxDynamicSharedMemorySize, K2B_SMEM);
    cudaFuncSetAttribute(k3_ffn2, cudaFuncAttributeMaxDynamicSharedMemorySize, smem3);

    k1_attn<<<4096, 512, smem1>>>(x, l0, n1w, n1b, qkvw, gw, gb, pw, pb);
    k2_ffn1<<<2048, 256, K2B_SMEM>>>(n2w, n2b, w1, b1);
    k3_ffn2<<<4096, 256, smem3>>>(dwv, dwb, w2, b2, out);
}

// round 13
// speedup vs baseline: 2.6706x; 1.0082x over previous
#include <cuda_runtime.h>
#include <cuda_bf16.h>
#include <stdint.h>
#include <math.h>

#define HWSZ 65536
#define NWD  256
typedef unsigned long long u64;

__device__ float g_res1[4ull*128*HWSZ];
__device__ float g_h1  [4ull*512*HWSZ];

__device__ __forceinline__ u64 pk2(float lo, float hi){ u64 r; asm("mov.b64 %0,{%1,%2};":"=l"(r):"f"(lo),"f"(hi)); return r; }
__device__ __forceinline__ u64 dup2(float v){ return pk2(v, v); }
__device__ __forceinline__ void fma2(u64& d, u64 a, u64 b){ asm("fma.rn.f32x2 %0,%1,%2,%0;":"+l"(d):"l"(a),"l"(b)); }
__device__ __forceinline__ u64 mul2(u64 a, u64 b){ u64 d; asm("mul.rn.f32x2 %0,%1,%2;":"=l"(d):"l"(a),"l"(b)); return d; }
__device__ __forceinline__ float lo2(u64 v){ return __uint_as_float((unsigned)v); }
__device__ __forceinline__ float hi2(u64 v){ return __uint_as_float((unsigned)(v>>32)); }
__device__ __forceinline__ float gelu_f(float v){ return 0.5f*v*(1.0f + erff(v*0.7071067811865475f)); }
__device__ __forceinline__ float sigm(float z){ return 1.f/(1.f + __expf(-z)); }

__device__ __forceinline__ uint32_t smem_u32(const void* p){
    uint32_t a;
    asm("{ .reg .u64 t; cvta.to.shared.u64 t, %1; cvt.u32.u64 %0, t; }" : "=r"(a) : "l"(p));
    return a;
}
__device__ __forceinline__ void ldsm4(uint32_t& r0, uint32_t& r1, uint32_t& r2, uint32_t& r3, uint32_t addr){
    asm volatile("ldmatrix.sync.aligned.m8n8.x4.shared.b16 {%0,%1,%2,%3}, [%4];"
                 : "=r"(r0), "=r"(r1), "=r"(r2), "=r"(r3) : "r"(addr));
}
__device__ __forceinline__ void ldsm4t(uint32_t& r0, uint32_t& r1, uint32_t& r2, uint32_t& r3, uint32_t addr){
    asm volatile("ldmatrix.sync.aligned.m8n8.x4.trans.shared.b16 {%0,%1,%2,%3}, [%4];"
                 : "=r"(r0), "=r"(r1), "=r"(r2), "=r"(r3) : "r"(addr));
}
__device__ __forceinline__ void mma_bf16(float* d, uint32_t a0, uint32_t a1, uint32_t a2, uint32_t a3,
                                         uint32_t b0, uint32_t b1){
    asm volatile("mma.sync.aligned.m16n8k16.row.col.f32.bf16.bf16.f32 "
                 "{%0,%1,%2,%3}, {%4,%5,%6,%7}, {%8,%9}, {%0,%1,%2,%3};"
                 : "+f"(d[0]), "+f"(d[1]), "+f"(d[2]), "+f"(d[3])
                 : "r"(a0), "r"(a1), "r"(a2), "r"(a3), "r"(b0), "r"(b1));
}
__device__ __forceinline__ unsigned short bfh(float v){ return __bfloat16_as_ushort(__float2bfloat16_rn(v)); }
__device__ __forceinline__ float bf2f(unsigned short u){ return __bfloat162float(__ushort_as_bfloat16(u)); }

// 4t x 4ol packed GEMM core (k1 proj)
template<int KC, int WSTR>
__device__ __forceinline__ void gemm44(const float* __restrict__ xs,
                                       const float* __restrict__ Ws,
                                       int tg, int og, u64 acc[4][2])
{
    const float* xp = xs + tg*4;
    const float* wp = Ws + og*4;
#pragma unroll 8
    for (int c = 0; c < KC; c++) {
        float4 xv = *(const float4*)(xp + c*64);
        ulonglong2 w = *(const ulonglong2*)(wp + c*WSTR);
        u64 x0 = dup2(xv.x), x1 = dup2(xv.y), x2 = dup2(xv.z), x3 = dup2(xv.w);
        fma2(acc[0][0], x0, w.x); fma2(acc[0][1], x0, w.y);
        fma2(acc[1][0], x1, w.x); fma2(acc[1][1], x1, w.y);
        fma2(acc[2][0], x2, w.x); fma2(acc[2][1], x2, w.y);
        fma2(acc[3][0], x3, w.x); fma2(acc[3][1], x3, w.y);
    }
}

// ================= Kernel 1 (unchanged, passing) ================================================
#define K1_WB 6336
__global__ void __launch_bounds__(512,1) k1_attn(
    const float* __restrict__ x, const float* __restrict__ l0,
    const float* __restrict__ n1w, const float* __restrict__ n1b,
    const float* __restrict__ qkvw,
    const float* __restrict__ gw, const float* __restrict__ gbv,
    const float* __restrict__ pw, const float* __restrict__ pbv)
{
    extern __shared__ float sm[];
    float* xs  = sm;
    float* qt  = xs + 8192;
    float* kt  = qt + 8448;
    float* vt  = kt + 8448;
    float* Wb  = vt + 8448;
    float* l0s = Wb + 2*K1_WB;
    float* red = l0s + 64;

    const int tid = threadIdx.x;
    const int blk = blockIdx.x;
    const int b   = blk >> 10, wr = blk & 1023;
    const int y0  = (wr >> 5) << 3, xw = (wr & 31) << 3;
    const float* xb = x + (size_t)b*128*HWSZ;
    const int tg4  = tid & 15;
    const int og12 = tid >> 4;

    for (int idx = tid; idx < 8192; idx += 512) {
        int c = idx >> 6, t = idx & 63;
        xs[c*64 + t] = xb[(size_t)c*HWSZ + (y0 + (t>>3))*NWD + xw + (t&7)];
    }
    if (tid < 64) l0s[tid] = l0[(size_t)b*HWSZ + (y0 + (tid>>3))*NWD + xw + (tid&7)];
    __syncthreads();

    {
        int t = tid & 63, q8 = tid >> 6;
        float s = 0.f, ss = 0.f;
#pragma unroll
        for (int cc = 0; cc < 16; cc++) {
            float v = xs[(q8*16+cc)*64 + t];
            s += v; ss += v*v;
        }
        red[q8*64+t] = s; red[512 + q8*64+t] = ss;
        __syncthreads();
        s = 0.f; ss = 0.f;
#pragma unroll
        for (int k = 0; k < 8; k++) { s += red[k*64+t]; ss += red[512 + k*64+t]; }
        float mu   = s*(1.f/128.f);
        float rstd = rsqrtf(ss*(1.f/128.f) - mu*mu + 1e-6f);
#pragma unroll
        for (int cc = 0; cc < 16; cc++) {
            int c = q8*16+cc;
            xs[c*64+t] = (xs[c*64+t]-mu)*rstd*n1w[c] + n1b[c];
        }
    }

    u64 acc[4][6];
#pragma unroll
    for (int r = 0; r < 4; r++)
#pragma unroll
        for (int p = 0; p < 6; p++) acc[r][p] = 0ull;

#pragma unroll
    for (int i = 0; i < 12; i++) {
        int idx = tid + i*512;
        int cc = idx & 15, o = idx >> 4;
        Wb[cc*396 + o] = qkvw[(size_t)o*128 + cc];
    }
    __syncthreads();

    for (int ck = 0; ck < 8; ck++) {
        const float* Wcur = Wb + (ck & 1)*K1_WB;
        float pf[12];
        if (ck < 7) {
            int c0n = (ck+1)*16;
#pragma unroll
            for (int i = 0; i < 12; i++) {
                int idx = tid + i*512;
                int cc = idx & 15, o = idx >> 4;
                pf[i] = qkvw[(size_t)o*128 + c0n + cc];
            }
        }
        const int c0 = ck*16;
        const float* wrow0 = Wcur + og12*12;
#pragma unroll 4
        for (int cc = 0; cc < 16; cc++) {
            float4 xv = *(const float4*)(xs + (c0+cc)*64 + tg4*4);
            const float* wrow = wrow0 + cc*396;
            ulonglong2 wA = *(const ulonglong2*)(wrow);
            ulonglong2 wB = *(const ulonglong2*)(wrow + 4);
            ulonglong2 wC = *(const ulonglong2*)(wrow + 8);
            u64 x0 = dup2(xv.x), x1 = dup2(xv.y), x2 = dup2(xv.z), x3 = dup2(xv.w);
            fma2(acc[0][0], x0, wA.x); fma2(acc[0][1], x0, wA.y); fma2(acc[0][2], x0, wB.x);
            fma2(acc[0][3], x0, wB.y); fma2(acc[0][4], x0, wC.x); fma2(acc[0][5], x0, wC.y);
            fma2(acc[1][0], x1, wA.x); fma2(acc[1][1], x1, wA.y); fma2(acc[1][2], x1, wB.x);
            fma2(acc[1][3], x1, wB.y); fma2(acc[1][4], x1, wC.x); fma2(acc[1][5], x1, wC.y);
            fma2(acc[2][0], x2, wA.x); fma2(acc[2][1], x2, wA.y); fma2(acc[2][2], x2, wB.x);
            fma2(acc[2][3], x2, wB.y); fma2(acc[2][4], x2, wC.x); fma2(acc[2][5], x2, wC.y);
            fma2(acc[3][0], x3, wA.x); fma2(acc[3][1], x3, wA.y); fma2(acc[3][2], x3, wB.x);
            fma2(acc[3][3], x3, wB.y); fma2(acc[3][4], x3, wC.x); fma2(acc[3][5], x3, wC.y);
        }
        if (ck < 7) {
            float* Wnext = Wb + ((ck+1) & 1)*K1_WB;
#pragma unroll
            for (int i = 0; i < 12; i++) {
                int idx = tid + i*512;
                int cc = idx & 15, o = idx >> 4;
                Wnext[cc*396 + o] = pf[i];
            }
        }
        __syncthreads();
    }

#pragma unroll
    for (int r = 0; r < 4; r++) {
        int t = tg4*4 + r;
        float lv = l0s[t];
#pragma unroll
        for (int p = 0; p < 6; p++) {
            int ol = og12*12 + p*2;
            float lo = lo2(acc[r][p]), hi = hi2(acc[r][p]);
            int seg = ol >> 7, loc = ol & 127;
            float* dst = (seg == 0) ? qt : (seg == 1) ? kt : vt;
            if (seg == 0) {
                lo *= sigm(lv*gw[ol]   + gbv[ol]);
                hi *= sigm(lv*gw[ol+1] + gbv[ol+1]);
            }
            *(u64*)(dst + t*132 + loc) = pk2(lo, hi);
        }
    }
    __syncthreads();

    if (tid < 256) {
        const int ip = tid & 31, hd = tid >> 5;
        const int qo = hd*16;
        const ulonglong2* qpA = (const ulonglong2*)(qt + ip*132 + qo);
        const ulonglong2* qpB = (const ulonglong2*)(qt + (ip+32)*132 + qo);
        ulonglong2 qa0 = qpA[0], qa1 = qpA[1], qa2 = qpA[2], qa3 = qpA[3];
        ulonglong2 qb0 = qpB[0], qb1 = qpB[1], qb2 = qpB[2], qb3 = qpB[3];

        float mA = -1e30f, lA = 0.f, mB = -1e30f, lB = 0.f;
        u64 oA[8], oB[8];
#pragma unroll
        for (int d2 = 0; d2 < 8; d2++) { oA[d2] = 0ull; oB[d2] = 0ull; }

        for (int jc = 0; jc < 8; jc++) {
            float eA[8], eB[8];
            float cmA = -1e30f, cmB = -1e30f;
#pragma unroll
            for (int jj = 0; jj < 8; jj++) {
                int j = jc*8 + jj;
                const ulonglong2* kp = (const ulonglong2*)(kt + j*132 + qo);
                ulonglong2 k0 = kp[0], k1 = kp[1], k2 = kp[2], k3 = kp[3];
                u64 a = 0ull;
                fma2(a, qa0.x, k0.x); fma2(a, qa0.y, k0.y);
                fma2(a, qa1.x, k1.x); fma2(a, qa1.y, k1.y);
                fma2(a, qa2.x, k2.x); fma2(a, qa2.y, k2.y);
                fma2(a, qa3.x, k3.x); fma2(a, qa3.y, k3.y);
                float sA = (lo2(a) + hi2(a))*0.25f;
                u64 bq = 0ull;
                fma2(bq, qb0.x, k0.x); fma2(bq, qb0.y, k0.y);
                fma2(bq, qb1.x, k1.x); fma2(bq, qb1.y, k1.y);
                fma2(bq, qb2.x, k2.x); fma2(bq, qb2.y, k2.y);
                fma2(bq, qb3.x, k3.x); fma2(bq, qb3.y, k3.y);
                float sB = (lo2(bq) + hi2(bq))*0.25f;
                eA[jj] = sA; cmA = fmaxf(cmA, sA);
                eB[jj] = sB; cmB = fmaxf(cmB, sB);
            }
            float mnA = fmaxf(mA, cmA), mnB = fmaxf(mB, cmB);
            float scA = __expf(mA - mnA), scB = __expf(mB - mnB);
            mA = mnA; mB = mnB;
            float sumA = 0.f, sumB = 0.f;
#pragma unroll
            for (int jj = 0; jj < 8; jj++) {
                eA[jj] = __expf(eA[jj] - mA); sumA += eA[jj];
                eB[jj] = __expf(eB[jj] - mB); sumB += eB[jj];
            }
            lA = lA*scA + sumA; lB = lB*scB + sumB;
            u64 s2A = dup2(scA), s2B = dup2(scB);
#pragma unroll
            for (int d2 = 0; d2 < 8; d2++) {
                oA[d2] = mul2(oA[d2], s2A);
                oB[d2] = mul2(oB[d2], s2B);
            }
#pragma unroll
            for (int jj = 0; jj < 8; jj++) {
                int j = jc*8 + jj;
                const ulonglong2* vp = (const ulonglong2*)(vt + j*132 + qo);
                ulonglong2 v0 = vp[0], v1 = vp[1], v2 = vp[2], v3 = vp[3];
                u64 pA = dup2(eA[jj]), pB = dup2(eB[jj]);
                fma2(oA[0], pA, v0.x); fma2(oA[1], pA, v0.y);
                fma2(oA[2], pA, v1.x); fma2(oA[3], pA, v1.y);
                fma2(oA[4], pA, v2.x); fma2(oA[5], pA, v2.y);
                fma2(oA[6], pA, v3.x); fma2(oA[7], pA, v3.y);
                fma2(oB[0], pB, v0.x); fma2(oB[1], pB, v0.y);
                fma2(oB[2], pB, v1.x); fma2(oB[3], pB, v1.y);
                fma2(oB[4], pB, v2.x); fma2(oB[5], pB, v2.y);
                fma2(oB[6], pB, v3.x); fma2(oB[7], pB, v3.y);
            }
        }
        float invA = 1.f/lA, invB = 1.f/lB;
#pragma unroll
        for (int d2 = 0; d2 < 8; d2++) {
            xs[(qo + d2*2  )*64 + ip]      = lo2(oA[d2])*invA;
            xs[(qo + d2*2+1)*64 + ip]      = hi2(oA[d2])*invA;
            xs[(qo + d2*2  )*64 + ip + 32] = lo2(oB[d2])*invB;
            xs[(qo + d2*2+1)*64 + ip + 32] = hi2(oB[d2])*invB;
        }
    }
    __syncthreads();

    float* Wsp = kt;
    for (int idx = tid; idx < 16384; idx += 512) {
        int c = idx & 127, ol = idx >> 7;
        Wsp[c*132 + ol] = pw[(size_t)ol*128 + c];
    }
    __syncthreads();
    {
        const int og = tid >> 4;
        u64 pacc[4][2];
#pragma unroll
        for (int r = 0; r < 4; r++) { pacc[r][0] = 0ull; pacc[r][1] = 0ull; }
        gemm44<128,132>(xs, Wsp, tg4, og, pacc);

        float* r1 = g_res1 + (size_t)b*128*HWSZ;
        const int t0 = tg4*4;
        const size_t pix = (size_t)(y0 + (t0>>3))*NWD + xw + (t0&7);
#pragma unroll
        for (int jp = 0; jp < 2; jp++)
#pragma unroll
            for (int h = 0; h < 2; h++) {
                int o = og*4 + jp*2 + h;
                float pb = pbv[o];
                float4 s4 = *(const float4*)(xb + (size_t)o*HWSZ + pix);
                float4 col;
                col.x = (h ? hi2(pacc[0][jp]) : lo2(pacc[0][jp])) + pb + s4.x;
                col.y = (h ? hi2(pacc[1][jp]) : lo2(pacc[1][jp])) + pb + s4.y;
                col.z = (h ? hi2(pacc[2][jp]) : lo2(pacc[2][jp])) + pb + s4.z;
                col.w = (h ? hi2(pacc[3][jp]) : lo2(pacc[3][jp])) + pb + s4.w;
                *(float4*)(r1 + (size_t)o*HWSZ + pix) = col;
            }
    }
}

// ================= Kernel 2: mma.sync bf16 3-pass (unchanged, passing) ==========================
#define K2B_BH   0
#define K2B_BL   34816
#define K2B_AH   69632
#define K2B_AL   104448
#define K2B_B1   139264
#define K2B_N2W  141312
#define K2B_N2B  141824
#define K2B_RED  142336
#define K2B_SMEM 144384

__global__ void __launch_bounds__(256,1) k2_ffn1(
    const float* __restrict__ n2w, const float* __restrict__ n2b,
    const float* __restrict__ w1, const float* __restrict__ b1)
{
    extern __shared__ char smc[];
    float* xs   = (float*)(smc);
    float* b1s  = (float*)(smc + K2B_B1);
    float* n2ws = (float*)(smc + K2B_N2W);
    float* n2bs = (float*)(smc + K2B_N2B);
    float* red  = (float*)(smc + K2B_RED);

    const int tid  = threadIdx.x;
    const int wid  = tid >> 5, lane = tid & 31;
    const int blk  = blockIdx.x;
    const int b    = blk >> 9, rr = blk & 511;
    const int y    = rr >> 1, x0 = (rr & 1)*128;
    const float* rb = g_res1 + (size_t)b*128*HWSZ + (size_t)y*NWD + x0;

    if (tid < 128) { n2ws[tid] = n2w[tid]; n2bs[tid] = n2b[tid]; }
    b1s[tid] = b1[tid]; b1s[tid+256] = b1[tid+256];

#pragma unroll
    for (int i = 0; i < 16; i++) {
        int idx = tid + i*256;
        int c = idx >> 5, f4 = idx & 31;
        *(float4*)(xs + c*128 + f4*4) = *(const float4*)(rb + (size_t)c*HWSZ + f4*4);
    }
    __syncthreads();

    {
        const int t = tid & 127, h = tid >> 7;
        float s = 0.f, ss = 0.f;
#pragma unroll
        for (int cc = 0; cc < 64; cc++) {
            float v = xs[(h*64+cc)*128 + t];
            s += v; ss += v*v;
        }
        red[h*128+t] = s; red[256 + h*128+t] = ss;
        __syncthreads();
        s  = red[t] + red[128+t];
        ss = red[256+t] + red[384+t];
        float mu   = s*(1.f/128.f);
        float rstd = rsqrtf(ss*(1.f/128.f) - mu*mu + 1e-6f);

        char* Ah = smc + K2B_AH + t*272;
        char* Al = smc + K2B_AL + t*272;
#pragma unroll 8
        for (int cc = 0; cc < 64; cc += 2) {
            int c = h*64 + cc;
            float v0 = (xs[c*128+t]     - mu)*rstd*n2ws[c]   + n2bs[c];
            float v1 = (xs[(c+1)*128+t] - mu)*rstd*n2ws[c+1] + n2bs[c+1];
            unsigned short h0 = bfh(v0), h1 = bfh(v1);
            unsigned short l0v = bfh(v0 - bf2f(h0)), l1v = bfh(v1 - bf2f(h1));
            *(uint32_t*)(Ah + c*2) = (uint32_t)h0  | ((uint32_t)h1  << 16);
            *(uint32_t*)(Al + c*2) = (uint32_t)l0v | ((uint32_t)l1v << 16);
        }
    }
    __syncthreads();

    const uint32_t AhB = smem_u32(smc + K2B_AH), AlB = smem_u32(smc + K2B_AL);
    const uint32_t BhB = smem_u32(smc + K2B_BH), BlB = smem_u32(smc + K2B_BL);
    const int tileM = wid*16;
    const uint32_t aoff = (uint32_t)((tileM + (lane & 15))*272 + (((lane >> 4) << 3))*2);
    const uint32_t boff = (uint32_t)((((lane >> 4) << 3) + (lane & 7))*272 + (((lane >> 3) & 1) << 3)*2);

    float* hb = g_h1 + (size_t)b*512*HWSZ + (size_t)y*NWD + x0;
    const int g = lane >> 2, n0l = (lane & 3)*2;

    for (int ck = 0; ck < 4; ck++) {
        {
            int n_l = tid >> 1, kh = (tid & 1)*64;
            const float* wr = w1 + (size_t)(ck*128 + n_l)*128 + kh;
            char* BhP = smc + K2B_BH + n_l*272 + kh*2;
            char* BlP = smc + K2B_BL + n_l*272 + kh*2;
#pragma unroll 4
            for (int cc = 0; cc < 64; cc += 4) {
                float4 wv = *(const float4*)(wr + cc);
                unsigned short h0 = bfh(wv.x), h1 = bfh(wv.y), h2 = bfh(wv.z), h3 = bfh(wv.w);
                unsigned short l0v = bfh(wv.x - bf2f(h0)), l1v = bfh(wv.y - bf2f(h1));
                unsigned short l2v = bfh(wv.z - bf2f(h2)), l3v = bfh(wv.w - bf2f(h3));
                *(uint32_t*)(BhP + cc*2)     = (uint32_t)h0  | ((uint32_t)h1  << 16);
                *(uint32_t*)(BhP + cc*2 + 4) = (uint32_t)h2  | ((uint32_t)h3  << 16);
                *(uint32_t*)(BlP + cc*2)     = (uint32_t)l0v | ((uint32_t)l1v << 16);
                *(uint32_t*)(BlP + cc*2 + 4) = (uint32_t)l2v | ((uint32_t)l3v << 16);
            }
        }
        __syncthreads();

        float acc[16][4];
#pragma unroll
        for (int nb = 0; nb < 16; nb++)
#pragma unroll
            for (int q = 0; q < 4; q++) acc[nb][q] = 0.f;

#pragma unroll
        for (int pass = 0; pass < 3; pass++) {
            const uint32_t Ab = (pass == 1) ? AlB : AhB;
            const uint32_t Bb = (pass == 2) ? BlB : BhB;
#pragma unroll
            for (int k16 = 0; k16 < 8; k16++) {
                uint32_t a0, a1, a2, a3;
                ldsm4(a0, a1, a2, a3, Ab + aoff + k16*32);
#pragma unroll
                for (int nbp = 0; nbp < 8; nbp++) {
                    uint32_t b0, b1r, b2, b3;
                    ldsm4(b0, b1r, b2, b3, Bb + boff + (uint32_t)(nbp*16*272) + k16*32);
                    mma_bf16(acc[nbp*2],     a0, a1, a2, a3, b0, b1r);
                    mma_bf16(acc[nbp*2 + 1], a0, a1, a2, a3, b2, b3);
                }
            }
        }

#pragma unroll
        for (int nb = 0; nb < 16; nb++) {
            int n = ck*128 + nb*8 + n0l;
            float bb0 = b1s[n], bb1 = b1s[n+1];
            int m0 = tileM + g;
            hb[(size_t)n*HWSZ + m0]         = gelu_f(acc[nb][0] + bb0);
            hb[(size_t)(n+1)*HWSZ + m0]     = gelu_f(acc[nb][1] + bb1);
            hb[(size_t)n*HWSZ + m0 + 8]     = gelu_f(acc[nb][2] + bb0);
            hb[(size_t)(n+1)*HWSZ + m0 + 8] = gelu_f(acc[nb][3] + bb1);
        }
        __syncthreads();
    }
}

// ================= Kernel 3: depthwise 3x3 + GELU + mma.sync FFN2 + residual ====================
// CTA = 8x8 spatial tile. M=64 tok, N=128, K=512 (8 chunks of 64).
// A stored k-major [ch][tok] bf16 hi/lo (pitch 144 B), loaded via ldmatrix.trans.
// B = w2 [n][k-chunk] bf16 hi/lo (pitch 144 B), non-trans.
#define K3_HS   0                      // halo fp32 [64ch][128f pitch]  32768 B
#define K3_AH   32768                  // 64 x 144                       9216 B
#define K3_AL   (K3_AH + 9216)
#define K3_BH   (K3_AL + 9216)         // 128 x 144                     18432 B
#define K3_BL   (K3_BH + 18432)
#define K3_SMEM (K3_BL + 18432)        // 88064 B

__global__ void __launch_bounds__(256,2) k3_ffn2(
    const float* __restrict__ dw, const float* __restrict__ dwb,
    const float* __restrict__ w2, const float* __restrict__ b2,
    float* __restrict__ out)
{
    extern __shared__ char smc[];
    float* hs = (float*)(smc + K3_HS);

    const int tid = threadIdx.x;
    const int wid = tid >> 5, lane = tid & 31;
    const int blk = blockIdx.x;
    const int b   = blk >> 10, rr = blk & 1023;
    const int y0  = (rr >> 5) << 3, xw = (rr & 31) << 3;
    const float* hbase = g_h1 + (size_t)b*512*HWSZ;

    const int tileM = (wid & 3)*16;        // m-stripe
    const int nhalf = (wid >> 2)*64;       // n-half
    const uint32_t AhB = smem_u32(smc + K3_AH), AlB = smem_u32(smc + K3_AL);
    const uint32_t BhB = smem_u32(smc + K3_BH), BlB = smem_u32(smc + K3_BL);
    // A via trans-ldmatrix from [k][m]: lanes 0-7:(k0-7,m+0) 8-15:(k0-7,m+8) 16-23:(k8-15,m+0) 24-31:(k8-15,m+8)
    const uint32_t aoff = (uint32_t)(((((lane >> 4) << 3) + (lane & 7))*144) + (tileM + (((lane >> 3) & 1) << 3))*2);
    const uint32_t boff = (uint32_t)(((((lane >> 4) << 3) + (lane & 7)) + nhalf)*144 + (((lane >> 3) & 1) << 3)*2);

    float acc[8][4];
#pragma unroll
    for (int nb = 0; nb < 8; nb++)
#pragma unroll
        for (int q = 0; q < 4; q++) acc[nb][q] = 0.f;

    for (int ck = 0; ck < 8; ck++) {
        const int c0 = ck*64;
        // halo load
        for (int idx = tid; idx < 6400; idx += 256) {
            int ch = idx / 100;
            int p  = idx - ch*100;
            int pr = p / 10;
            int pc = p - pr*10;
            int py = y0 - 1 + pr;
            int px = xw - 1 + pc;
            float v = 0.f;
            if ((unsigned)py < 256u && (unsigned)px < 256u)
                v = hbase[(size_t)(c0+ch)*HWSZ + py*NWD + px];
            hs[ch*128 + pr*12 + pc] = v;
        }
        // stage B chunk: w2[n=0..127][k=c0..c0+63] hi/lo
        {
            int n_l = tid >> 1, kh = (tid & 1)*32;
            const float* wr = w2 + (size_t)n_l*512 + c0 + kh;
            char* BhP = smc + K3_BH + n_l*144 + kh*2;
            char* BlP = smc + K3_BL + n_l*144 + kh*2;
#pragma unroll 4
            for (int cc = 0; cc < 32; cc += 4) {
                float4 wv = *(const float4*)(wr + cc);
                unsigned short h0 = bfh(wv.x), h1 = bfh(wv.y), h2 = bfh(wv.z), h3 = bfh(wv.w);
                unsigned short l0v = bfh(wv.x - bf2f(h0)), l1v = bfh(wv.y - bf2f(h1));
                unsigned short l2v = bfh(wv.z - bf2f(h2)), l3v = bfh(wv.w - bf2f(h3));
                *(uint32_t*)(BhP + cc*2)     = (uint32_t)h0  | ((uint32_t)h1  << 16);
                *(uint32_t*)(BhP + cc*2 + 4) = (uint32_t)h2  | ((uint32_t)h3  << 16);
                *(uint32_t*)(BlP + cc*2)     = (uint32_t)l0v | ((uint32_t)l1v << 16);
                *(uint32_t*)(BlP + cc*2 + 4) = (uint32_t)l2v | ((uint32_t)l3v << 16);
            }
        }
        __syncthreads();

        // depthwise conv + GELU -> A hi/lo [k=ch][m=tok], one STS.128 per tile
#pragma unroll
        for (int k = 0; k < 2; k++) {
            int u   = tid + k*256;
            int chl = u >> 3, row = u & 7;
            const float* dwp = dw + (size_t)(c0+chl)*9;
            const float* hp  = hs + chl*128 + row*12;
            float o8[8];
            float bbv = dwb[c0+chl];
#pragma unroll
            for (int xp = 0; xp < 8; xp++) o8[xp] = bbv;
#pragma unroll
            for (int ky = 0; ky < 3; ky++) {
                const float* rp = hp + ky*12;
                float4 ra = *(const float4*)(rp);
                float4 rb4 = *(const float4*)(rp + 4);
                float2 rc = *(const float2*)(rp + 8);
                float rw[10] = {ra.x, ra.y, ra.z, ra.w, rb4.x, rb4.y, rb4.z, rb4.w, rc.x, rc.y};
                float d0 = dwp[ky*3], d1 = dwp[ky*3+1], d2 = dwp[ky*3+2];
#pragma unroll
                for (int xp = 0; xp < 8; xp++)
                    o8[xp] = fmaf(d0, rw[xp], fmaf(d1, rw[xp+1], fmaf(d2, rw[xp+2], o8[xp])));
            }
            uint32_t hpk[4], lpk[4];
#pragma unroll
            for (int i = 0; i < 4; i++) {
                float v0 = gelu_f(o8[2*i]), v1 = gelu_f(o8[2*i+1]);
                unsigned short h0 = bfh(v0), h1 = bfh(v1);
                unsigned short l0v = bfh(v0 - bf2f(h0)), l1v = bfh(v1 - bf2f(h1));
                hpk[i] = (uint32_t)h0  | ((uint32_t)h1  << 16);
                lpk[i] = (uint32_t)l0v | ((uint32_t)l1v << 16);
            }
            *(uint4*)(smc + K3_AH + chl*144 + row*16) = make_uint4(hpk[0], hpk[1], hpk[2], hpk[3]);
            *(uint4*)(smc + K3_AL + chl*144 + row*16) = make_uint4(lpk[0], lpk[1], lpk[2], lpk[3]);
        }
        __syncthreads();

        // mma: 3 passes x 4 k16 x 4 n16-blocks
#pragma unroll
        for (int pass = 0; pass < 3; pass++) {
            const uint32_t Ab = (pass == 1) ? AlB : AhB;
            const uint32_t Bb = (pass == 2) ? BlB : BhB;
#pragma unroll
            for (int k16 = 0; k16 < 4; k16++) {
                uint32_t a0, a1, a2, a3;
                ldsm4t(a0, a1, a2, a3, Ab + aoff + k16*2304);   // 16 k-rows * 144 B
#pragma unroll
                for (int nbp = 0; nbp < 4; nbp++) {
                    uint32_t b0, b1r, b2, b3;
                    ldsm4(b0, b1r, b2, b3, Bb + boff + (uint32_t)(nbp*16*144) + k16*32);
                    mma_bf16(acc[nbp*2],     a0, a1, a2, a3, b0, b1r);
                    mma_bf16(acc[nbp*2 + 1], a0, a1, a2, a3, b2, b3);
                }
            }
        }
        __syncthreads();
    }

    // epilogue: bias + residual + store
    {
        const float* r1 = g_res1 + (size_t)b*128*HWSZ;
        float* ob = out + (size_t)b*128*HWSZ;
        const int g = lane >> 2, n0l = (lane & 3)*2;
        const int m0 = tileM + g;
        const size_t pix0 = (size_t)(y0 + (m0 >> 3))*NWD + xw + (m0 & 7);
        const size_t pix1 = pix0 + NWD;   // token m0+8 = one image row below (same x)
#pragma unroll
        for (int nb = 0; nb < 8; nb++) {
            int o = nhalf + nb*8 + n0l;
            float bb0 = b2[o], bb1 = b2[o+1];
            size_t i00 = (size_t)o*HWSZ + pix0, i10 = (size_t)(o+1)*HWSZ + pix0;
            size_t i01 = (size_t)o*HWSZ + pix1, i11 = (size_t)(o+1)*HWSZ + pix1;
            ob[i00] = acc[nb][0] + bb0 + r1[i00];
            ob[i10] = acc[nb][1] + bb1 + r1[i10];
            ob[i01] = acc[nb][2] + bb0 + r1[i01];
            ob[i11] = acc[nb][3] + bb1 + r1[i11];
        }
    }
}

// =================================================================================================
extern "C" void kernel_launch(void* const* d_in, const int* in_sizes, int n_in,
                              void* d_out, int out_size)
{
    const float* x    = (const float*)d_in[0];
    const float* l0   = (const float*)d_in[1];
    const float* n1w  = (const float*)d_in[2];
    const float* n1b  = (const float*)d_in[3];
    const float* n2w  = (const float*)d_in[4];
    const float* n2b  = (const float*)d_in[5];
    const float* qkvw = (const float*)d_in[6];
    const float* gw   = (const float*)d_in[7];
    const float* gb   = (const float*)d_in[8];
    const float* pw   = (const float*)d_in[9];
    const float* pb   = (const float*)d_in[10];
    const float* w1   = (const float*)d_in[11];
    const float* b1   = (const float*)d_in[12];
    const float* dwv  = (const float*)d_in[13];
    const float* dwb  = (const float*)d_in[14];
    const float* w2   = (const float*)d_in[15];
    const float* b2   = (const float*)d_in[16];
    float* out = (float*)d_out;

    const int smem1 = (8192 + 3*8448 + 2*K1_WB + 64 + 1024) * (int)sizeof(float);  // 189184

    cudaFuncSetAttribute(k1_attn, cudaFuncAttributeMaxDynamicSharedMemorySize, smem1);
    cudaFuncSetAttribute(k2_ffn1, cudaFuncAttributeMaxDynamicSharedMemorySize, K2B_SMEM);
    cudaFuncSetAttribute(k3_ffn2, cudaFuncAttributeMaxDynamicSharedMemorySize, K3_SMEM);

    k1_attn<<<4096, 512, smem1>>>(x, l0, n1w, n1b, qkvw, gw, gb, pw, pb);
    k2_ffn1<<<2048, 256, K2B_SMEM>>>(n2w, n2b, w1, b1);
    k3_ffn2<<<4096, 256, K3_SMEM>>>(dwv, dwb, w2, b2, out);
}

// round 15
// speedup vs baseline: 3.6292x; 1.3590x over previous
#include <cuda_runtime.h>
#include <cuda_bf16.h>
#include <stdint.h>
#include <math.h>

#define HWSZ 65536
#define NWD  256
typedef unsigned long long u64;

__device__ float g_res1[4ull*128*HWSZ];
__device__ float g_h1  [4ull*512*HWSZ];

// precomputed bf16 hi/lo weights
__device__ __align__(16) unsigned short g_wqkv_h[384*128];
__device__ __align__(16) unsigned short g_wqkv_l[384*128];
__device__ __align__(16) unsigned short g_wp_h[128*128];
__device__ __align__(16) unsigned short g_wp_l[128*128];
__device__ __align__(16) unsigned short g_w1_h[512*128];
__device__ __align__(16) unsigned short g_w1_l[512*128];
__device__ __align__(16) unsigned short g_w2_h[128*512];
__device__ __align__(16) unsigned short g_w2_l[128*512];

__device__ __forceinline__ u64 pk2(float lo, float hi){ u64 r; asm("mov.b64 %0,{%1,%2};":"=l"(r):"f"(lo),"f"(hi)); return r; }
__device__ __forceinline__ u64 dup2(float v){ return pk2(v, v); }
__device__ __forceinline__ void fma2(u64& d, u64 a, u64 b){ asm("fma.rn.f32x2 %0,%1,%2,%0;":"+l"(d):"l"(a),"l"(b)); }
__device__ __forceinline__ u64 mul2(u64 a, u64 b){ u64 d; asm("mul.rn.f32x2 %0,%1,%2;":"=l"(d):"l"(a),"l"(b)); return d; }
__device__ __forceinline__ float lo2(u64 v){ return __uint_as_float((unsigned)v); }
__device__ __forceinline__ float hi2(u64 v){ return __uint_as_float((unsigned)(v>>32)); }
__device__ __forceinline__ float gelu_f(float v){ return 0.5f*v*(1.0f + erff(v*0.7071067811865475f)); }
__device__ __forceinline__ float sigm(float z){ return 1.f/(1.f + __expf(-z)); }

__device__ __forceinline__ uint32_t smem_u32(const void* p){
    uint32_t a;
    asm("{ .reg .u64 t; cvta.to.shared.u64 t, %1; cvt.u32.u64 %0, t; }" : "=r"(a) : "l"(p));
    return a;
}
__device__ __forceinline__ void ldsm4(uint32_t& r0, uint32_t& r1, uint32_t& r2, uint32_t& r3, uint32_t addr){
    asm volatile("ldmatrix.sync.aligned.m8n8.x4.shared.b16 {%0,%1,%2,%3}, [%4];"
                 : "=r"(r0), "=r"(r1), "=r"(r2), "=r"(r3) : "r"(addr));
}
__device__ __forceinline__ void ldsm4t(uint32_t& r0, uint32_t& r1, uint32_t& r2, uint32_t& r3, uint32_t addr){
    asm volatile("ldmatrix.sync.aligned.m8n8.x4.trans.shared.b16 {%0,%1,%2,%3}, [%4];"
                 : "=r"(r0), "=r"(r1), "=r"(r2), "=r"(r3) : "r"(addr));
}
__device__ __forceinline__ void mma_bf16(float* d, uint32_t a0, uint32_t a1, uint32_t a2, uint32_t a3,
                                         uint32_t b0, uint32_t b1){
    asm volatile("mma.sync.aligned.m16n8k16.row.col.f32.bf16.bf16.f32 "
                 "{%0,%1,%2,%3}, {%4,%5,%6,%7}, {%8,%9}, {%0,%1,%2,%3};"
                 : "+f"(d[0]), "+f"(d[1]), "+f"(d[2]), "+f"(d[3])
                 : "r"(a0), "r"(a1), "r"(a2), "r"(a3), "r"(b0), "r"(b1));
}
__device__ __forceinline__ unsigned short bfh(float v){ return __bfloat16_as_ushort(__float2bfloat16_rn(v)); }
__device__ __forceinline__ float bf2f(unsigned short u){ return __bfloat162float(__ushort_as_bfloat16(u)); }

// ================= Kernel 0: precompute bf16 hi/lo weights ======================================
__global__ void kconv(const float* __restrict__ qkvw, const float* __restrict__ pw,
                      const float* __restrict__ w1, const float* __restrict__ w2)
{
    int i = blockIdx.x*256 + threadIdx.x;   // 768 blocks * 256 = 196608
    if (i < 49152) {
        float v = qkvw[i];
        unsigned short h = bfh(v);
        g_wqkv_h[i] = h; g_wqkv_l[i] = bfh(v - bf2f(h));
    } else if (i < 65536) {
        int j = i - 49152;
        float v = pw[j];
        unsigned short h = bfh(v);
        g_wp_h[j] = h; g_wp_l[j] = bfh(v - bf2f(h));
    } else if (i < 131072) {
        int j = i - 65536;
        float v = w1[j];
        unsigned short h = bfh(v);
        g_w1_h[j] = h; g_w1_l[j] = bfh(v - bf2f(h));
    } else {
        int j = i - 131072;
        float v = w2[j];
        unsigned short h = bfh(v);
        g_w2_h[j] = h; g_w2_l[j] = bfh(v - bf2f(h));
    }
}

// ================= Kernel 1: LN1 + mma QKV + gate + attention + mma proj + residual =============
// smem byte layout:
#define K1_AH   0            // A hi  64 x 272
#define K1_AL   17408        // A lo
#define K1_BH   34816        // B hi 128 x 272 (region also hosts fp32 xs / attention out)
#define K1_BL   69632        // B lo
#define K1_QT   104448       // qt fp32 [64][132]
#define K1_KT   138240
#define K1_VT   172032
#define K1_L0S  205824
#define K1_RED  206080
#define K1_SMEM 210176

__global__ void __launch_bounds__(512,1) k1_attn(
    const float* __restrict__ x, const float* __restrict__ l0,
    const float* __restrict__ n1w, const float* __restrict__ n1b,
    const float* __restrict__ gw, const float* __restrict__ gbv,
    const float* __restrict__ pbv)
{
    extern __shared__ char smc[];
    float* xs  = (float*)(smc + K1_BH);   // fp32 x window / attention output [c][64]
    float* qt  = (float*)(smc + K1_QT);
    float* kt  = (float*)(smc + K1_KT);
    float* vt  = (float*)(smc + K1_VT);
    float* l0s = (float*)(smc + K1_L0S);
    float* red = (float*)(smc + K1_RED);

    const int tid = threadIdx.x;
    const int wid = tid >> 5, lane = tid & 31;
    const int blk = blockIdx.x;
    const int b   = blk >> 10, wr = blk & 1023;
    const int y0  = (wr >> 5) << 3, xw = (wr & 31) << 3;
    const float* xb = x + (size_t)b*128*HWSZ;

    // load x window [c][64]
    for (int idx = tid; idx < 8192; idx += 512) {
        int c = idx >> 6, t = idx & 63;
        xs[c*64 + t] = xb[(size_t)c*HWSZ + (y0 + (t>>3))*NWD + xw + (t&7)];
    }
    if (tid < 64) l0s[tid] = l0[(size_t)b*HWSZ + (y0 + (tid>>3))*NWD + xw + (tid&7)];
    __syncthreads();

    // LN1 fused with A hi/lo tile build ([m=t][k=c], pitch 272B)
    {
        int t = tid & 63, q8 = tid >> 6;
        float s = 0.f, ss = 0.f;
#pragma unroll
        for (int cc = 0; cc < 16; cc++) {
            float v = xs[(q8*16+cc)*64 + t];
            s += v; ss += v*v;
        }
        red[q8*64+t] = s; red[512 + q8*64+t] = ss;
        __syncthreads();
        s = 0.f; ss = 0.f;
#pragma unroll
        for (int k = 0; k < 8; k++) { s += red[k*64+t]; ss += red[512 + k*64+t]; }
        float mu   = s*(1.f/128.f);
        float rstd = rsqrtf(ss*(1.f/128.f) - mu*mu + 1e-6f);

        char* Ah = smc + K1_AH + t*272 + q8*32;
        char* Al = smc + K1_AL + t*272 + q8*32;
#pragma unroll
        for (int cc = 0; cc < 16; cc += 2) {
            int c = q8*16 + cc;
            float v0 = (xs[c*64+t]     - mu)*rstd*n1w[c]   + n1b[c];
            float v1 = (xs[(c+1)*64+t] - mu)*rstd*n1w[c+1] + n1b[c+1];
            unsigned short h0 = bfh(v0), h1 = bfh(v1);
            unsigned short l0v = bfh(v0 - bf2f(h0)), l1v = bfh(v1 - bf2f(h1));
            *(uint32_t*)(Ah + cc*2) = (uint32_t)h0  | ((uint32_t)h1  << 16);
            *(uint32_t*)(Al + cc*2) = (uint32_t)l0v | ((uint32_t)l1v << 16);
        }
    }
    __syncthreads();    // xs dead; A ready; B region free

    const int mrow = wid & 3, nq = wid >> 2;
    const uint32_t AhB = smem_u32(smc + K1_AH), AlB = smem_u32(smc + K1_AL);
    const uint32_t BhB = smem_u32(smc + K1_BH), BlB = smem_u32(smc + K1_BL);
    const uint32_t aoff = (uint32_t)((mrow*16 + (lane & 15))*272 + (((lane >> 4) << 3))*2);
    const uint32_t boff = (uint32_t)(((((lane >> 4) << 3) + (lane & 7)) + nq*32)*272 + (((lane >> 3) & 1) << 4));
    const int g = lane >> 2, n0l = (lane & 3)*2;
    const int t0v = mrow*16 + g, t1v = t0v + 8;

    // ---- QKV: 3 segments of 128 outputs via mma ----
    for (int ot = 0; ot < 3; ot++) {
#pragma unroll
        for (int i = 0; i < 8; i++) {
            int idx = tid + i*512;                 // 0..4095
            int half = idx >> 11, rem = idx & 2047;
            int row = rem >> 4, seg = rem & 15;
            const unsigned short* src = (half ? g_wqkv_l : g_wqkv_h)
                                        + (size_t)(ot*128 + row)*128 + seg*8;
            *(uint4*)(smc + (half ? K1_BL : K1_BH) + row*272 + seg*16) = *(const uint4*)src;
        }
        __syncthreads();

        float acc[4][4];
#pragma unroll
        for (int j = 0; j < 4; j++)
#pragma unroll
            for (int q = 0; q < 4; q++) acc[j][q] = 0.f;

#pragma unroll
        for (int pass = 0; pass < 3; pass++) {
            const uint32_t Ab = (pass == 1) ? AlB : AhB;
            const uint32_t Bb = (pass == 2) ? BlB : BhB;
#pragma unroll
            for (int k16 = 0; k16 < 8; k16++) {
                uint32_t a0, a1, a2, a3;
                ldsm4(a0, a1, a2, a3, Ab + aoff + k16*32);
#pragma unroll
                for (int nb2 = 0; nb2 < 2; nb2++) {
                    uint32_t b0, b1r, b2, b3;
                    ldsm4(b0, b1r, b2, b3, Bb + boff + (uint32_t)(nb2*16*272) + k16*32);
                    mma_bf16(acc[nb2*2],     a0, a1, a2, a3, b0, b1r);
                    mma_bf16(acc[nb2*2 + 1], a0, a1, a2, a3, b2, b3);
                }
            }
        }

        float* dst = (ot == 0) ? qt : (ot == 1) ? kt : vt;
        if (ot == 0) {
            float lv0 = l0s[t0v], lv1 = l0s[t1v];
#pragma unroll
            for (int j = 0; j < 4; j++) {
                int n = nq*32 + j*8 + n0l;
                float gw0 = gw[n], gw1 = gw[n+1], gb0 = gbv[n], gb1 = gbv[n+1];
                *(u64*)(dst + t0v*132 + n) = pk2(acc[j][0]*sigm(lv0*gw0+gb0),
                                                 acc[j][1]*sigm(lv0*gw1+gb1));
                *(u64*)(dst + t1v*132 + n) = pk2(acc[j][2]*sigm(lv1*gw0+gb0),
                                                 acc[j][3]*sigm(lv1*gw1+gb1));
            }
        } else {
#pragma unroll
            for (int j = 0; j < 4; j++) {
                int n = nq*32 + j*8 + n0l;
                *(u64*)(dst + t0v*132 + n) = pk2(acc[j][0], acc[j][1]);
                *(u64*)(dst + t1v*132 + n) = pk2(acc[j][2], acc[j][3]);
            }
        }
        __syncthreads();
    }

    // ---- attention: 8 heads x 32 i-pairs, online softmax (unchanged) ----
    if (tid < 256) {
        const int ip = tid & 31, hd = tid >> 5;
        const int qo = hd*16;
        const ulonglong2* qpA = (const ulonglong2*)(qt + ip*132 + qo);
        const ulonglong2* qpB = (const ulonglong2*)(qt + (ip+32)*132 + qo);
        ulonglong2 qa0 = qpA[0], qa1 = qpA[1], qa2 = qpA[2], qa3 = qpA[3];
        ulonglong2 qb0 = qpB[0], qb1 = qpB[1], qb2 = qpB[2], qb3 = qpB[3];

        float mA = -1e30f, lA = 0.f, mB = -1e30f, lB = 0.f;
        u64 oA[8], oB[8];
#pragma unroll
        for (int d2 = 0; d2 < 8; d2++) { oA[d2] = 0ull; oB[d2] = 0ull; }

        for (int jc = 0; jc < 8; jc++) {
            float eA[8], eB[8];
            float cmA = -1e30f, cmB = -1e30f;
#pragma unroll
            for (int jj = 0; jj < 8; jj++) {
                int j = jc*8 + jj;
                const ulonglong2* kp = (const ulonglong2*)(kt + j*132 + qo);
                ulonglong2 k0 = kp[0], k1 = kp[1], k2 = kp[2], k3 = kp[3];
                u64 a = 0ull;
                fma2(a, qa0.x, k0.x); fma2(a, qa0.y, k0.y);
                fma2(a, qa1.x, k1.x); fma2(a, qa1.y, k1.y);
                fma2(a, qa2.x, k2.x); fma2(a, qa2.y, k2.y);
                fma2(a, qa3.x, k3.x); fma2(a, qa3.y, k3.y);
                float sA = (lo2(a) + hi2(a))*0.25f;
                u64 bq = 0ull;
                fma2(bq, qb0.x, k0.x); fma2(bq, qb0.y, k0.y);
                fma2(bq, qb1.x, k1.x); fma2(bq, qb1.y, k1.y);
                fma2(bq, qb2.x, k2.x); fma2(bq, qb2.y, k2.y);
                fma2(bq, qb3.x, k3.x); fma2(bq, qb3.y, k3.y);
                float sB = (lo2(bq) + hi2(bq))*0.25f;
                eA[jj] = sA; cmA = fmaxf(cmA, sA);
                eB[jj] = sB; cmB = fmaxf(cmB, sB);
            }
            float mnA = fmaxf(mA, cmA), mnB = fmaxf(mB, cmB);
            float scA = __expf(mA - mnA), scB = __expf(mB - mnB);
            mA = mnA; mB = mnB;
            float sumA = 0.f, sumB = 0.f;
#pragma unroll
            for (int jj = 0; jj < 8; jj++) {
                eA[jj] = __expf(eA[jj] - mA); sumA += eA[jj];
                eB[jj] = __expf(eB[jj] - mB); sumB += eB[jj];
            }
            lA = lA*scA + sumA; lB = lB*scB + sumB;
            u64 s2A = dup2(scA), s2B = dup2(scB);
#pragma unroll
            for (int d2 = 0; d2 < 8; d2++) {
                oA[d2] = mul2(oA[d2], s2A);
                oB[d2] = mul2(oB[d2], s2B);
            }
#pragma unroll
            for (int jj = 0; jj < 8; jj++) {
                int j = jc*8 + jj;
                const ulonglong2* vp = (const ulonglong2*)(vt + j*132 + qo);
                ulonglong2 v0 = vp[0], v1 = vp[1], v2 = vp[2], v3 = vp[3];
                u64 pA = dup2(eA[jj]), pB = dup2(eB[jj]);
                fma2(oA[0], pA, v0.x); fma2(oA[1], pA, v0.y);
                fma2(oA[2], pA, v1.x); fma2(oA[3], pA, v1.y);
                fma2(oA[4], pA, v2.x); fma2(oA[5], pA, v2.y);
                fma2(oA[6], pA, v3.x); fma2(oA[7], pA, v3.y);
                fma2(oB[0], pB, v0.x); fma2(oB[1], pB, v0.y);
                fma2(oB[2], pB, v1.x); fma2(oB[3], pB, v1.y);
                fma2(oB[4], pB, v2.x); fma2(oB[5], pB, v2.y);
                fma2(oB[6], pB, v3.x); fma2(oB[7], pB, v3.y);
            }
        }
        float invA = 1.f/lA, invB = 1.f/lB;
#pragma unroll
        for (int d2 = 0; d2 < 8; d2++) {
            xs[(qo + d2*2  )*64 + ip]      = lo2(oA[d2])*invA;
            xs[(qo + d2*2+1)*64 + ip]      = hi2(oA[d2])*invA;
            xs[(qo + d2*2  )*64 + ip + 32] = lo2(oB[d2])*invB;
            xs[(qo + d2*2+1)*64 + ip + 32] = hi2(oB[d2])*invB;
        }
    }
    __syncthreads();

    // ---- proj via mma: A' from attention output ----
    {
        int t = tid & 63, q8 = tid >> 6;
        char* Ah = smc + K1_AH + t*272 + q8*32;
        char* Al = smc + K1_AL + t*272 + q8*32;
#pragma unroll
        for (int cc = 0; cc < 16; cc += 2) {
            int c = q8*16 + cc;
            float v0 = xs[c*64 + t];
            float v1 = xs[(c+1)*64 + t];
            unsigned short h0 = bfh(v0), h1 = bfh(v1);
            unsigned short l0v = bfh(v0 - bf2f(h0)), l1v = bfh(v1 - bf2f(h1));
            *(uint32_t*)(Ah + cc*2) = (uint32_t)h0  | ((uint32_t)h1  << 16);
            *(uint32_t*)(Al + cc*2) = (uint32_t)l0v | ((uint32_t)l1v << 16);
        }
    }
    __syncthreads();    // ao consumed

#pragma unroll
    for (int i = 0; i < 8; i++) {
        int idx = tid + i*512;
        int half = idx >> 11, rem = idx & 2047;
        int row = rem >> 4, seg = rem & 15;
        const unsigned short* src = (half ? g_wp_l : g_wp_h) + (size_t)row*128 + seg*8;
        *(uint4*)(smc + (half ? K1_BL : K1_BH) + row*272 + seg*16) = *(const uint4*)src;
    }
    __syncthreads();

    {
        float acc[4][4];
#pragma unroll
        for (int j = 0; j < 4; j++)
#pragma unroll
            for (int q = 0; q < 4; q++) acc[j][q] = 0.f;

#pragma unroll
        for (int pass = 0; pass < 3; pass++) {
            const uint32_t Ab = (pass == 1) ? AlB : AhB;
            const uint32_t Bb = (pass == 2) ? BlB : BhB;
#pragma unroll
            for (int k16 = 0; k16 < 8; k16++) {
                uint32_t a0, a1, a2, a3;
                ldsm4(a0, a1, a2, a3, Ab + aoff + k16*32);
#pragma unroll
                for (int nb2 = 0; nb2 < 2; nb2++) {
                    uint32_t b0, b1r, b2, b3;
                    ldsm4(b0, b1r, b2, b3, Bb + boff + (uint32_t)(nb2*16*272) + k16*32);
                    mma_bf16(acc[nb2*2],     a0, a1, a2, a3, b0, b1r);
                    mma_bf16(acc[nb2*2 + 1], a0, a1, a2, a3, b2, b3);
                }
            }
        }

        float* r1 = g_res1 + (size_t)b*128*HWSZ;
        const size_t pix0 = (size_t)(y0 + (t0v>>3))*NWD + xw + (t0v & 7);
        const size_t pix1 = (size_t)(y0 + (t1v>>3))*NWD + xw + (t1v & 7);
#pragma unroll
        for (int j = 0; j < 4; j++) {
            int n = nq*32 + j*8 + n0l;
            float pb0 = pbv[n], pb1 = pbv[n+1];
            size_t i00 = (size_t)n*HWSZ + pix0, i10 = (size_t)(n+1)*HWSZ + pix0;
            size_t i01 = (size_t)n*HWSZ + pix1, i11 = (size_t)(n+1)*HWSZ + pix1;
            r1[i00] = acc[j][0] + pb0 + xb[i00];
            r1[i10] = acc[j][1] + pb1 + xb[i10];
            r1[i01] = acc[j][2] + pb0 + xb[i01];
            r1[i11] = acc[j][3] + pb1 + xb[i11];
        }
    }
}

// ================= Kernel 2: mma.sync bf16 3-pass (staging now a copy) ==========================
#define K2B_BH   0
#define K2B_BL   34816
#define K2B_AH   69632
#define K2B_AL   104448
#define K2B_B1   139264
#define K2B_N2W  141312
#define K2B_N2B  141824
#define K2B_RED  142336
#define K2B_SMEM 144384

__global__ void __launch_bounds__(256,1) k2_ffn1(
    const float* __restrict__ n2w, const float* __restrict__ n2b,
    const float* __restrict__ b1)
{
    extern __shared__ char smc[];
    float* xs   = (float*)(smc);
    float* b1s  = (float*)(smc + K2B_B1);
    float* n2ws = (float*)(smc + K2B_N2W);
    float* n2bs = (float*)(smc + K2B_N2B);
    float* red  = (float*)(smc + K2B_RED);

    const int tid  = threadIdx.x;
    const int wid  = tid >> 5, lane = tid & 31;
    const int blk  = blockIdx.x;
    const int b    = blk >> 9, rr = blk & 511;
    const int y    = rr >> 1, x0 = (rr & 1)*128;
    const float* rb = g_res1 + (size_t)b*128*HWSZ + (size_t)y*NWD + x0;

    if (tid < 128) { n2ws[tid] = n2w[tid]; n2bs[tid] = n2b[tid]; }
    b1s[tid] = b1[tid]; b1s[tid+256] = b1[tid+256];

#pragma unroll
    for (int i = 0; i < 16; i++) {
        int idx = tid + i*256;
        int c = idx >> 5, f4 = idx & 31;
        *(float4*)(xs + c*128 + f4*4) = *(const float4*)(rb + (size_t)c*HWSZ + f4*4);
    }
    __syncthreads();

    {
        const int t = tid & 127, h = tid >> 7;
        float s = 0.f, ss = 0.f;
#pragma unroll
        for (int cc = 0; cc < 64; cc++) {
            float v = xs[(h*64+cc)*128 + t];
            s += v; ss += v*v;
        }
        red[h*128+t] = s; red[256 + h*128+t] = ss;
        __syncthreads();
        s  = red[t] + red[128+t];
        ss = red[256+t] + red[384+t];
        float mu   = s*(1.f/128.f);
        float rstd = rsqrtf(ss*(1.f/128.f) - mu*mu + 1e-6f);

        char* Ah = smc + K2B_AH + t*272;
        char* Al = smc + K2B_AL + t*272;
#pragma unroll 8
        for (int cc = 0; cc < 64; cc += 2) {
            int c = h*64 + cc;
            float v0 = (xs[c*128+t]     - mu)*rstd*n2ws[c]   + n2bs[c];
            float v1 = (xs[(c+1)*128+t] - mu)*rstd*n2ws[c+1] + n2bs[c+1];
            unsigned short h0 = bfh(v0), h1 = bfh(v1);
            unsigned short l0v = bfh(v0 - bf2f(h0)), l1v = bfh(v1 - bf2f(h1));
            *(uint32_t*)(Ah + c*2) = (uint32_t)h0  | ((uint32_t)h1  << 16);
            *(uint32_t*)(Al + c*2) = (uint32_t)l0v | ((uint32_t)l1v << 16);
        }
    }
    __syncthreads();

    const uint32_t AhB = smem_u32(smc + K2B_AH), AlB = smem_u32(smc + K2B_AL);
    const uint32_t BhB = smem_u32(smc + K2B_BH), BlB = smem_u32(smc + K2B_BL);
    const int tileM = wid*16;
    const uint32_t aoff = (uint32_t)((tileM + (lane & 15))*272 + (((lane >> 4) << 3))*2);
    const uint32_t boff = (uint32_t)((((lane >> 4) << 3) + (lane & 7))*272 + (((lane >> 3) & 1) << 3)*2);

    float* hb = g_h1 + (size_t)b*512*HWSZ + (size_t)y*NWD + x0;
    const int g = lane >> 2, n0l = (lane & 3)*2;

    for (int ck = 0; ck < 4; ck++) {
        // stage B chunk: pure copy from precomputed bf16
#pragma unroll
        for (int i = 0; i < 16; i++) {
            int idx = tid + i*256;                 // 0..4095
            int half = idx >> 11, rem = idx & 2047;
            int row = rem >> 4, seg = rem & 15;
            const unsigned short* src = (half ? g_w1_l : g_w1_h)
                                        + (size_t)(ck*128 + row)*128 + seg*8;
            *(uint4*)(smc + (half ? K2B_BL : K2B_BH) + row*272 + seg*16) = *(const uint4*)src;
        }
        __syncthreads();

        float acc[16][4];
#pragma unroll
        for (int nb = 0; nb < 16; nb++)
#pragma unroll
            for (int q = 0; q < 4; q++) acc[nb][q] = 0.f;

#pragma unroll
        for (int pass = 0; pass < 3; pass++) {
            const uint32_t Ab = (pass == 1) ? AlB : AhB;
            const uint32_t Bb = (pass == 2) ? BlB : BhB;
#pragma unroll
            for (int k16 = 0; k16 < 8; k16++) {
                uint32_t a0, a1, a2, a3;
                ldsm4(a0, a1, a2, a3, Ab + aoff + k16*32);
#pragma unroll
                for (int nbp = 0; nbp < 8; nbp++) {
                    uint32_t b0, b1r, b2, b3;
                    ldsm4(b0, b1r, b2, b3, Bb + boff + (uint32_t)(nbp*16*272) + k16*32);
                    mma_bf16(acc[nbp*2],     a0, a1, a2, a3, b0, b1r);
                    mma_bf16(acc[nbp*2 + 1], a0, a1, a2, a3, b2, b3);
                }
            }
        }

#pragma unroll
        for (int nb = 0; nb < 16; nb++) {
            int n = ck*128 + nb*8 + n0l;
            float bb0 = b1s[n], bb1 = b1s[n+1];
            int m0 = tileM + g;
            hb[(size_t)n*HWSZ + m0]         = gelu_f(acc[nb][0] + bb0);
            hb[(size_t)(n+1)*HWSZ + m0]     = gelu_f(acc[nb][1] + bb1);
            hb[(size_t)n*HWSZ + m0 + 8]     = gelu_f(acc[nb][2] + bb0);
            hb[(size_t)(n+1)*HWSZ + m0 + 8] = gelu_f(acc[nb][3] + bb1);
        }
        __syncthreads();
    }
}

// ================= Kernel 3: depthwise 3x3 + GELU + mma FFN2, 64-n B halves, occ3 ===============
#define K3_HS   0                      // halo fp32                32768 B
#define K3_AH   32768                  // 64 x 144                  9216 B
#define K3_AL   41984
#define K3_BH   51200                  // 64 x 144 (one n-half)     9216 B
#define K3_BL   60416
#define K3_SMEM 69632

__global__ void __launch_bounds__(256,3) k3_ffn2(
    const float* __restrict__ dw, const float* __restrict__ dwb,
    const float* __restrict__ b2, float* __restrict__ out)
{
    extern __shared__ char smc[];
    float* hs = (float*)(smc + K3_HS);

    const int tid = threadIdx.x;
    const int wid = tid >> 5, lane = tid & 31;
    const int blk = blockIdx.x;
    const int b   = blk >> 10, rr = blk & 1023;
    const int y0  = (rr >> 5) << 3, xw = (rr & 31) << 3;
    const float* hbase = g_h1 + (size_t)b*512*HWSZ;

    const int mrow = wid & 3, nq2 = wid >> 2;   // 4 m-stripes x 2 n32-quarters (within 64-n half)
    const uint32_t AhB = smem_u32(smc + K3_AH), AlB = smem_u32(smc + K3_AL);
    const uint32_t BhB = smem_u32(smc + K3_BH), BlB = smem_u32(smc + K3_BL);
    const uint32_t aoff = (uint32_t)(((((lane >> 4) << 3) + (lane & 7))*144) + (mrow*16 + (((lane >> 3) & 1) << 3))*2);
    const uint32_t boff = (uint32_t)(((((lane >> 4) << 3) + (lane & 7)) + nq2*32)*144 + (((lane >> 3) & 1) << 4));

    float acc[2][4][4];
#pragma unroll
    for (int h = 0; h < 2; h++)
#pragma unroll
        for (int j = 0; j < 4; j++)
#pragma unroll
            for (int q = 0; q < 4; q++) acc[h][j][q] = 0.f;

    for (int ck = 0; ck < 8; ck++) {
        const int c0 = ck*64;
        // halo load
        for (int idx = tid; idx < 6400; idx += 256) {
            int ch = idx / 100;
            int p  = idx - ch*100;
            int pr = p / 10;
            int pc = p - pr*10;
            int py = y0 - 1 + pr;
            int px = xw - 1 + pc;
            float v = 0.f;
            if ((unsigned)py < 256u && (unsigned)px < 256u)
                v = hbase[(size_t)(c0+ch)*HWSZ + py*NWD + px];
            hs[ch*128 + pr*12 + pc] = v;
        }
        // stage B half 0 (copy)
#pragma unroll
        for (int i = 0; i < 4; i++) {
            int idx = tid + i*256;                 // 0..1023
            int hl = idx >> 9, rem = idx & 511;
            int row = rem >> 3, seg = rem & 7;
            const unsigned short* src = (hl ? g_w2_l : g_w2_h)
                                        + (size_t)row*512 + c0 + seg*8;
            *(uint4*)(smc + (hl ? K3_BL : K3_BH) + row*144 + seg*16) = *(const uint4*)src;
        }
        __syncthreads();

        // depthwise conv + GELU -> A hi/lo [k=ch][m=tok]
#pragma unroll
        for (int k = 0; k < 2; k++) {
            int u   = tid + k*256;
            int chl = u >> 3, row = u & 7;
            const float* dwp = dw + (size_t)(c0+chl)*9;
            const float* hp  = hs + chl*128 + row*12;
            float o8[8];
            float bbv = dwb[c0+chl];
#pragma unroll
            for (int xp = 0; xp < 8; xp++) o8[xp] = bbv;
#pragma unroll
            for (int ky = 0; ky < 3; ky++) {
                const float* rp = hp + ky*12;
                float4 ra = *(const float4*)(rp);
                float4 rb4 = *(const float4*)(rp + 4);
                float2 rc = *(const float2*)(rp + 8);
                float rw[10] = {ra.x, ra.y, ra.z, ra.w, rb4.x, rb4.y, rb4.z, rb4.w, rc.x, rc.y};
                float d0 = dwp[ky*3], d1 = dwp[ky*3+1], d2 = dwp[ky*3+2];
#pragma unroll
                for (int xp = 0; xp < 8; xp++)
                    o8[xp] = fmaf(d0, rw[xp], fmaf(d1, rw[xp+1], fmaf(d2, rw[xp+2], o8[xp])));
            }
            uint32_t hpk[4], lpk[4];
#pragma unroll
            for (int i = 0; i < 4; i++) {
                float v0 = gelu_f(o8[2*i]), v1 = gelu_f(o8[2*i+1]);
                unsigned short h0 = bfh(v0), h1 = bfh(v1);
                unsigned short l0v = bfh(v0 - bf2f(h0)), l1v = bfh(v1 - bf2f(h1));
                hpk[i] = (uint32_t)h0  | ((uint32_t)h1  << 16);
                lpk[i] = (uint32_t)l0v | ((uint32_t)l1v << 16);
            }
            *(uint4*)(smc + K3_AH + chl*144 + row*16) = make_uint4(hpk[0], hpk[1], hpk[2], hpk[3]);
            *(uint4*)(smc + K3_AL + chl*144 + row*16) = make_uint4(lpk[0], lpk[1], lpk[2], lpk[3]);
        }
        __syncthreads();

        // mma half 0
#pragma unroll
        for (int pass = 0; pass < 3; pass++) {
            const uint32_t Ab = (pass == 1) ? AlB : AhB;
            const uint32_t Bb = (pass == 2) ? BlB : BhB;
#pragma unroll
            for (int k16 = 0; k16 < 4; k16++) {
                uint32_t a0, a1, a2, a3;
                ldsm4t(a0, a1, a2, a3, Ab + aoff + k16*2304);
#pragma unroll
                for (int nb2 = 0; nb2 < 2; nb2++) {
                    uint32_t b0, b1r, b2, b3;
                    ldsm4(b0, b1r, b2, b3, Bb + boff + (uint32_t)(nb2*16*144) + k16*32);
                    mma_bf16(acc[0][nb2*2],     a0, a1, a2, a3, b0, b1r);
                    mma_bf16(acc[0][nb2*2 + 1], a0, a1, a2, a3, b2, b3);
                }
            }
        }
        __syncthreads();

        // stage B half 1 (copy)
#pragma unroll
        for (int i = 0; i < 4; i++) {
            int idx = tid + i*256;
            int hl = idx >> 9, rem = idx & 511;
            int row = rem >> 3, seg = rem & 7;
            const unsigned short* src = (hl ? g_w2_l : g_w2_h)
                                        + (size_t)(64 + row)*512 + c0 + seg*8;
            *(uint4*)(smc + (hl ? K3_BL : K3_BH) + row*144 + seg*16) = *(const uint4*)src;
        }
        __syncthreads();

        // mma half 1
#pragma unroll
        for (int pass = 0; pass < 3; pass++) {
            const uint32_t Ab = (pass == 1) ? AlB : AhB;
            const uint32_t Bb = (pass == 2) ? BlB : BhB;
#pragma unroll
            for (int k16 = 0; k16 < 4; k16++) {
                uint32_t a0, a1, a2, a3;
                ldsm4t(a0, a1, a2, a3, Ab + aoff + k16*2304);
#pragma unroll
                for (int nb2 = 0; nb2 < 2; nb2++) {
                    uint32_t b0, b1r, b2, b3;
                    ldsm4(b0, b1r, b2, b3, Bb + boff + (uint32_t)(nb2*16*144) + k16*32);
                    mma_bf16(acc[1][nb2*2],     a0, a1, a2, a3, b0, b1r);
                    mma_bf16(acc[1][nb2*2 + 1], a0, a1, a2, a3, b2, b3);
                }
            }
        }
        __syncthreads();
    }

    // epilogue: bias + residual + store
    {
        const float* r1 = g_res1 + (size_t)b*128*HWSZ;
        float* ob = out + (size_t)b*128*HWSZ;
        const int g = lane >> 2, n0l = (lane & 3)*2;
        const int m0 = mrow*16 + g;
        const size_t pix0 = (size_t)(y0 + (m0 >> 3))*NWD + xw + (m0 & 7);
        const size_t pix1 = pix0 + NWD;   // token m0+8 = next image row
#pragma unroll
        for (int h = 0; h < 2; h++)
#pragma unroll
            for (int j = 0; j < 4; j++) {
                int o = h*64 + nq2*32 + j*8 + n0l;
                float bb0 = b2[o], bb1 = b2[o+1];
                size_t i00 = (size_t)o*HWSZ + pix0, i10 = (size_t)(o+1)*HWSZ + pix0;
                size_t i01 = (size_t)o*HWSZ + pix1, i11 = (size_t)(o+1)*HWSZ + pix1;
                ob[i00] = acc[h][j][0] + bb0 + r1[i00];
                ob[i10] = acc[h][j][1] + bb1 + r1[i10];
                ob[i01] = acc[h][j][2] + bb0 + r1[i01];
                ob[i11] = acc[h][j][3] + bb1 + r1[i11];
            }
    }
}

// =================================================================================================
extern "C" void kernel_launch(void* const* d_in, const int* in_sizes, int n_in,
                              void* d_out, int out_size)
{
    const float* x    = (const float*)d_in[0];
    const float* l0   = (const float*)d_in[1];
    const float* n1w  = (const float*)d_in[2];
    const float* n1b  = (const float*)d_in[3];
    const float* n2w  = (const float*)d_in[4];
    const float* n2b  = (const float*)d_in[5];
    const float* qkvw = (const float*)d_in[6];
    const float* gw   = (const float*)d_in[7];
    const float* gb   = (const float*)d_in[8];
    const float* pw   = (const float*)d_in[9];
    const float* pb   = (const float*)d_in[10];
    const float* w1   = (const float*)d_in[11];
    const float* b1   = (const float*)d_in[12];
    const float* dwv  = (const float*)d_in[13];
    const float* dwb  = (const float*)d_in[14];
    const float* w2   = (const float*)d_in[15];
    const float* b2   = (const float*)d_in[16];
    float* out = (float*)d_out;

    cudaFuncSetAttribute(k1_attn, cudaFuncAttributeMaxDynamicSharedMemorySize, K1_SMEM);
    cudaFuncSetAttribute(k2_ffn1, cudaFuncAttributeMaxDynamicSharedMemorySize, K2B_SMEM);
    cudaFuncSetAttribute(k3_ffn2, cudaFuncAttributeMaxDynamicSharedMemorySize, K3_SMEM);

    kconv<<<768, 256>>>(qkvw, pw, w1, w2);
    k1_attn<<<4096, 512, K1_SMEM>>>(x, l0, n1w, n1b, gw, gb, pb);
    k2_ffn1<<<2048, 256, K2B_SMEM>>>(n2w, n2b, b1);
    k3_ffn2<<<4096, 256, K3_SMEM>>>(dwv, dwb, b2, out);
}

// round 16
// speedup vs baseline: 3.6753x; 1.0127x over previous
#include <cuda_runtime.h>
#include <cuda_bf16.h>
#include <stdint.h>
#include <math.h>

#define HWSZ 65536
#define NWD  256
typedef unsigned long long u64;

__device__ float g_res1[4ull*128*HWSZ];
__device__ float g_h1  [4ull*512*HWSZ];

// precomputed bf16 hi/lo weights
__device__ __align__(16) unsigned short g_wqkv_h[384*128];
__device__ __align__(16) unsigned short g_wqkv_l[384*128];
__device__ __align__(16) unsigned short g_wp_h[128*128];
__device__ __align__(16) unsigned short g_wp_l[128*128];
__device__ __align__(16) unsigned short g_w1_h[512*128];
__device__ __align__(16) unsigned short g_w1_l[512*128];
__device__ __align__(16) unsigned short g_w2_h[128*512];
__device__ __align__(16) unsigned short g_w2_l[128*512];

__device__ __forceinline__ u64 pk2(float lo, float hi){ u64 r; asm("mov.b64 %0,{%1,%2};":"=l"(r):"f"(lo),"f"(hi)); return r; }
__device__ __forceinline__ u64 dup2(float v){ return pk2(v, v); }
__device__ __forceinline__ void fma2(u64& d, u64 a, u64 b){ asm("fma.rn.f32x2 %0,%1,%2,%0;":"+l"(d):"l"(a),"l"(b)); }
__device__ __forceinline__ u64 mul2(u64 a, u64 b){ u64 d; asm("mul.rn.f32x2 %0,%1,%2;":"=l"(d):"l"(a),"l"(b)); return d; }
__device__ __forceinline__ float lo2(u64 v){ return __uint_as_float((unsigned)v); }
__device__ __forceinline__ float hi2(u64 v){ return __uint_as_float((unsigned)(v>>32)); }
__device__ __forceinline__ float gelu_f(float v){ return 0.5f*v*(1.0f + erff(v*0.7071067811865475f)); }
__device__ __forceinline__ float sigm(float z){ return 1.f/(1.f + __expf(-z)); }

__device__ __forceinline__ uint32_t smem_u32(const void* p){
    uint32_t a;
    asm("{ .reg .u64 t; cvta.to.shared.u64 t, %1; cvt.u32.u64 %0, t; }" : "=r"(a) : "l"(p));
    return a;
}
__device__ __forceinline__ void ldsm4(uint32_t& r0, uint32_t& r1, uint32_t& r2, uint32_t& r3, uint32_t addr){
    asm volatile("ldmatrix.sync.aligned.m8n8.x4.shared.b16 {%0,%1,%2,%3}, [%4];"
                 : "=r"(r0), "=r"(r1), "=r"(r2), "=r"(r3) : "r"(addr));
}
__device__ __forceinline__ void ldsm4t(uint32_t& r0, uint32_t& r1, uint32_t& r2, uint32_t& r3, uint32_t addr){
    asm volatile("ldmatrix.sync.aligned.m8n8.x4.trans.shared.b16 {%0,%1,%2,%3}, [%4];"
                 : "=r"(r0), "=r"(r1), "=r"(r2), "=r"(r3) : "r"(addr));
}
__device__ __forceinline__ void mma_bf16(float* d, uint32_t a0, uint32_t a1, uint32_t a2, uint32_t a3,
                                         uint32_t b0, uint32_t b1){
    asm volatile("mma.sync.aligned.m16n8k16.row.col.f32.bf16.bf16.f32 "
                 "{%0,%1,%2,%3}, {%4,%5,%6,%7}, {%8,%9}, {%0,%1,%2,%3};"
                 : "+f"(d[0]), "+f"(d[1]), "+f"(d[2]), "+f"(d[3])
                 : "r"(a0), "r"(a1), "r"(a2), "r"(a3), "r"(b0), "r"(b1));
}
__device__ __forceinline__ unsigned short bfh(float v){ return __bfloat16_as_ushort(__float2bfloat16_rn(v)); }
__device__ __forceinline__ float bf2f(unsigned short u){ return __bfloat162float(__ushort_as_bfloat16(u)); }

// ================= Kernel 0: precompute bf16 hi/lo weights ======================================
__global__ void kconv(const float* __restrict__ qkvw, const float* __restrict__ pw,
                      const float* __restrict__ w1, const float* __restrict__ w2)
{
    int i = blockIdx.x*256 + threadIdx.x;
    if (i < 49152) {
        float v = qkvw[i];
        unsigned short h = bfh(v);
        g_wqkv_h[i] = h; g_wqkv_l[i] = bfh(v - bf2f(h));
    } else if (i < 65536) {
        int j = i - 49152;
        float v = pw[j];
        unsigned short h = bfh(v);
        g_wp_h[j] = h; g_wp_l[j] = bfh(v - bf2f(h));
    } else if (i < 131072) {
        int j = i - 65536;
        float v = w1[j];
        unsigned short h = bfh(v);
        g_w1_h[j] = h; g_w1_l[j] = bfh(v - bf2f(h));
    } else {
        int j = i - 131072;
        float v = w2[j];
        unsigned short h = bfh(v);
        g_w2_h[j] = h; g_w2_l[j] = bfh(v - bf2f(h));
    }
}

// ================= Kernel 1: LN1 + mma QKV + gate + attention + mma proj + residual =============
#define K1_AH   0
#define K1_AL   17408
#define K1_BH   34816
#define K1_BL   69632
#define K1_QT   104448
#define K1_KT   138240
#define K1_VT   172032
#define K1_L0S  205824
#define K1_RED  206080
#define K1_SMEM 210176

__global__ void __launch_bounds__(512,1) k1_attn(
    const float* __restrict__ x, const float* __restrict__ l0,
    const float* __restrict__ n1w, const float* __restrict__ n1b,
    const float* __restrict__ gw, const float* __restrict__ gbv,
    const float* __restrict__ pbv)
{
    extern __shared__ char smc[];
    float* xs  = (float*)(smc + K1_BH);
    float* qt  = (float*)(smc + K1_QT);
    float* kt  = (float*)(smc + K1_KT);
    float* vt  = (float*)(smc + K1_VT);
    float* l0s = (float*)(smc + K1_L0S);
    float* red = (float*)(smc + K1_RED);

    const int tid = threadIdx.x;
    const int wid = tid >> 5, lane = tid & 31;
    const int blk = blockIdx.x;
    const int b   = blk >> 10, wr = blk & 1023;
    const int y0  = (wr >> 5) << 3, xw = (wr & 31) << 3;
    const float* xb = x + (size_t)b*128*HWSZ;

    for (int idx = tid; idx < 8192; idx += 512) {
        int c = idx >> 6, t = idx & 63;
        xs[c*64 + t] = xb[(size_t)c*HWSZ + (y0 + (t>>3))*NWD + xw + (t&7)];
    }
    if (tid < 64) l0s[tid] = l0[(size_t)b*HWSZ + (y0 + (tid>>3))*NWD + xw + (tid&7)];
    __syncthreads();

    {
        int t = tid & 63, q8 = tid >> 6;
        float s = 0.f, ss = 0.f;
#pragma unroll
        for (int cc = 0; cc < 16; cc++) {
            float v = xs[(q8*16+cc)*64 + t];
            s += v; ss += v*v;
        }
        red[q8*64+t] = s; red[512 + q8*64+t] = ss;
        __syncthreads();
        s = 0.f; ss = 0.f;
#pragma unroll
        for (int k = 0; k < 8; k++) { s += red[k*64+t]; ss += red[512 + k*64+t]; }
        float mu   = s*(1.f/128.f);
        float rstd = rsqrtf(ss*(1.f/128.f) - mu*mu + 1e-6f);

        char* Ah = smc + K1_AH + t*272 + q8*32;
        char* Al = smc + K1_AL + t*272 + q8*32;
#pragma unroll
        for (int cc = 0; cc < 16; cc += 2) {
            int c = q8*16 + cc;
            float v0 = (xs[c*64+t]     - mu)*rstd*n1w[c]   + n1b[c];
            float v1 = (xs[(c+1)*64+t] - mu)*rstd*n1w[c+1] + n1b[c+1];
            unsigned short h0 = bfh(v0), h1 = bfh(v1);
            unsigned short l0v = bfh(v0 - bf2f(h0)), l1v = bfh(v1 - bf2f(h1));
            *(uint32_t*)(Ah + cc*2) = (uint32_t)h0  | ((uint32_t)h1  << 16);
            *(uint32_t*)(Al + cc*2) = (uint32_t)l0v | ((uint32_t)l1v << 16);
        }
    }
    __syncthreads();

    const int mrow = wid & 3, nq = wid >> 2;
    const uint32_t AhB = smem_u32(smc + K1_AH), AlB = smem_u32(smc + K1_AL);
    const uint32_t BhB = smem_u32(smc + K1_BH), BlB = smem_u32(smc + K1_BL);
    const uint32_t aoff = (uint32_t)((mrow*16 + (lane & 15))*272 + (((lane >> 4) << 3))*2);
    const uint32_t boff = (uint32_t)(((((lane >> 4) << 3) + (lane & 7)) + nq*32)*272 + (((lane >> 3) & 1) << 4));
    const int g = lane >> 2, n0l = (lane & 3)*2;
    const int t0v = mrow*16 + g, t1v = t0v + 8;

    for (int ot = 0; ot < 3; ot++) {
#pragma unroll
        for (int i = 0; i < 8; i++) {
            int idx = tid + i*512;
            int half = idx >> 11, rem = idx & 2047;
            int row = rem >> 4, seg = rem & 15;
            const unsigned short* src = (half ? g_wqkv_l : g_wqkv_h)
                                        + (size_t)(ot*128 + row)*128 + seg*8;
            *(uint4*)(smc + (half ? K1_BL : K1_BH) + row*272 + seg*16) = *(const uint4*)src;
        }
        __syncthreads();

        float acc[4][4];
#pragma unroll
        for (int j = 0; j < 4; j++)
#pragma unroll
            for (int q = 0; q < 4; q++) acc[j][q] = 0.f;

#pragma unroll
        for (int pass = 0; pass < 3; pass++) {
            const uint32_t Ab = (pass == 1) ? AlB : AhB;
            const uint32_t Bb = (pass == 2) ? BlB : BhB;
#pragma unroll
            for (int k16 = 0; k16 < 8; k16++) {
                uint32_t a0, a1, a2, a3;
                ldsm4(a0, a1, a2, a3, Ab + aoff + k16*32);
#pragma unroll
                for (int nb2 = 0; nb2 < 2; nb2++) {
                    uint32_t b0, b1r, b2, b3;
                    ldsm4(b0, b1r, b2, b3, Bb + boff + (uint32_t)(nb2*16*272) + k16*32);
                    mma_bf16(acc[nb2*2],     a0, a1, a2, a3, b0, b1r);
                    mma_bf16(acc[nb2*2 + 1], a0, a1, a2, a3, b2, b3);
                }
            }
        }

        float* dst = (ot == 0) ? qt : (ot == 1) ? kt : vt;
        if (ot == 0) {
            float lv0 = l0s[t0v], lv1 = l0s[t1v];
#pragma unroll
            for (int j = 0; j < 4; j++) {
                int n = nq*32 + j*8 + n0l;
                float gw0 = gw[n], gw1 = gw[n+1], gb0 = gbv[n], gb1 = gbv[n+1];
                *(u64*)(dst + t0v*132 + n) = pk2(acc[j][0]*sigm(lv0*gw0+gb0),
                                                 acc[j][1]*sigm(lv0*gw1+gb1));
                *(u64*)(dst + t1v*132 + n) = pk2(acc[j][2]*sigm(lv1*gw0+gb0),
                                                 acc[j][3]*sigm(lv1*gw1+gb1));
            }
        } else {
#pragma unroll
            for (int j = 0; j < 4; j++) {
                int n = nq*32 + j*8 + n0l;
                *(u64*)(dst + t0v*132 + n) = pk2(acc[j][0], acc[j][1]);
                *(u64*)(dst + t1v*132 + n) = pk2(acc[j][2], acc[j][3]);
            }
        }
        __syncthreads();
    }

    if (tid < 256) {
        const int ip = tid & 31, hd = tid >> 5;
        const int qo = hd*16;
        const ulonglong2* qpA = (const ulonglong2*)(qt + ip*132 + qo);
        const ulonglong2* qpB = (const ulonglong2*)(qt + (ip+32)*132 + qo);
        ulonglong2 qa0 = qpA[0], qa1 = qpA[1], qa2 = qpA[2], qa3 = qpA[3];
        ulonglong2 qb0 = qpB[0], qb1 = qpB[1], qb2 = qpB[2], qb3 = qpB[3];

        float mA = -1e30f, lA = 0.f, mB = -1e30f, lB = 0.f;
        u64 oA[8], oB[8];
#pragma unroll
        for (int d2 = 0; d2 < 8; d2++) { oA[d2] = 0ull; oB[d2] = 0ull; }

        for (int jc = 0; jc < 8; jc++) {
            float eA[8], eB[8];
            float cmA = -1e30f, cmB = -1e30f;
#pragma unroll
            for (int jj = 0; jj < 8; jj++) {
                int j = jc*8 + jj;
                const ulonglong2* kp = (const ulonglong2*)(kt + j*132 + qo);
                ulonglong2 k0 = kp[0], k1 = kp[1], k2 = kp[2], k3 = kp[3];
                u64 a = 0ull;
                fma2(a, qa0.x, k0.x); fma2(a, qa0.y, k0.y);
                fma2(a, qa1.x, k1.x); fma2(a, qa1.y, k1.y);
                fma2(a, qa2.x, k2.x); fma2(a, qa2.y, k2.y);
                fma2(a, qa3.x, k3.x); fma2(a, qa3.y, k3.y);
                float sA = (lo2(a) + hi2(a))*0.25f;
                u64 bq = 0ull;
                fma2(bq, qb0.x, k0.x); fma2(bq, qb0.y, k0.y);
                fma2(bq, qb1.x, k1.x); fma2(bq, qb1.y, k1.y);
                fma2(bq, qb2.x, k2.x); fma2(bq, qb2.y, k2.y);
                fma2(bq, qb3.x, k3.x); fma2(bq, qb3.y, k3.y);
                float sB = (lo2(bq) + hi2(bq))*0.25f;
                eA[jj] = sA; cmA = fmaxf(cmA, sA);
                eB[jj] = sB; cmB = fmaxf(cmB, sB);
            }
            float mnA = fmaxf(mA, cmA), mnB = fmaxf(mB, cmB);
            float scA = __expf(mA - mnA), scB = __expf(mB - mnB);
            mA = mnA; mB = mnB;
            float sumA = 0.f, sumB = 0.f;
#pragma unroll
            for (int jj = 0; jj < 8; jj++) {
                eA[jj] = __expf(eA[jj] - mA); sumA += eA[jj];
                eB[jj] = __expf(eB[jj] - mB); sumB += eB[jj];
            }
            lA = lA*scA + sumA; lB = lB*scB + sumB;
            u64 s2A = dup2(scA), s2B = dup2(scB);
#pragma unroll
            for (int d2 = 0; d2 < 8; d2++) {
                oA[d2] = mul2(oA[d2], s2A);
                oB[d2] = mul2(oB[d2], s2B);
            }
#pragma unroll
            for (int jj = 0; jj < 8; jj++) {
                int j = jc*8 + jj;
                const ulonglong2* vp = (const ulonglong2*)(vt + j*132 + qo);
                ulonglong2 v0 = vp[0], v1 = vp[1], v2 = vp[2], v3 = vp[3];
                u64 pA = dup2(eA[jj]), pB = dup2(eB[jj]);
                fma2(oA[0], pA, v0.x); fma2(oA[1], pA, v0.y);
                fma2(oA[2], pA, v1.x); fma2(oA[3], pA, v1.y);
                fma2(oA[4], pA, v2.x); fma2(oA[5], pA, v2.y);
                fma2(oA[6], pA, v3.x); fma2(oA[7], pA, v3.y);
                fma2(oB[0], pB, v0.x); fma2(oB[1], pB, v0.y);
                fma2(oB[2], pB, v1.x); fma2(oB[3], pB, v1.y);
                fma2(oB[4], pB, v2.x); fma2(oB[5], pB, v2.y);
                fma2(oB[6], pB, v3.x); fma2(oB[7], pB, v3.y);
            }
        }
        float invA = 1.f/lA, invB = 1.f/lB;
#pragma unroll
        for (int d2 = 0; d2 < 8; d2++) {
            xs[(qo + d2*2  )*64 + ip]      = lo2(oA[d2])*invA;
            xs[(qo + d2*2+1)*64 + ip]      = hi2(oA[d2])*invA;
            xs[(qo + d2*2  )*64 + ip + 32] = lo2(oB[d2])*invB;
            xs[(qo + d2*2+1)*64 + ip + 32] = hi2(oB[d2])*invB;
        }
    }
    __syncthreads();

    {
        int t = tid & 63, q8 = tid >> 6;
        char* Ah = smc + K1_AH + t*272 + q8*32;
        char* Al = smc + K1_AL + t*272 + q8*32;
#pragma unroll
        for (int cc = 0; cc < 16; cc += 2) {
            int c = q8*16 + cc;
            float v0 = xs[c*64 + t];
            float v1 = xs[(c+1)*64 + t];
            unsigned short h0 = bfh(v0), h1 = bfh(v1);
            unsigned short l0v = bfh(v0 - bf2f(h0)), l1v = bfh(v1 - bf2f(h1));
            *(uint32_t*)(Ah + cc*2) = (uint32_t)h0  | ((uint32_t)h1  << 16);
            *(uint32_t*)(Al + cc*2) = (uint32_t)l0v | ((uint32_t)l1v << 16);
        }
    }
    __syncthreads();

#pragma unroll
    for (int i = 0; i < 8; i++) {
        int idx = tid + i*512;
        int half = idx >> 11, rem = idx & 2047;
        int row = rem >> 4, seg = rem & 15;
        const unsigned short* src = (half ? g_wp_l : g_wp_h) + (size_t)row*128 + seg*8;
        *(uint4*)(smc + (half ? K1_BL : K1_BH) + row*272 + seg*16) = *(const uint4*)src;
    }
    __syncthreads();

    {
        float acc[4][4];
#pragma unroll
        for (int j = 0; j < 4; j++)
#pragma unroll
            for (int q = 0; q < 4; q++) acc[j][q] = 0.f;

#pragma unroll
        for (int pass = 0; pass < 3; pass++) {
            const uint32_t Ab = (pass == 1) ? AlB : AhB;
            const uint32_t Bb = (pass == 2) ? BlB : BhB;
#pragma unroll
            for (int k16 = 0; k16 < 8; k16++) {
                uint32_t a0, a1, a2, a3;
                ldsm4(a0, a1, a2, a3, Ab + aoff + k16*32);
#pragma unroll
                for (int nb2 = 0; nb2 < 2; nb2++) {
                    uint32_t b0, b1r, b2, b3;
                    ldsm4(b0, b1r, b2, b3, Bb + boff + (uint32_t)(nb2*16*272) + k16*32);
                    mma_bf16(acc[nb2*2],     a0, a1, a2, a3, b0, b1r);
                    mma_bf16(acc[nb2*2 + 1], a0, a1, a2, a3, b2, b3);
                }
            }
        }

        float* r1 = g_res1 + (size_t)b*128*HWSZ;
        const size_t pix0 = (size_t)(y0 + (t0v>>3))*NWD + xw + (t0v & 7);
        const size_t pix1 = (size_t)(y0 + (t1v>>3))*NWD + xw + (t1v & 7);
#pragma unroll
        for (int j = 0; j < 4; j++) {
            int n = nq*32 + j*8 + n0l;
            float pb0 = pbv[n], pb1 = pbv[n+1];
            size_t i00 = (size_t)n*HWSZ + pix0, i10 = (size_t)(n+1)*HWSZ + pix0;
            size_t i01 = (size_t)n*HWSZ + pix1, i11 = (size_t)(n+1)*HWSZ + pix1;
            r1[i00] = acc[j][0] + pb0 + xb[i00];
            r1[i10] = acc[j][1] + pb1 + xb[i10];
            r1[i01] = acc[j][2] + pb0 + xb[i01];
            r1[i11] = acc[j][3] + pb1 + xb[i11];
        }
    }
}

// ================= Kernel 2: mma.sync bf16 3-pass — 512 threads (16 warps) ======================
#define K2B_BH   0
#define K2B_BL   34816
#define K2B_AH   69632
#define K2B_AL   104448
#define K2B_B1   139264
#define K2B_N2W  141312
#define K2B_N2B  141824
#define K2B_RED  142336
#define K2B_SMEM 146432

__global__ void __launch_bounds__(512,1) k2_ffn1(
    const float* __restrict__ n2w, const float* __restrict__ n2b,
    const float* __restrict__ b1)
{
    extern __shared__ char smc[];
    float* xs   = (float*)(smc);
    float* b1s  = (float*)(smc + K2B_B1);
    float* n2ws = (float*)(smc + K2B_N2W);
    float* n2bs = (float*)(smc + K2B_N2B);
    float* red  = (float*)(smc + K2B_RED);

    const int tid  = threadIdx.x;
    const int wid  = tid >> 5, lane = tid & 31;
    const int blk  = blockIdx.x;
    const int b    = blk >> 9, rr = blk & 511;
    const int y    = rr >> 1, x0 = (rr & 1)*128;
    const float* rb = g_res1 + (size_t)b*128*HWSZ + (size_t)y*NWD + x0;

    if (tid < 128) { n2ws[tid] = n2w[tid]; n2bs[tid] = n2b[tid]; }
    b1s[tid] = b1[tid];

#pragma unroll
    for (int i = 0; i < 8; i++) {
        int idx = tid + i*512;
        int c = idx >> 5, f4 = idx & 31;
        *(float4*)(xs + c*128 + f4*4) = *(const float4*)(rb + (size_t)c*HWSZ + f4*4);
    }
    __syncthreads();

    {   // LN2 + A build: thread = (t, quarter of channels)
        const int t = tid & 127, h = tid >> 7;   // h in 0..3
        float s = 0.f, ss = 0.f;
#pragma unroll
        for (int cc = 0; cc < 32; cc++) {
            float v = xs[(h*32+cc)*128 + t];
            s += v; ss += v*v;
        }
        red[h*128+t] = s; red[512 + h*128+t] = ss;
        __syncthreads();
        s  = red[t] + red[128+t] + red[256+t] + red[384+t];
        ss = red[512+t] + red[640+t] + red[768+t] + red[896+t];
        float mu   = s*(1.f/128.f);
        float rstd = rsqrtf(ss*(1.f/128.f) - mu*mu + 1e-6f);

        char* Ah = smc + K2B_AH + t*272 + h*64;
        char* Al = smc + K2B_AL + t*272 + h*64;
#pragma unroll
        for (int cc = 0; cc < 32; cc += 2) {
            int c = h*32 + cc;
            float v0 = (xs[c*128+t]     - mu)*rstd*n2ws[c]   + n2bs[c];
            float v1 = (xs[(c+1)*128+t] - mu)*rstd*n2ws[c+1] + n2bs[c+1];
            unsigned short h0 = bfh(v0), h1 = bfh(v1);
            unsigned short l0v = bfh(v0 - bf2f(h0)), l1v = bfh(v1 - bf2f(h1));
            *(uint32_t*)(Ah + cc*2) = (uint32_t)h0  | ((uint32_t)h1  << 16);
            *(uint32_t*)(Al + cc*2) = (uint32_t)l0v | ((uint32_t)l1v << 16);
        }
    }
    __syncthreads();

    const uint32_t AhB = smem_u32(smc + K2B_AH), AlB = smem_u32(smc + K2B_AL);
    const uint32_t BhB = smem_u32(smc + K2B_BH), BlB = smem_u32(smc + K2B_BL);
    const int tileM = (wid & 7)*16;          // 8 m-stripes
    const int nh64  = (wid >> 3)*64;         // 2 n-halves
    const uint32_t aoff = (uint32_t)((tileM + (lane & 15))*272 + (((lane >> 4) << 3))*2);
    const uint32_t boff = (uint32_t)(((((lane >> 4) << 3) + (lane & 7)) + nh64)*272 + (((lane >> 3) & 1) << 3)*2);

    float* hb = g_h1 + (size_t)b*512*HWSZ + (size_t)y*NWD + x0;
    const int g = lane >> 2, n0l = (lane & 3)*2;

    for (int ck = 0; ck < 4; ck++) {
#pragma unroll
        for (int i = 0; i < 8; i++) {
            int idx = tid + i*512;
            int half = idx >> 11, rem = idx & 2047;
            int row = rem >> 4, seg = rem & 15;
            const unsigned short* src = (half ? g_w1_l : g_w1_h)
                                        + (size_t)(ck*128 + row)*128 + seg*8;
            *(uint4*)(smc + (half ? K2B_BL : K2B_BH) + row*272 + seg*16) = *(const uint4*)src;
        }
        __syncthreads();

        float acc[8][4];
#pragma unroll
        for (int nb = 0; nb < 8; nb++)
#pragma unroll
            for (int q = 0; q < 4; q++) acc[nb][q] = 0.f;

#pragma unroll
        for (int pass = 0; pass < 3; pass++) {
            const uint32_t Ab = (pass == 1) ? AlB : AhB;
            const uint32_t Bb = (pass == 2) ? BlB : BhB;
#pragma unroll
            for (int k16 = 0; k16 < 8; k16++) {
                uint32_t a0, a1, a2, a3;
                ldsm4(a0, a1, a2, a3, Ab + aoff + k16*32);
#pragma unroll
                for (int nbp = 0; nbp < 4; nbp++) {
                    uint32_t b0, b1r, b2, b3;
                    ldsm4(b0, b1r, b2, b3, Bb + boff + (uint32_t)(nbp*16*272) + k16*32);
                    mma_bf16(acc[nbp*2],     a0, a1, a2, a3, b0, b1r);
                    mma_bf16(acc[nbp*2 + 1], a0, a1, a2, a3, b2, b3);
                }
            }
        }

#pragma unroll
        for (int nb = 0; nb < 8; nb++) {
            int n = ck*128 + nh64 + nb*8 + n0l;
            float bb0 = b1s[n], bb1 = b1s[n+1];
            int m0 = tileM + g;
            hb[(size_t)n*HWSZ + m0]         = gelu_f(acc[nb][0] + bb0);
            hb[(size_t)(n+1)*HWSZ + m0]     = gelu_f(acc[nb][1] + bb1);
            hb[(size_t)n*HWSZ + m0 + 8]     = gelu_f(acc[nb][2] + bb0);
            hb[(size_t)(n+1)*HWSZ + m0 + 8] = gelu_f(acc[nb][3] + bb1);
        }
        __syncthreads();
    }
}

// ================= Kernel 3: depthwise 3x3 + GELU + mma FFN2 — 512 threads, occ 2 ===============
#define K3_HS   0
#define K3_AH   32768
#define K3_AL   41984
#define K3_BH   51200
#define K3_BL   60416
#define K3_SMEM 69632

__global__ void __launch_bounds__(512,2) k3_ffn2(
    const float* __restrict__ dw, const float* __restrict__ dwb,
    const float* __restrict__ b2, float* __restrict__ out)
{
    extern __shared__ char smc[];
    float* hs = (float*)(smc + K3_HS);

    const int tid = threadIdx.x;
    const int wid = tid >> 5, lane = tid & 31;
    const int blk = blockIdx.x;
    const int b   = blk >> 10, rr = blk & 1023;
    const int y0  = (rr >> 5) << 3, xw = (rr & 31) << 3;
    const float* hbase = g_h1 + (size_t)b*512*HWSZ;

    const int mrow = wid & 3, nq2 = wid >> 2;   // 4 m-stripes x 4 n16-quarters of the 64-n half
    const uint32_t AhB = smem_u32(smc + K3_AH), AlB = smem_u32(smc + K3_AL);
    const uint32_t BhB = smem_u32(smc + K3_BH), BlB = smem_u32(smc + K3_BL);
    const uint32_t aoff = (uint32_t)(((((lane >> 4) << 3) + (lane & 7))*144) + (mrow*16 + (((lane >> 3) & 1) << 3))*2);
    const uint32_t boff = (uint32_t)(((((lane >> 4) << 3) + (lane & 7)) + nq2*16)*144 + (((lane >> 3) & 1) << 4));

    float acc[2][2][4];
#pragma unroll
    for (int h = 0; h < 2; h++)
#pragma unroll
        for (int j = 0; j < 2; j++)
#pragma unroll
            for (int q = 0; q < 4; q++) acc[h][j][q] = 0.f;

    for (int ck = 0; ck < 8; ck++) {
        const int c0 = ck*64;
        // halo load
        for (int idx = tid; idx < 6400; idx += 512) {
            int ch = idx / 100;
            int p  = idx - ch*100;
            int pr = p / 10;
            int pc = p - pr*10;
            int py = y0 - 1 + pr;
            int px = xw - 1 + pc;
            float v = 0.f;
            if ((unsigned)py < 256u && (unsigned)px < 256u)
                v = hbase[(size_t)(c0+ch)*HWSZ + py*NWD + px];
            hs[ch*128 + pr*12 + pc] = v;
        }
        // stage B half 0
#pragma unroll
        for (int i = 0; i < 2; i++) {
            int idx = tid + i*512;                 // 0..1023
            int hl = idx >> 9, rem = idx & 511;
            int row = rem >> 3, seg = rem & 7;
            const unsigned short* src = (hl ? g_w2_l : g_w2_h)
                                        + (size_t)row*512 + c0 + seg*8;
            *(uint4*)(smc + (hl ? K3_BL : K3_BH) + row*144 + seg*16) = *(const uint4*)src;
        }
        __syncthreads();

        // depthwise conv + GELU -> A hi/lo [k=ch][m=tok]; exactly one row per thread
        {
            int chl = tid >> 3, row = tid & 7;
            const float* dwp = dw + (size_t)(c0+chl)*9;
            const float* hp  = hs + chl*128 + row*12;
            float o8[8];
            float bbv = dwb[c0+chl];
#pragma unroll
            for (int xp = 0; xp < 8; xp++) o8[xp] = bbv;
#pragma unroll
            for (int ky = 0; ky < 3; ky++) {
                const float* rp = hp + ky*12;
                float4 ra = *(const float4*)(rp);
                float4 rb4 = *(const float4*)(rp + 4);
                float2 rc = *(const float2*)(rp + 8);
                float rw[10] = {ra.x, ra.y, ra.z, ra.w, rb4.x, rb4.y, rb4.z, rb4.w, rc.x, rc.y};
                float d0 = dwp[ky*3], d1 = dwp[ky*3+1], d2 = dwp[ky*3+2];
#pragma unroll
                for (int xp = 0; xp < 8; xp++)
                    o8[xp] = fmaf(d0, rw[xp], fmaf(d1, rw[xp+1], fmaf(d2, rw[xp+2], o8[xp])));
            }
            uint32_t hpk[4], lpk[4];
#pragma unroll
            for (int i = 0; i < 4; i++) {
                float v0 = gelu_f(o8[2*i]), v1 = gelu_f(o8[2*i+1]);
                unsigned short h0 = bfh(v0), h1 = bfh(v1);
                unsigned short l0v = bfh(v0 - bf2f(h0)), l1v = bfh(v1 - bf2f(h1));
                hpk[i] = (uint32_t)h0  | ((uint32_t)h1  << 16);
                lpk[i] = (uint32_t)l0v | ((uint32_t)l1v << 16);
            }
            *(uint4*)(smc + K3_AH + chl*144 + row*16) = make_uint4(hpk[0], hpk[1], hpk[2], hpk[3]);
            *(uint4*)(smc + K3_AL + chl*144 + row*16) = make_uint4(lpk[0], lpk[1], lpk[2], lpk[3]);
        }
        __syncthreads();

        // mma half 0
#pragma unroll
        for (int pass = 0; pass < 3; pass++) {
            const uint32_t Ab = (pass == 1) ? AlB : AhB;
            const uint32_t Bb = (pass == 2) ? BlB : BhB;
#pragma unroll
            for (int k16 = 0; k16 < 4; k16++) {
                uint32_t a0, a1, a2, a3;
                ldsm4t(a0, a1, a2, a3, Ab + aoff + k16*2304);
                uint32_t b0, b1r, b2, b3;
                ldsm4(b0, b1r, b2, b3, Bb + boff + k16*32);
                mma_bf16(acc[0][0], a0, a1, a2, a3, b0, b1r);
                mma_bf16(acc[0][1], a0, a1, a2, a3, b2, b3);
            }
        }
        __syncthreads();

        // stage B half 1
#pragma unroll
        for (int i = 0; i < 2; i++) {
            int idx = tid + i*512;
            int hl = idx >> 9, rem = idx & 511;
            int row = rem >> 3, seg = rem & 7;
            const unsigned short* src = (hl ? g_w2_l : g_w2_h)
                                        + (size_t)(64 + row)*512 + c0 + seg*8;
            *(uint4*)(smc + (hl ? K3_BL : K3_BH) + row*144 + seg*16) = *(const uint4*)src;
        }
        __syncthreads();

        // mma half 1
#pragma unroll
        for (int pass = 0; pass < 3; pass++) {
            const uint32_t Ab = (pass == 1) ? AlB : AhB;
            const uint32_t Bb = (pass == 2) ? BlB : BhB;
#pragma unroll
            for (int k16 = 0; k16 < 4; k16++) {
                uint32_t a0, a1, a2, a3;
                ldsm4t(a0, a1, a2, a3, Ab + aoff + k16*2304);
                uint32_t b0, b1r, b2, b3;
                ldsm4(b0, b1r, b2, b3, Bb + boff + k16*32);
                mma_bf16(acc[1][0], a0, a1, a2, a3, b0, b1r);
                mma_bf16(acc[1][1], a0, a1, a2, a3, b2, b3);
            }
        }
        __syncthreads();
    }

    // epilogue: bias + residual + store
    {
        const float* r1 = g_res1 + (size_t)b*128*HWSZ;
        float* ob = out + (size_t)b*128*HWSZ;
        const int g = lane >> 2, n0l = (lane & 3)*2;
        const int m0 = mrow*16 + g;
        const size_t pix0 = (size_t)(y0 + (m0 >> 3))*NWD + xw + (m0 & 7);
        const size_t pix1 = pix0 + NWD;   // token m0+8 = next image row
#pragma unroll
        for (int h = 0; h < 2; h++)
#pragma unroll
            for (int j = 0; j < 2; j++) {
                int o = h*64 + nq2*16 + j*8 + n0l;
                float bb0 = b2[o], bb1 = b2[o+1];
                size_t i00 = (size_t)o*HWSZ + pix0, i10 = (size_t)(o+1)*HWSZ + pix0;
                size_t i01 = (size_t)o*HWSZ + pix1, i11 = (size_t)(o+1)*HWSZ + pix1;
                ob[i00] = acc[h][j][0] + bb0 + r1[i00];
                ob[i10] = acc[h][j][1] + bb1 + r1[i10];
                ob[i01] = acc[h][j][2] + bb0 + r1[i01];
                ob[i11] = acc[h][j][3] + bb1 + r1[i11];
            }
    }
}

// =================================================================================================
extern "C" void kernel_launch(void* const* d_in, const int* in_sizes, int n_in,
                              void* d_out, int out_size)
{
    const float* x    = (const float*)d_in[0];
    const float* l0   = (const float*)d_in[1];
    const float* n1w  = (const float*)d_in[2];
    const float* n1b  = (const float*)d_in[3];
    const float* n2w  = (const float*)d_in[4];
    const float* n2b  = (const float*)d_in[5];
    const float* qkvw = (const float*)d_in[6];
    const float* gw   = (const float*)d_in[7];
    const float* gb   = (const float*)d_in[8];
    const float* pw   = (const float*)d_in[9];
    const float* pb   = (const float*)d_in[10];
    const float* w1   = (const float*)d_in[11];
    const float* b1   = (const float*)d_in[12];
    const float* dwv  = (const float*)d_in[13];
    const float* dwb  = (const float*)d_in[14];
    const float* w2   = (const float*)d_in[15];
    const float* b2   = (const float*)d_in[16];
    float* out = (float*)d_out;

    cudaFuncSetAttribute(k1_attn, cudaFuncAttributeMaxDynamicSharedMemorySize, K1_SMEM);
    cudaFuncSetAttribute(k2_ffn1, cudaFuncAttributeMaxDynamicSharedMemorySize, K2B_SMEM);
    cudaFuncSetAttribute(k3_ffn2, cudaFuncAttributeMaxDynamicSharedMemorySize, K3_SMEM);

    kconv<<<768, 256>>>(qkvw, pw, w1, w2);
    k1_attn<<<4096, 512, K1_SMEM>>>(x, l0, n1w, n1b, gw, gb, pb);
    k2_ffn1<<<2048, 512, K2B_SMEM>>>(n2w, n2b, b1);
    k3_ffn2<<<4096, 512, K3_SMEM>>>(dwv, dwb, b2, out);
}

// round 17
// speedup vs baseline: 4.0091x; 1.0908x over previous
#include <cuda_runtime.h>
#include <cuda_bf16.h>
#include <stdint.h>
#include <math.h>

#define HWSZ 65536
#define NWD  256
typedef unsigned long long u64;

__device__ float g_res1[4ull*128*HWSZ];
__device__ float g_h1  [4ull*512*HWSZ];

// precomputed bf16 hi/lo weights
__device__ __align__(16) unsigned short g_wqkv_h[384*128];
__device__ __align__(16) unsigned short g_wqkv_l[384*128];
__device__ __align__(16) unsigned short g_wp_h[128*128];
__device__ __align__(16) unsigned short g_wp_l[128*128];
__device__ __align__(16) unsigned short g_w1_h[512*128];
__device__ __align__(16) unsigned short g_w1_l[512*128];
__device__ __align__(16) unsigned short g_w2_h[128*512];
__device__ __align__(16) unsigned short g_w2_l[128*512];

__device__ __forceinline__ u64 pk2(float lo, float hi){ u64 r; asm("mov.b64 %0,{%1,%2};":"=l"(r):"f"(lo),"f"(hi)); return r; }
__device__ __forceinline__ u64 dup2(float v){ return pk2(v, v); }
__device__ __forceinline__ void fma2(u64& d, u64 a, u64 b){ asm("fma.rn.f32x2 %0,%1,%2,%0;":"+l"(d):"l"(a),"l"(b)); }
__device__ __forceinline__ u64 mul2(u64 a, u64 b){ u64 d; asm("mul.rn.f32x2 %0,%1,%2;":"=l"(d):"l"(a),"l"(b)); return d; }
__device__ __forceinline__ float lo2(u64 v){ return __uint_as_float((unsigned)v); }
__device__ __forceinline__ float hi2(u64 v){ return __uint_as_float((unsigned)(v>>32)); }
__device__ __forceinline__ float gelu_f(float v){ return 0.5f*v*(1.0f + erff(v*0.7071067811865475f)); }
__device__ __forceinline__ float sigm(float z){ return 1.f/(1.f + __expf(-z)); }

__device__ __forceinline__ uint32_t smem_u32(const void* p){
    uint32_t a;
    asm("{ .reg .u64 t; cvta.to.shared.u64 t, %1; cvt.u32.u64 %0, t; }" : "=r"(a) : "l"(p));
    return a;
}
__device__ __forceinline__ void ldsm4(uint32_t& r0, uint32_t& r1, uint32_t& r2, uint32_t& r3, uint32_t addr){
    asm volatile("ldmatrix.sync.aligned.m8n8.x4.shared.b16 {%0,%1,%2,%3}, [%4];"
                 : "=r"(r0), "=r"(r1), "=r"(r2), "=r"(r3) : "r"(addr));
}
__device__ __forceinline__ void ldsm4t(uint32_t& r0, uint32_t& r1, uint32_t& r2, uint32_t& r3, uint32_t addr){
    asm volatile("ldmatrix.sync.aligned.m8n8.x4.trans.shared.b16 {%0,%1,%2,%3}, [%4];"
                 : "=r"(r0), "=r"(r1), "=r"(r2), "=r"(r3) : "r"(addr));
}
__device__ __forceinline__ void mma_bf16(float* d, uint32_t a0, uint32_t a1, uint32_t a2, uint32_t a3,
                                         uint32_t b0, uint32_t b1){
    asm volatile("mma.sync.aligned.m16n8k16.row.col.f32.bf16.bf16.f32 "
                 "{%0,%1,%2,%3}, {%4,%5,%6,%7}, {%8,%9}, {%0,%1,%2,%3};"
                 : "+f"(d[0]), "+f"(d[1]), "+f"(d[2]), "+f"(d[3])
                 : "r"(a0), "r"(a1), "r"(a2), "r"(a3), "r"(b0), "r"(b1));
}
__device__ __forceinline__ unsigned short bfh(float v){ return __bfloat16_as_ushort(__float2bfloat16_rn(v)); }
__device__ __forceinline__ float bf2f(unsigned short u){ return __bfloat162float(__ushort_as_bfloat16(u)); }

// fused 3-pass mma for one 16n B-block: loads Bh/Bl once, A frags passed in
__device__ __forceinline__ void mma6(float* accL, float* accR,
                                     uint32_t ah0, uint32_t ah1, uint32_t ah2, uint32_t ah3,
                                     uint32_t al0, uint32_t al1, uint32_t al2, uint32_t al3,
                                     uint32_t BhA, uint32_t BlA)
{
    uint32_t bh0, bh1, bh2, bh3, bl0, bl1, bl2, bl3;
    ldsm4(bh0, bh1, bh2, bh3, BhA);
    ldsm4(bl0, bl1, bl2, bl3, BlA);
    mma_bf16(accL, ah0, ah1, ah2, ah3, bh0, bh1);
    mma_bf16(accR, ah0, ah1, ah2, ah3, bh2, bh3);
    mma_bf16(accL, al0, al1, al2, al3, bh0, bh1);
    mma_bf16(accR, al0, al1, al2, al3, bh2, bh3);
    mma_bf16(accL, ah0, ah1, ah2, ah3, bl0, bl1);
    mma_bf16(accR, ah0, ah1, ah2, ah3, bl2, bl3);
}

// ================= Kernel 0: precompute bf16 hi/lo weights ======================================
__global__ void kconv(const float* __restrict__ qkvw, const float* __restrict__ pw,
                      const float* __restrict__ w1, const float* __restrict__ w2)
{
    int i = blockIdx.x*256 + threadIdx.x;
    if (i < 49152) {
        float v = qkvw[i];
        unsigned short h = bfh(v);
        g_wqkv_h[i] = h; g_wqkv_l[i] = bfh(v - bf2f(h));
    } else if (i < 65536) {
        int j = i - 49152;
        float v = pw[j];
        unsigned short h = bfh(v);
        g_wp_h[j] = h; g_wp_l[j] = bfh(v - bf2f(h));
    } else if (i < 131072) {
        int j = i - 65536;
        float v = w1[j];
        unsigned short h = bfh(v);
        g_w1_h[j] = h; g_w1_l[j] = bfh(v - bf2f(h));
    } else {
        int j = i - 131072;
        float v = w2[j];
        unsigned short h = bfh(v);
        g_w2_h[j] = h; g_w2_l[j] = bfh(v - bf2f(h));
    }
}

// ================= Kernel 1: LN1 + mma QKV + gate + attention + mma proj + residual =============
#define K1_AH   0
#define K1_AL   17408
#define K1_BH   34816
#define K1_BL   69632
#define K1_QT   104448
#define K1_KT   138240
#define K1_VT   172032
#define K1_L0S  205824
#define K1_RED  206080
#define K1_SMEM 210176

__global__ void __launch_bounds__(512,1) k1_attn(
    const float* __restrict__ x, const float* __restrict__ l0,
    const float* __restrict__ n1w, const float* __restrict__ n1b,
    const float* __restrict__ gw, const float* __restrict__ gbv,
    const float* __restrict__ pbv)
{
    extern __shared__ char smc[];
    float* xs  = (float*)(smc + K1_BH);
    float* qt  = (float*)(smc + K1_QT);
    float* kt  = (float*)(smc + K1_KT);
    float* vt  = (float*)(smc + K1_VT);
    float* l0s = (float*)(smc + K1_L0S);
    float* red = (float*)(smc + K1_RED);

    const int tid = threadIdx.x;
    const int wid = tid >> 5, lane = tid & 31;
    const int blk = blockIdx.x;
    const int b   = blk >> 10, wr = blk & 1023;
    const int y0  = (wr >> 5) << 3, xw = (wr & 31) << 3;
    const float* xb = x + (size_t)b*128*HWSZ;

    for (int idx = tid; idx < 8192; idx += 512) {
        int c = idx >> 6, t = idx & 63;
        xs[c*64 + t] = xb[(size_t)c*HWSZ + (y0 + (t>>3))*NWD + xw + (t&7)];
    }
    if (tid < 64) l0s[tid] = l0[(size_t)b*HWSZ + (y0 + (tid>>3))*NWD + xw + (tid&7)];
    __syncthreads();

    {
        int t = tid & 63, q8 = tid >> 6;
        float s = 0.f, ss = 0.f;
#pragma unroll
        for (int cc = 0; cc < 16; cc++) {
            float v = xs[(q8*16+cc)*64 + t];
            s += v; ss += v*v;
        }
        red[q8*64+t] = s; red[512 + q8*64+t] = ss;
        __syncthreads();
        s = 0.f; ss = 0.f;
#pragma unroll
        for (int k = 0; k < 8; k++) { s += red[k*64+t]; ss += red[512 + k*64+t]; }
        float mu   = s*(1.f/128.f);
        float rstd = rsqrtf(ss*(1.f/128.f) - mu*mu + 1e-6f);

        char* Ah = smc + K1_AH + t*272 + q8*32;
        char* Al = smc + K1_AL + t*272 + q8*32;
#pragma unroll
        for (int cc = 0; cc < 16; cc += 2) {
            int c = q8*16 + cc;
            float v0 = (xs[c*64+t]     - mu)*rstd*n1w[c]   + n1b[c];
            float v1 = (xs[(c+1)*64+t] - mu)*rstd*n1w[c+1] + n1b[c+1];
            unsigned short h0 = bfh(v0), h1 = bfh(v1);
            unsigned short l0v = bfh(v0 - bf2f(h0)), l1v = bfh(v1 - bf2f(h1));
            *(uint32_t*)(Ah + cc*2) = (uint32_t)h0  | ((uint32_t)h1  << 16);
            *(uint32_t*)(Al + cc*2) = (uint32_t)l0v | ((uint32_t)l1v << 16);
        }
    }
    __syncthreads();

    const int mrow = wid & 3, nq = wid >> 2;
    const uint32_t AhB = smem_u32(smc + K1_AH), AlB = smem_u32(smc + K1_AL);
    const uint32_t BhB = smem_u32(smc + K1_BH), BlB = smem_u32(smc + K1_BL);
    const uint32_t aoff = (uint32_t)((mrow*16 + (lane & 15))*272 + (((lane >> 4) << 3))*2);
    const uint32_t boff = (uint32_t)(((((lane >> 4) << 3) + (lane & 7)) + nq*32)*272 + (((lane >> 3) & 1) << 4));
    const int g = lane >> 2, n0l = (lane & 3)*2;
    const int t0v = mrow*16 + g, t1v = t0v + 8;

    for (int ot = 0; ot < 3; ot++) {
#pragma unroll
        for (int i = 0; i < 8; i++) {
            int idx = tid + i*512;
            int half = idx >> 11, rem = idx & 2047;
            int row = rem >> 4, seg = rem & 15;
            const unsigned short* src = (half ? g_wqkv_l : g_wqkv_h)
                                        + (size_t)(ot*128 + row)*128 + seg*8;
            *(uint4*)(smc + (half ? K1_BL : K1_BH) + row*272 + seg*16) = *(const uint4*)src;
        }
        __syncthreads();

        float acc[4][4];
#pragma unroll
        for (int j = 0; j < 4; j++)
#pragma unroll
            for (int q = 0; q < 4; q++) acc[j][q] = 0.f;

#pragma unroll
        for (int k16 = 0; k16 < 8; k16++) {
            uint32_t ah0, ah1, ah2, ah3, al0, al1, al2, al3;
            ldsm4(ah0, ah1, ah2, ah3, AhB + aoff + k16*32);
            ldsm4(al0, al1, al2, al3, AlB + aoff + k16*32);
#pragma unroll
            for (int nb2 = 0; nb2 < 2; nb2++) {
                mma6(acc[nb2*2], acc[nb2*2+1],
                     ah0, ah1, ah2, ah3, al0, al1, al2, al3,
                     BhB + boff + (uint32_t)(nb2*16*272) + k16*32,
                     BlB + boff + (uint32_t)(nb2*16*272) + k16*32);
            }
        }

        float* dst = (ot == 0) ? qt : (ot == 1) ? kt : vt;
        if (ot == 0) {
            float lv0 = l0s[t0v], lv1 = l0s[t1v];
#pragma unroll
            for (int j = 0; j < 4; j++) {
                int n = nq*32 + j*8 + n0l;
                float gw0 = gw[n], gw1 = gw[n+1], gb0 = gbv[n], gb1 = gbv[n+1];
                *(u64*)(dst + t0v*132 + n) = pk2(acc[j][0]*sigm(lv0*gw0+gb0),
                                                 acc[j][1]*sigm(lv0*gw1+gb1));
                *(u64*)(dst + t1v*132 + n) = pk2(acc[j][2]*sigm(lv1*gw0+gb0),
                                                 acc[j][3]*sigm(lv1*gw1+gb1));
            }
        } else {
#pragma unroll
            for (int j = 0; j < 4; j++) {
                int n = nq*32 + j*8 + n0l;
                *(u64*)(dst + t0v*132 + n) = pk2(acc[j][0], acc[j][1]);
                *(u64*)(dst + t1v*132 + n) = pk2(acc[j][2], acc[j][3]);
            }
        }
        __syncthreads();
    }

    // ---- attention: 8 heads x 64 rows, one row per thread, all 512 threads ----
    {
        const int i = tid & 63, hd = tid >> 6;
        const int qo = hd*16;
        const ulonglong2* qp = (const ulonglong2*)(qt + i*132 + qo);
        ulonglong2 qa0 = qp[0], qa1 = qp[1], qa2 = qp[2], qa3 = qp[3];

        float m = -1e30f, l = 0.f;
        u64 o[8];
#pragma unroll
        for (int d2 = 0; d2 < 8; d2++) o[d2] = 0ull;

        for (int jc = 0; jc < 8; jc++) {
            float e[8];
            float cm = -1e30f;
#pragma unroll
            for (int jj = 0; jj < 8; jj++) {
                int j = jc*8 + jj;
                const ulonglong2* kp = (const ulonglong2*)(kt + j*132 + qo);
                ulonglong2 k0 = kp[0], k1 = kp[1], k2 = kp[2], k3 = kp[3];
                u64 a = 0ull;
                fma2(a, qa0.x, k0.x); fma2(a, qa0.y, k0.y);
                fma2(a, qa1.x, k1.x); fma2(a, qa1.y, k1.y);
                fma2(a, qa2.x, k2.x); fma2(a, qa2.y, k2.y);
                fma2(a, qa3.x, k3.x); fma2(a, qa3.y, k3.y);
                float s = (lo2(a) + hi2(a))*0.25f;
                e[jj] = s; cm = fmaxf(cm, s);
            }
            float mn = fmaxf(m, cm);
            float sc = __expf(m - mn);
            m = mn;
            float sum = 0.f;
#pragma unroll
            for (int jj = 0; jj < 8; jj++) { e[jj] = __expf(e[jj] - m); sum += e[jj]; }
            l = l*sc + sum;
            u64 s2 = dup2(sc);
#pragma unroll
            for (int d2 = 0; d2 < 8; d2++) o[d2] = mul2(o[d2], s2);
#pragma unroll
            for (int jj = 0; jj < 8; jj++) {
                int j = jc*8 + jj;
                const ulonglong2* vp = (const ulonglong2*)(vt + j*132 + qo);
                ulonglong2 v0 = vp[0], v1 = vp[1], v2 = vp[2], v3 = vp[3];
                u64 pj = dup2(e[jj]);
                fma2(o[0], pj, v0.x); fma2(o[1], pj, v0.y);
                fma2(o[2], pj, v1.x); fma2(o[3], pj, v1.y);
                fma2(o[4], pj, v2.x); fma2(o[5], pj, v2.y);
                fma2(o[6], pj, v3.x); fma2(o[7], pj, v3.y);
            }
        }
        float inv = 1.f/l;
#pragma unroll
        for (int d2 = 0; d2 < 8; d2++) {
            xs[(qo + d2*2  )*64 + i] = lo2(o[d2])*inv;
            xs[(qo + d2*2+1)*64 + i] = hi2(o[d2])*inv;
        }
    }
    __syncthreads();

    {
        int t = tid & 63, q8 = tid >> 6;
        char* Ah = smc + K1_AH + t*272 + q8*32;
        char* Al = smc + K1_AL + t*272 + q8*32;
#pragma unroll
        for (int cc = 0; cc < 16; cc += 2) {
            int c = q8*16 + cc;
            float v0 = xs[c*64 + t];
            float v1 = xs[(c+1)*64 + t];
            unsigned short h0 = bfh(v0), h1 = bfh(v1);
            unsigned short l0v = bfh(v0 - bf2f(h0)), l1v = bfh(v1 - bf2f(h1));
            *(uint32_t*)(Ah + cc*2) = (uint32_t)h0  | ((uint32_t)h1  << 16);
            *(uint32_t*)(Al + cc*2) = (uint32_t)l0v | ((uint32_t)l1v << 16);
        }
    }
    __syncthreads();

#pragma unroll
    for (int i = 0; i < 8; i++) {
        int idx = tid + i*512;
        int half = idx >> 11, rem = idx & 2047;
        int row = rem >> 4, seg = rem & 15;
        const unsigned short* src = (half ? g_wp_l : g_wp_h) + (size_t)row*128 + seg*8;
        *(uint4*)(smc + (half ? K1_BL : K1_BH) + row*272 + seg*16) = *(const uint4*)src;
    }
    __syncthreads();

    {
        float acc[4][4];
#pragma unroll
        for (int j = 0; j < 4; j++)
#pragma unroll
            for (int q = 0; q < 4; q++) acc[j][q] = 0.f;

#pragma unroll
        for (int k16 = 0; k16 < 8; k16++) {
            uint32_t ah0, ah1, ah2, ah3, al0, al1, al2, al3;
            ldsm4(ah0, ah1, ah2, ah3, AhB + aoff + k16*32);
            ldsm4(al0, al1, al2, al3, AlB + aoff + k16*32);
#pragma unroll
            for (int nb2 = 0; nb2 < 2; nb2++) {
                mma6(acc[nb2*2], acc[nb2*2+1],
                     ah0, ah1, ah2, ah3, al0, al1, al2, al3,
                     BhB + boff + (uint32_t)(nb2*16*272) + k16*32,
                     BlB + boff + (uint32_t)(nb2*16*272) + k16*32);
            }
        }

        float* r1 = g_res1 + (size_t)b*128*HWSZ;
        const size_t pix0 = (size_t)(y0 + (t0v>>3))*NWD + xw + (t0v & 7);
        const size_t pix1 = (size_t)(y0 + (t1v>>3))*NWD + xw + (t1v & 7);
#pragma unroll
        for (int j = 0; j < 4; j++) {
            int n = nq*32 + j*8 + n0l;
            float pb0 = pbv[n], pb1 = pbv[n+1];
            size_t i00 = (size_t)n*HWSZ + pix0, i10 = (size_t)(n+1)*HWSZ + pix0;
            size_t i01 = (size_t)n*HWSZ + pix1, i11 = (size_t)(n+1)*HWSZ + pix1;
            r1[i00] = acc[j][0] + pb0 + xb[i00];
            r1[i10] = acc[j][1] + pb1 + xb[i10];
            r1[i01] = acc[j][2] + pb0 + xb[i01];
            r1[i11] = acc[j][3] + pb1 + xb[i11];
        }
    }
}

// ================= Kernel 2: mma.sync bf16 fused 3-pass — 512 threads ===========================
#define K2B_BH   0
#define K2B_BL   34816
#define K2B_AH   69632
#define K2B_AL   104448
#define K2B_B1   139264
#define K2B_N2W  141312
#define K2B_N2B  141824
#define K2B_RED  142336
#define K2B_SMEM 146432

__global__ void __launch_bounds__(512,1) k2_ffn1(
    const float* __restrict__ n2w, const float* __restrict__ n2b,
    const float* __restrict__ b1)
{
    extern __shared__ char smc[];
    float* xs   = (float*)(smc);
    float* b1s  = (float*)(smc + K2B_B1);
    float* n2ws = (float*)(smc + K2B_N2W);
    float* n2bs = (float*)(smc + K2B_N2B);
    float* red  = (float*)(smc + K2B_RED);

    const int tid  = threadIdx.x;
    const int wid  = tid >> 5, lane = tid & 31;
    const int blk  = blockIdx.x;
    const int b    = blk >> 9, rr = blk & 511;
    const int y    = rr >> 1, x0 = (rr & 1)*128;
    const float* rb = g_res1 + (size_t)b*128*HWSZ + (size_t)y*NWD + x0;

    if (tid < 128) { n2ws[tid] = n2w[tid]; n2bs[tid] = n2b[tid]; }
    b1s[tid] = b1[tid];

#pragma unroll
    for (int i = 0; i < 8; i++) {
        int idx = tid + i*512;
        int c = idx >> 5, f4 = idx & 31;
        *(float4*)(xs + c*128 + f4*4) = *(const float4*)(rb + (size_t)c*HWSZ + f4*4);
    }
    __syncthreads();

    {
        const int t = tid & 127, h = tid >> 7;
        float s = 0.f, ss = 0.f;
#pragma unroll
        for (int cc = 0; cc < 32; cc++) {
            float v = xs[(h*32+cc)*128 + t];
            s += v; ss += v*v;
        }
        red[h*128+t] = s; red[512 + h*128+t] = ss;
        __syncthreads();
        s  = red[t] + red[128+t] + red[256+t] + red[384+t];
        ss = red[512+t] + red[640+t] + red[768+t] + red[896+t];
        float mu   = s*(1.f/128.f);
        float rstd = rsqrtf(ss*(1.f/128.f) - mu*mu + 1e-6f);

        char* Ah = smc + K2B_AH + t*272 + h*64;
        char* Al = smc + K2B_AL + t*272 + h*64;
#pragma unroll
        for (int cc = 0; cc < 32; cc += 2) {
            int c = h*32 + cc;
            float v0 = (xs[c*128+t]     - mu)*rstd*n2ws[c]   + n2bs[c];
            float v1 = (xs[(c+1)*128+t] - mu)*rstd*n2ws[c+1] + n2bs[c+1];
            unsigned short h0 = bfh(v0), h1 = bfh(v1);
            unsigned short l0v = bfh(v0 - bf2f(h0)), l1v = bfh(v1 - bf2f(h1));
            *(uint32_t*)(Ah + cc*2) = (uint32_t)h0  | ((uint32_t)h1  << 16);
            *(uint32_t*)(Al + cc*2) = (uint32_t)l0v | ((uint32_t)l1v << 16);
        }
    }
    __syncthreads();

    const uint32_t AhB = smem_u32(smc + K2B_AH), AlB = smem_u32(smc + K2B_AL);
    const uint32_t BhB = smem_u32(smc + K2B_BH), BlB = smem_u32(smc + K2B_BL);
    const int tileM = (wid & 7)*16;
    const int nh64  = (wid >> 3)*64;
    const uint32_t aoff = (uint32_t)((tileM + (lane & 15))*272 + (((lane >> 4) << 3))*2);
    const uint32_t boff = (uint32_t)(((((lane >> 4) << 3) + (lane & 7)) + nh64)*272 + (((lane >> 3) & 1) << 3)*2);

    float* hb = g_h1 + (size_t)b*512*HWSZ + (size_t)y*NWD + x0;
    const int g = lane >> 2, n0l = (lane & 3)*2;

    for (int ck = 0; ck < 4; ck++) {
#pragma unroll
        for (int i = 0; i < 8; i++) {
            int idx = tid + i*512;
            int half = idx >> 11, rem = idx & 2047;
            int row = rem >> 4, seg = rem & 15;
            const unsigned short* src = (half ? g_w1_l : g_w1_h)
                                        + (size_t)(ck*128 + row)*128 + seg*8;
            *(uint4*)(smc + (half ? K2B_BL : K2B_BH) + row*272 + seg*16) = *(const uint4*)src;
        }
        __syncthreads();

        float acc[8][4];
#pragma unroll
        for (int nb = 0; nb < 8; nb++)
#pragma unroll
            for (int q = 0; q < 4; q++) acc[nb][q] = 0.f;

#pragma unroll
        for (int k16 = 0; k16 < 8; k16++) {
            uint32_t ah0, ah1, ah2, ah3, al0, al1, al2, al3;
            ldsm4(ah0, ah1, ah2, ah3, AhB + aoff + k16*32);
            ldsm4(al0, al1, al2, al3, AlB + aoff + k16*32);
#pragma unroll
            for (int nbp = 0; nbp < 4; nbp++) {
                mma6(acc[nbp*2], acc[nbp*2+1],
                     ah0, ah1, ah2, ah3, al0, al1, al2, al3,
                     BhB + boff + (uint32_t)(nbp*16*272) + k16*32,
                     BlB + boff + (uint32_t)(nbp*16*272) + k16*32);
            }
        }

#pragma unroll
        for (int nb = 0; nb < 8; nb++) {
            int n = ck*128 + nh64 + nb*8 + n0l;
            float bb0 = b1s[n], bb1 = b1s[n+1];
            int m0 = tileM + g;
            hb[(size_t)n*HWSZ + m0]         = gelu_f(acc[nb][0] + bb0);
            hb[(size_t)(n+1)*HWSZ + m0]     = gelu_f(acc[nb][1] + bb1);
            hb[(size_t)n*HWSZ + m0 + 8]     = gelu_f(acc[nb][2] + bb0);
            hb[(size_t)(n+1)*HWSZ + m0 + 8] = gelu_f(acc[nb][3] + bb1);
        }
        __syncthreads();
    }
}

// ================= Kernel 3: depthwise 3x3 + GELU + mma FFN2 — full-B, 3 syncs/chunk ============
#define K3_HS   0                      // halo fp32                32768 B
#define K3_AH   32768                  // 64 x 144                  9216 B
#define K3_AL   41984
#define K3_BH   51200                  // 128 x 144                18432 B
#define K3_BL   69632
#define K3_SMEM 88064

__global__ void __launch_bounds__(512,2) k3_ffn2(
    const float* __restrict__ dw, const float* __restrict__ dwb,
    const float* __restrict__ b2, float* __restrict__ out)
{
    extern __shared__ char smc[];
    float* hs = (float*)(smc + K3_HS);

    const int tid = threadIdx.x;
    const int wid = tid >> 5, lane = tid & 31;
    const int blk = blockIdx.x;
    const int b   = blk >> 10, rr = blk & 1023;
    const int y0  = (rr >> 5) << 3, xw = (rr & 31) << 3;
    const float* hbase = g_h1 + (size_t)b*512*HWSZ;

    const int mrow = wid & 3, nq2 = wid >> 2;   // 4 m-stripes x 4 n32-quarters
    const uint32_t AhB = smem_u32(smc + K3_AH), AlB = smem_u32(smc + K3_AL);
    const uint32_t BhB = smem_u32(smc + K3_BH), BlB = smem_u32(smc + K3_BL);
    const uint32_t aoff = (uint32_t)(((((lane >> 4) << 3) + (lane & 7))*144) + (mrow*16 + (((lane >> 3) & 1) << 3))*2);
    const uint32_t boff = (uint32_t)(((((lane >> 4) << 3) + (lane & 7)) + nq2*32)*144 + (((lane >> 3) & 1) << 4));

    float acc[4][4];
#pragma unroll
    for (int j = 0; j < 4; j++)
#pragma unroll
        for (int q = 0; q < 4; q++) acc[j][q] = 0.f;

    for (int ck = 0; ck < 8; ck++) {
        const int c0 = ck*64;
        // halo load
        for (int idx = tid; idx < 6400; idx += 512) {
            int ch = idx / 100;
            int p  = idx - ch*100;
            int pr = p / 10;
            int pc = p - pr*10;
            int py = y0 - 1 + pr;
            int px = xw - 1 + pc;
            float v = 0.f;
            if ((unsigned)py < 256u && (unsigned)px < 256u)
                v = hbase[(size_t)(c0+ch)*HWSZ + py*NWD + px];
            hs[ch*128 + pr*12 + pc] = v;
        }
        // stage full B (128 n-rows, hi+lo)
#pragma unroll
        for (int i = 0; i < 4; i++) {
            int idx = tid + i*512;                 // 0..2047
            int hl = idx >> 10, rem = idx & 1023;
            int row = rem >> 3, seg = rem & 7;
            const unsigned short* src = (hl ? g_w2_l : g_w2_h)
                                        + (size_t)row*512 + c0 + seg*8;
            *(uint4*)(smc + (hl ? K3_BL : K3_BH) + row*144 + seg*16) = *(const uint4*)src;
        }
        __syncthreads();

        // depthwise conv + GELU -> A hi/lo [k=ch][m=tok]; one row per thread
        {
            int chl = tid >> 3, row = tid & 7;
            const float* dwp = dw + (size_t)(c0+chl)*9;
            const float* hp  = hs + chl*128 + row*12;
            float o8[8];
            float bbv = dwb[c0+chl];
#pragma unroll
            for (int xp = 0; xp < 8; xp++) o8[xp] = bbv;
#pragma unroll
            for (int ky = 0; ky < 3; ky++) {
                const float* rp = hp + ky*12;
                float4 ra = *(const float4*)(rp);
                float4 rb4 = *(const float4*)(rp + 4);
                float2 rc = *(const float2*)(rp + 8);
                float rw[10] = {ra.x, ra.y, ra.z, ra.w, rb4.x, rb4.y, rb4.z, rb4.w, rc.x, rc.y};
                float d0 = dwp[ky*3], d1 = dwp[ky*3+1], d2 = dwp[ky*3+2];
#pragma unroll
                for (int xp = 0; xp < 8; xp++)
                    o8[xp] = fmaf(d0, rw[xp], fmaf(d1, rw[xp+1], fmaf(d2, rw[xp+2], o8[xp])));
            }
            uint32_t hpk[4], lpk[4];
#pragma unroll
            for (int i = 0; i < 4; i++) {
                float v0 = gelu_f(o8[2*i]), v1 = gelu_f(o8[2*i+1]);
                unsigned short h0 = bfh(v0), h1 = bfh(v1);
                unsigned short l0v = bfh(v0 - bf2f(h0)), l1v = bfh(v1 - bf2f(h1));
                hpk[i] = (uint32_t)h0  | ((uint32_t)h1  << 16);
                lpk[i] = (uint32_t)l0v | ((uint32_t)l1v << 16);
            }
            *(uint4*)(smc + K3_AH + chl*144 + row*16) = make_uint4(hpk[0], hpk[1], hpk[2], hpk[3]);
            *(uint4*)(smc + K3_AL + chl*144 + row*16) = make_uint4(lpk[0], lpk[1], lpk[2], lpk[3]);
        }
        __syncthreads();

        // fused 3-pass mma over full B
#pragma unroll
        for (int k16 = 0; k16 < 4; k16++) {
            uint32_t ah0, ah1, ah2, ah3, al0, al1, al2, al3;
            ldsm4t(ah0, ah1, ah2, ah3, AhB + aoff + k16*2304);
            ldsm4t(al0, al1, al2, al3, AlB + aoff + k16*2304);
#pragma unroll
            for (int nb2 = 0; nb2 < 2; nb2++) {
                mma6(acc[nb2*2], acc[nb2*2+1],
                     ah0, ah1, ah2, ah3, al0, al1, al2, al3,
                     BhB + boff + (uint32_t)(nb2*16*144) + k16*32,
                     BlB + boff + (uint32_t)(nb2*16*144) + k16*32);
            }
        }
        __syncthreads();
    }

    // epilogue: bias + residual + store
    {
        const float* r1 = g_res1 + (size_t)b*128*HWSZ;
        float* ob = out + (size_t)b*128*HWSZ;
        const int g = lane >> 2, n0l = (lane & 3)*2;
        const int m0 = mrow*16 + g;
        const size_t pix0 = (size_t)(y0 + (m0 >> 3))*NWD + xw + (m0 & 7);
        const size_t pix1 = pix0 + NWD;
#pragma unroll
        for (int j = 0; j < 4; j++) {
            int o = nq2*32 + (j >> 1)*16 + (j & 1)*8 + n0l;
            float bb0 = b2[o], bb1 = b2[o+1];
            size_t i00 = (size_t)o*HWSZ + pix0, i10 = (size_t)(o+1)*HWSZ + pix0;
            size_t i01 = (size_t)o*HWSZ + pix1, i11 = (size_t)(o+1)*HWSZ + pix1;
            ob[i00] = acc[j][0] + bb0 + r1[i00];
            ob[i10] = acc[j][1] + bb1 + r1[i10];
            ob[i01] = acc[j][2] + bb0 + r1[i01];
            ob[i11] = acc[j][3] + bb1 + r1[i11];
        }
    }
}

// =================================================================================================
extern "C" void kernel_launch(void* const* d_in, const int* in_sizes, int n_in,
                              void* d_out, int out_size)
{
    const float* x    = (const float*)d_in[0];
    const float* l0   = (const float*)d_in[1];
    const float* n1w  = (const float*)d_in[2];
    const float* n1b  = (const float*)d_in[3];
    const float* n2w  = (const float*)d_in[4];
    const float* n2b  = (const float*)d_in[5];
    const float* qkvw = (const float*)d_in[6];
    const float* gw   = (const float*)d_in[7];
    const float* gb   = (const float*)d_in[8];
    const float* pw   = (const float*)d_in[9];
    const float* pb   = (const float*)d_in[10];
    const float* w1   = (const float*)d_in[11];
    const float* b1   = (const float*)d_in[12];
    const float* dwv  = (const float*)d_in[13];
    const float* dwb  = (const float*)d_in[14];
    const float* w2   = (const float*)d_in[15];
    const float* b2   = (const float*)d_in[16];
    float* out = (float*)d_out;

    cudaFuncSetAttribute(k1_attn, cudaFuncAttributeMaxDynamicSharedMemorySize, K1_SMEM);
    cudaFuncSetAttribute(k2_ffn1, cudaFuncAttributeMaxDynamicSharedMemorySize, K2B_SMEM);
    cudaFuncSetAttribute(k3_ffn2, cudaFuncAttributeMaxDynamicSharedMemorySize, K3_SMEM);

    kconv<<<768, 256>>>(qkvw, pw, w1, w2);
    k1_attn<<<4096, 512, K1_SMEM>>>(x, l0, n1w, n1b, gw, gb, pb);
    k2_ffn1<<<2048, 512, K2B_SMEM>>>(n2w, n2b, b1);
    k3_ffn2<<<4096, 512, K3_SMEM>>>(dwv, dwb, b2, out);
}